// round 1
// baseline (speedup 1.0000x reference)
#include <cuda_runtime.h>
#include <cuda_bf16.h>
#include <cstddef>

#define B_  2
#define S_  2048
#define DM  1024
#define H_  16
#define DH  64
#define M_  (B_*S_)   // 4096

// Scratch: projected Q,K,V in [B,H,S,Dh] layout (device globals — no allocs)
__device__ float g_q[B_*H_*S_*DH];
__device__ float g_k[B_*H_*S_*DH];
__device__ float g_v[B_*H_*S_*DH];
__device__ int   g_mask_mode;   // 0=int32, 1=uint8, 2=float32

// ---------------------------------------------------------------------------
// Detect the storage dtype of the boolean mask (jax bool may arrive as i32,
// u8, or f32 depending on the harness conversion). Deterministic per-launch.
// ---------------------------------------------------------------------------
__global__ void detect_mask_kernel(const unsigned int* __restrict__ m) {
    int t = threadIdx.x;
    int ok_i32 = 1, ok_u8 = 1;
    for (int i = t; i < 4096; i += 256) {
        unsigned w = m[i];
        ok_i32 &= (w <= 1u);                      // words are 0/1
        ok_u8  &= ((w & 0xFEFEFEFEu) == 0u);      // every byte is 0/1
    }
    ok_i32 = __syncthreads_and(ok_i32);
    ok_u8  = __syncthreads_and(ok_u8);
    if (t == 0) g_mask_mode = ok_i32 ? 0 : (ok_u8 ? 1 : 2);
}

// ---------------------------------------------------------------------------
// Projection GEMM: out[m,n] = (sum_k X[m,k]*W[n,k] + bias[n]) * scale
// Written in head-split layout out[((b*H+h)*S + s)*DH + d],  h=n/64, d=n%64.
// Tiling: BM=BN=128, BK=8, 256 threads, 8x8 micro-tile, register prefetch.
// ---------------------------------------------------------------------------
__global__ __launch_bounds__(256) void proj_kernel(
    const float* __restrict__ X, const float* __restrict__ W,
    const float* __restrict__ bias, float* __restrict__ out, float scale)
{
    __shared__ float Xs[8 * 128];   // Xs[k][m]
    __shared__ float Ws[8 * 128];   // Ws[k][n]

    const int t  = threadIdx.x;
    const int tm = t >> 4;          // 0..15
    const int tn = t & 15;          // 0..15
    const int m0 = blockIdx.y * 128;
    const int n0 = blockIdx.x * 128;

    const int lr = t >> 1;          // 0..127 (tile row)
    const int lk = (t & 1) * 4;     // 0 or 4 (k offset)

    const float* Xp = X + (size_t)(m0 + lr) * DM + lk;
    const float* Wp = W + (size_t)(n0 + lr) * DM + lk;

    float acc[8][8];
#pragma unroll
    for (int i = 0; i < 8; ++i)
#pragma unroll
        for (int j = 0; j < 8; ++j) acc[i][j] = 0.f;

    float4 xa = *(const float4*)Xp;
    float4 wa = *(const float4*)Wp;

    for (int kt = 0; kt < DM / 8; ++kt) {
        // stage current fragment to smem (transposed)
        Xs[(lk + 0) * 128 + lr] = xa.x;
        Xs[(lk + 1) * 128 + lr] = xa.y;
        Xs[(lk + 2) * 128 + lr] = xa.z;
        Xs[(lk + 3) * 128 + lr] = xa.w;
        Ws[(lk + 0) * 128 + lr] = wa.x;
        Ws[(lk + 1) * 128 + lr] = wa.y;
        Ws[(lk + 2) * 128 + lr] = wa.z;
        Ws[(lk + 3) * 128 + lr] = wa.w;
        __syncthreads();

        // prefetch next k-slice into registers (hide LDG under compute)
        if (kt + 1 < DM / 8) {
            xa = *(const float4*)(Xp + (kt + 1) * 8);
            wa = *(const float4*)(Wp + (kt + 1) * 8);
        }

#pragma unroll
        for (int k = 0; k < 8; ++k) {
            float4 a0 = *(const float4*)(Xs + k * 128 + 8 * tm);
            float4 a1 = *(const float4*)(Xs + k * 128 + 8 * tm + 4);
            float4 b0 = *(const float4*)(Ws + k * 128 + 8 * tn);
            float4 b1 = *(const float4*)(Ws + k * 128 + 8 * tn + 4);
            float a[8] = {a0.x, a0.y, a0.z, a0.w, a1.x, a1.y, a1.z, a1.w};
            float bb[8] = {b0.x, b0.y, b0.z, b0.w, b1.x, b1.y, b1.z, b1.w};
#pragma unroll
            for (int i = 0; i < 8; ++i)
#pragma unroll
                for (int j = 0; j < 8; ++j) acc[i][j] += a[i] * bb[j];
        }
        __syncthreads();
    }

    // epilogue: bias + scale, write head-split
    const int n_base = n0 + 8 * tn;
    const int h0 = n_base >> 6;
    const int d0 = n_base & 63;
    float4 bias0 = *(const float4*)(bias + n_base);
    float4 bias1 = *(const float4*)(bias + n_base + 4);
    const int m_base = m0 + 8 * tm;
    const int b = m_base >> 11;

#pragma unroll
    for (int i = 0; i < 8; ++i) {
        const int s = (m_base + i) & (S_ - 1);
        float4 r0, r1;
        r0.x = (acc[i][0] + bias0.x) * scale;
        r0.y = (acc[i][1] + bias0.y) * scale;
        r0.z = (acc[i][2] + bias0.z) * scale;
        r0.w = (acc[i][3] + bias0.w) * scale;
        r1.x = (acc[i][4] + bias1.x) * scale;
        r1.y = (acc[i][5] + bias1.y) * scale;
        r1.z = (acc[i][6] + bias1.z) * scale;
        r1.w = (acc[i][7] + bias1.w) * scale;
        size_t off = ((size_t)(b * H_ + h0) * S_ + s) * DH + d0;
        *(float4*)(out + off)     = r0;
        *(float4*)(out + off + 4) = r1;
    }
}

// ---------------------------------------------------------------------------
// Flash attention: one CTA per (b, h, 64-query tile). 256 threads,
// 4x4 register tiles, online softmax with 16-lane shfl row reductions.
// ---------------------------------------------------------------------------
__global__ __launch_bounds__(256) void attn_kernel(
    const float* __restrict__ q_g, const float* __restrict__ k_g,
    const float* __restrict__ v_g, const void* __restrict__ mask,
    float* __restrict__ out)
{
    extern __shared__ float sm[];
    float* Qs = sm;            // Qs[d*64 + q]   (transposed)
    float* Ks = sm + 4096;     // Ks[d*64 + k]   (transposed)
    float* Vs = sm + 8192;     // Vs[k*64 + d]   (natural)
    float* Ss = sm + 12288;    // Ss[q*64 + k]   (probabilities)

    const int t  = threadIdx.x;
    const int tm = t >> 4;     // 0..15 -> query rows 4*tm..+3
    const int tn = t & 15;     // 0..15 -> key/d cols 4*tn..+3
    const int b  = blockIdx.z, h = blockIdx.y;
    const int q0 = blockIdx.x * 64;

    const float* Qg = q_g + ((size_t)(b * H_ + h) * S_ + q0) * DH;
    const float* Kg = k_g + (size_t)(b * H_ + h) * S_ * DH;
    const float* Vg = v_g + (size_t)(b * H_ + h) * S_ * DH;

    // load Q tile transposed
    {
        const int r  = t >> 2;
        const int c0 = (t & 3) << 4;
        const float* src = Qg + r * DH + c0;
#pragma unroll
        for (int cc = 0; cc < 16; cc += 4) {
            float4 v = *(const float4*)(src + cc);
            Qs[(c0 + cc + 0) * 64 + r] = v.x;
            Qs[(c0 + cc + 1) * 64 + r] = v.y;
            Qs[(c0 + cc + 2) * 64 + r] = v.z;
            Qs[(c0 + cc + 3) * 64 + r] = v.w;
        }
    }

    float m_i[4], l_i[4], o[4][4];
#pragma unroll
    for (int i = 0; i < 4; ++i) {
        m_i[i] = -1e30f; l_i[i] = 0.f;
#pragma unroll
        for (int j = 0; j < 4; ++j) o[i][j] = 0.f;
    }

    const int mode = g_mask_mode;
    const int row0 = b * S_ + q0;

    for (int kt = 0; kt < S_ / 64; ++kt) {
        const int k0 = kt * 64;
        __syncthreads();
        // load K (transposed) and V (natural)
        {
            const int r  = t >> 2;
            const int c0 = (t & 3) << 4;
            const float* ks = Kg + (size_t)(k0 + r) * DH + c0;
            const float* vs = Vg + (size_t)(k0 + r) * DH + c0;
#pragma unroll
            for (int cc = 0; cc < 16; cc += 4) {
                float4 kv = *(const float4*)(ks + cc);
                Ks[(c0 + cc + 0) * 64 + r] = kv.x;
                Ks[(c0 + cc + 1) * 64 + r] = kv.y;
                Ks[(c0 + cc + 2) * 64 + r] = kv.z;
                Ks[(c0 + cc + 3) * 64 + r] = kv.w;
                *(float4*)(Vs + r * 64 + c0 + cc) = *(const float4*)(vs + cc);
            }
        }
        __syncthreads();

        // S = Q K^T  (Q pre-scaled by 1/sqrt(Dh) in projection)
        float s[4][4];
#pragma unroll
        for (int i = 0; i < 4; ++i)
#pragma unroll
            for (int j = 0; j < 4; ++j) s[i][j] = 0.f;

#pragma unroll 8
        for (int d = 0; d < 64; ++d) {
            float4 a  = *(const float4*)(Qs + d * 64 + 4 * tm);
            float4 bv = *(const float4*)(Ks + d * 64 + 4 * tn);
            s[0][0] += a.x * bv.x; s[0][1] += a.x * bv.y; s[0][2] += a.x * bv.z; s[0][3] += a.x * bv.w;
            s[1][0] += a.y * bv.x; s[1][1] += a.y * bv.y; s[1][2] += a.y * bv.z; s[1][3] += a.y * bv.w;
            s[2][0] += a.z * bv.x; s[2][1] += a.z * bv.y; s[2][2] += a.z * bv.z; s[2][3] += a.z * bv.w;
            s[3][0] += a.w * bv.x; s[3][1] += a.w * bv.y; s[3][2] += a.w * bv.z; s[3][3] += a.w * bv.w;
        }

        // apply mask (True -> -1e30)
        if (mode == 0) {
            const int* mp = (const int*)mask;
#pragma unroll
            for (int i = 0; i < 4; ++i) {
                size_t off = (size_t)(row0 + 4 * tm + i) * S_ + k0 + 4 * tn;
                int4 mw = *(const int4*)(mp + off);
                if (mw.x) s[i][0] = -1e30f;
                if (mw.y) s[i][1] = -1e30f;
                if (mw.z) s[i][2] = -1e30f;
                if (mw.w) s[i][3] = -1e30f;
            }
        } else if (mode == 1) {
            const unsigned char* mp = (const unsigned char*)mask;
#pragma unroll
            for (int i = 0; i < 4; ++i) {
                size_t off = (size_t)(row0 + 4 * tm + i) * S_ + k0 + 4 * tn;
                unsigned w = *(const unsigned int*)(mp + off);
                if (w & 0x000000FFu) s[i][0] = -1e30f;
                if (w & 0x0000FF00u) s[i][1] = -1e30f;
                if (w & 0x00FF0000u) s[i][2] = -1e30f;
                if (w & 0xFF000000u) s[i][3] = -1e30f;
            }
        } else {
            const float* mp = (const float*)mask;
#pragma unroll
            for (int i = 0; i < 4; ++i) {
                size_t off = (size_t)(row0 + 4 * tm + i) * S_ + k0 + 4 * tn;
                float4 mw = *(const float4*)(mp + off);
                if (mw.x != 0.f) s[i][0] = -1e30f;
                if (mw.y != 0.f) s[i][1] = -1e30f;
                if (mw.z != 0.f) s[i][2] = -1e30f;
                if (mw.w != 0.f) s[i][3] = -1e30f;
            }
        }

        // online softmax (rows span 16 consecutive lanes: same tm group)
#pragma unroll
        for (int i = 0; i < 4; ++i) {
            float rmax = fmaxf(fmaxf(s[i][0], s[i][1]), fmaxf(s[i][2], s[i][3]));
#pragma unroll
            for (int x = 1; x < 16; x <<= 1)
                rmax = fmaxf(rmax, __shfl_xor_sync(0xffffffffu, rmax, x));
            float m_new = fmaxf(m_i[i], rmax);
            float f = __expf(m_i[i] - m_new);
            float4 p;
            p.x = (s[i][0] <= -1e29f) ? 0.f : __expf(s[i][0] - m_new);
            p.y = (s[i][1] <= -1e29f) ? 0.f : __expf(s[i][1] - m_new);
            p.z = (s[i][2] <= -1e29f) ? 0.f : __expf(s[i][2] - m_new);
            p.w = (s[i][3] <= -1e29f) ? 0.f : __expf(s[i][3] - m_new);
            float psum = p.x + p.y + p.z + p.w;
#pragma unroll
            for (int x = 1; x < 16; x <<= 1)
                psum += __shfl_xor_sync(0xffffffffu, psum, x);
            l_i[i] = l_i[i] * f + psum;
            m_i[i] = m_new;
            o[i][0] *= f; o[i][1] *= f; o[i][2] *= f; o[i][3] *= f;
            *(float4*)(Ss + (4 * tm + i) * 64 + 4 * tn) = p;
        }
        __syncthreads();

        // O += P @ V
#pragma unroll 8
        for (int k = 0; k < 64; ++k) {
            float4 vv = *(const float4*)(Vs + k * 64 + 4 * tn);
#pragma unroll
            for (int i = 0; i < 4; ++i) {
                float pp = Ss[(4 * tm + i) * 64 + k];
                o[i][0] += pp * vv.x;
                o[i][1] += pp * vv.y;
                o[i][2] += pp * vv.z;
                o[i][3] += pp * vv.w;
            }
        }
    }

    // epilogue: normalize and write [B,S,D] with head offset
#pragma unroll
    for (int i = 0; i < 4; ++i) {
        float inv = (l_i[i] > 0.f) ? 1.0f / l_i[i] : 0.f;
        int qq = q0 + 4 * tm + i;
        float4 r;
        r.x = o[i][0] * inv;
        r.y = o[i][1] * inv;
        r.z = o[i][2] * inv;
        r.w = o[i][3] * inv;
        *(float4*)(out + (size_t)(b * S_ + qq) * DM + h * DH + 4 * tn) = r;
    }
}

// ---------------------------------------------------------------------------
extern "C" void kernel_launch(void* const* d_in, const int* in_sizes, int n_in,
                              void* d_out, int out_size) {
    const float* query = (const float*)d_in[0];
    const float* key   = (const float*)d_in[1];
    const float* value = (const float*)d_in[2];
    const void*  mask  = d_in[3];
    const float* Wq = (const float*)d_in[4];
    const float* bq = (const float*)d_in[5];
    const float* Wk = (const float*)d_in[6];
    const float* bk = (const float*)d_in[7];
    const float* Wv = (const float*)d_in[8];
    const float* bv = (const float*)d_in[9];
    float* out = (float*)d_out;

    float *gq, *gk, *gv;
    cudaGetSymbolAddress((void**)&gq, g_q);
    cudaGetSymbolAddress((void**)&gk, g_k);
    cudaGetSymbolAddress((void**)&gv, g_v);

    detect_mask_kernel<<<1, 256>>>((const unsigned int*)mask);

    dim3 pgrid(DM / 128, M_ / 128);   // (8, 32)
    proj_kernel<<<pgrid, 256>>>(query, Wq, bq, gq, 0.125f);  // 1/sqrt(64)
    proj_kernel<<<pgrid, 256>>>(key,   Wk, bk, gk, 1.0f);
    proj_kernel<<<pgrid, 256>>>(value, Wv, bv, gv, 1.0f);

    cudaFuncSetAttribute(attn_kernel,
                         cudaFuncAttributeMaxDynamicSharedMemorySize, 65536);
    dim3 agrid(S_ / 64, H_, B_);      // (32, 16, 2)
    attn_kernel<<<agrid, 256, 65536>>>(gq, gk, gv, mask, out);
}

// round 3
// speedup vs baseline: 2.2275x; 2.2275x over previous
#include <cuda_runtime.h>
#include <cuda_bf16.h>
#include <cstdint>
#include <cstddef>

#define B_  2
#define S_  2048
#define DM  1024
#define H_  16
#define DH  64
#define M_  (B_*S_)   // 4096

// Scratch: projected Q,K,V in [B,H,S,Dh] layout
__device__ float g_q[B_*H_*S_*DH];
__device__ float g_k[B_*H_*S_*DH];
__device__ float g_v[B_*H_*S_*DH];
__device__ int   g_mask_mode;

// ---------------------------------------------------------------------------
// Helpers
// ---------------------------------------------------------------------------
__device__ __forceinline__ uint32_t smem_u32(const void* p) {
    uint32_t a;
    asm("{ .reg .u64 t; cvta.to.shared.u64 t, %1; cvt.u32.u64 %0, t; }"
        : "=r"(a) : "l"(p));
    return a;
}

__device__ __forceinline__ void ldsm4(uint32_t addr, uint32_t* r) {
    asm volatile("ldmatrix.sync.aligned.m8n8.x4.shared.b16 {%0,%1,%2,%3}, [%4];"
        : "=r"(r[0]), "=r"(r[1]), "=r"(r[2]), "=r"(r[3]) : "r"(addr));
}
__device__ __forceinline__ void ldsm4t(uint32_t addr, uint32_t* r) {
    asm volatile("ldmatrix.sync.aligned.m8n8.x4.trans.shared.b16 {%0,%1,%2,%3}, [%4];"
        : "=r"(r[0]), "=r"(r[1]), "=r"(r[2]), "=r"(r[3]) : "r"(addr));
}

__device__ __forceinline__ void mma16816(float* c, const uint32_t* a,
                                         uint32_t b0, uint32_t b1) {
    asm volatile(
        "mma.sync.aligned.m16n8k16.row.col.f32.bf16.bf16.f32 "
        "{%0,%1,%2,%3}, {%4,%5,%6,%7}, {%8,%9}, {%0,%1,%2,%3};"
        : "+f"(c[0]), "+f"(c[1]), "+f"(c[2]), "+f"(c[3])
        : "r"(a[0]), "r"(a[1]), "r"(a[2]), "r"(a[3]), "r"(b0), "r"(b1));
}

// pack two floats -> bf16x2 (lo half = lo_elem, hi half = hi_elem)
__device__ __forceinline__ uint32_t cvt2_bf16(float lo_elem, float hi_elem) {
    uint32_t r;
    asm("cvt.rn.bf16x2.f32 %0, %1, %2;" : "=r"(r) : "f"(hi_elem), "f"(lo_elem));
    return r;
}
__device__ __forceinline__ float bf16lo_f(uint32_t v) { return __uint_as_float(v << 16); }
__device__ __forceinline__ float bf16hi_f(uint32_t v) { return __uint_as_float(v & 0xFFFF0000u); }

// split (x,y) into bf16x2 hi word + bf16x2 residual word
__device__ __forceinline__ void split_pair(float x, float y, uint32_t& h, uint32_t& l) {
    h = cvt2_bf16(x, y);
    float rx = x - bf16lo_f(h);
    float ry = y - bf16hi_f(h);
    l = cvt2_bf16(rx, ry);
}

// split float4 -> two hi words and two lo words
__device__ __forceinline__ void split4(float4 v, uint2& hw, uint2& lw) {
    uint32_t h0, l0, h1, l1;
    split_pair(v.x, v.y, h0, l0);
    split_pair(v.z, v.w, h1, l1);
    hw.x = h0; hw.y = h1; lw.x = l0; lw.y = l1;
}

// ---------------------------------------------------------------------------
// Mask dtype detection
// ---------------------------------------------------------------------------
__global__ void detect_mask_kernel(const unsigned int* __restrict__ m) {
    int t = threadIdx.x;
    int ok_i32 = 1, ok_u8 = 1;
    for (int i = t; i < 4096; i += 256) {
        unsigned w = m[i];
        ok_i32 &= (w <= 1u);
        ok_u8  &= ((w & 0xFEFEFEFEu) == 0u);
    }
    ok_i32 = __syncthreads_and(ok_i32);
    ok_u8  = __syncthreads_and(ok_u8);
    if (t == 0) g_mask_mode = ok_i32 ? 0 : (ok_u8 ? 1 : 2);
}

// ---------------------------------------------------------------------------
// Projection GEMM via mma.sync bf16 3-term split.
// out[m,n] = (sum_k X[m,k]*W[n,k] + bias[n]) * scale  -> head-split layout
// BM=128 BN=128 BK=32, 256 threads (8 warps = 4m x 2n)
// ---------------------------------------------------------------------------
#define PSTR 40   // halves per smem row (32 + 8 pad); 80B row, conflict-free ldsm

__global__ __launch_bounds__(256) void proj_mma_kernel(
    const float* __restrict__ X, const float* __restrict__ W,
    const float* __restrict__ bias, float* __restrict__ out, float scale)
{
    __shared__ __align__(16) unsigned short Ah[128 * PSTR];
    __shared__ __align__(16) unsigned short Al[128 * PSTR];
    __shared__ __align__(16) unsigned short Bh[128 * PSTR];
    __shared__ __align__(16) unsigned short Bl[128 * PSTR];

    const int tid  = threadIdx.x;
    const int lane = tid & 31;
    const int wid  = tid >> 5;
    const int wm   = wid & 3;       // 4 m-bands of 32 rows
    const int wn   = wid >> 2;      // 2 n-bands of 64 cols
    const int m0   = blockIdx.y * 128;
    const int n0   = blockIdx.x * 128;

    const uint32_t sAh = smem_u32(Ah), sAl = smem_u32(Al);
    const uint32_t sBh = smem_u32(Bh), sBl = smem_u32(Bl);

    // per-thread load slots: s = tid + 256*i, r = s>>3, c4 = s&7
    const int lr = tid >> 3 >= 0 ? 0 : 0; (void)lr;

    float C[2][8][4];
#pragma unroll
    for (int i = 0; i < 2; ++i)
#pragma unroll
        for (int j = 0; j < 8; ++j)
#pragma unroll
            for (int k = 0; k < 4; ++k) C[i][j][k] = 0.f;

    float4 ax[4], bx[4];
#pragma unroll
    for (int i = 0; i < 4; ++i) {
        int s = tid + 256 * i, r = s >> 3, c4 = s & 7;
        ax[i] = *(const float4*)(X + (size_t)(m0 + r) * DM + c4 * 4);
        bx[i] = *(const float4*)(W + (size_t)(n0 + r) * DM + c4 * 4);
    }

    const int flr = lane & 15;      // ldmatrix row within 16
    const int flc = lane >> 4;      // ldmatrix k-half (0/1)

    for (int kt = 0; kt < DM / 32; ++kt) {
        __syncthreads();
        // stage current fragment
#pragma unroll
        for (int i = 0; i < 4; ++i) {
            int s = tid + 256 * i, r = s >> 3, c4 = s & 7;
            uint2 hw, lw;
            split4(ax[i], hw, lw);
            *(uint2*)((char*)Ah + r * (PSTR * 2) + c4 * 8) = hw;
            *(uint2*)((char*)Al + r * (PSTR * 2) + c4 * 8) = lw;
            split4(bx[i], hw, lw);
            *(uint2*)((char*)Bh + r * (PSTR * 2) + c4 * 8) = hw;
            *(uint2*)((char*)Bl + r * (PSTR * 2) + c4 * 8) = lw;
        }
        __syncthreads();

        // prefetch next slice
        if (kt + 1 < DM / 32) {
#pragma unroll
            for (int i = 0; i < 4; ++i) {
                int s = tid + 256 * i, r = s >> 3, c4 = s & 7;
                ax[i] = *(const float4*)(X + (size_t)(m0 + r) * DM + (kt + 1) * 32 + c4 * 4);
                bx[i] = *(const float4*)(W + (size_t)(n0 + r) * DM + (kt + 1) * 32 + c4 * 4);
            }
        }

#pragma unroll
        for (int ks = 0; ks < 2; ++ks) {
            uint32_t a_h[2][4], a_l[2][4];
#pragma unroll
            for (int mt = 0; mt < 2; ++mt) {
                uint32_t off = (uint32_t)((32 * wm + 16 * mt + flr) * PSTR + ks * 16 + flc * 8) * 2;
                ldsm4(sAh + off, a_h[mt]);
                ldsm4(sAl + off, a_l[mt]);
            }
#pragma unroll
            for (int ntp = 0; ntp < 4; ++ntp) {
                uint32_t boff = (uint32_t)((64 * wn + 16 * ntp + flr) * PSTR + ks * 16 + flc * 8) * 2;
                uint32_t bh4[4], bl4[4];
                ldsm4(sBh + boff, bh4);
                ldsm4(sBl + boff, bl4);
#pragma unroll
                for (int mt = 0; mt < 2; ++mt) {
                    mma16816(C[mt][2 * ntp],     a_h[mt], bh4[0], bh4[2]);
                    mma16816(C[mt][2 * ntp],     a_h[mt], bl4[0], bl4[2]);
                    mma16816(C[mt][2 * ntp],     a_l[mt], bh4[0], bh4[2]);
                    mma16816(C[mt][2 * ntp + 1], a_h[mt], bh4[1], bh4[3]);
                    mma16816(C[mt][2 * ntp + 1], a_h[mt], bl4[1], bl4[3]);
                    mma16816(C[mt][2 * ntp + 1], a_l[mt], bh4[1], bh4[3]);
                }
            }
        }
    }

    // epilogue: bias + scale, head-split stores (float2)
#pragma unroll
    for (int nt = 0; nt < 8; ++nt) {
        int n = n0 + 64 * wn + 8 * nt + 2 * (lane & 3);
        int h = n >> 6, d = n & 63;
        float2 bv = *(const float2*)(bias + n);
#pragma unroll
        for (int mt = 0; mt < 2; ++mt) {
            int mbase = m0 + 32 * wm + 16 * mt + (lane >> 2);
#pragma unroll
            for (int half = 0; half < 2; ++half) {
                int m = mbase + 8 * half;
                int b = m >> 11, s = m & (S_ - 1);
                float2 r;
                r.x = (C[mt][nt][2 * half + 0] + bv.x) * scale;
                r.y = (C[mt][nt][2 * half + 1] + bv.y) * scale;
                *(float2*)(out + ((size_t)(b * H_ + h) * S_ + s) * DH + d) = r;
            }
        }
    }
}

// ---------------------------------------------------------------------------
// Flash attention via mma.sync bf16 3-term split.
// CTA: 128 q-rows (8 warps x 16), K-tile 64. grid (S/128, H, B).
// ---------------------------------------------------------------------------
#define ASTR 72   // halves per row (64 + 8 pad); 144B row

// smem layout inside sbuf:
//   phase0: Q_hi @0 (18432B), Q_lo @18432
//   loop:   K_hi @0 (9216), K_lo @9216, V_hi @18432, V_lo @27648
//   mask bytes @36864 (8192)
__global__ __launch_bounds__(256) void attn_mma_kernel(
    const float* __restrict__ qg, const float* __restrict__ kg,
    const float* __restrict__ vg, const void* __restrict__ mask,
    float* __restrict__ out)
{
    __shared__ __align__(16) char sbuf[45056];

    const int tid  = threadIdx.x;
    const int lane = tid & 31;
    const int wid  = tid >> 5;
    const int bz   = blockIdx.z;
    const int h    = blockIdx.y;
    const int q0   = blockIdx.x * 128;

    const size_t bh = (size_t)(bz * H_ + h);
    const float* Qg = qg + (bh * S_ + q0) * DH;
    const float* Kg = kg + bh * S_ * DH;
    const float* Vg = vg + bh * S_ * DH;

    const uint32_t sb = smem_u32(sbuf);

    // ---- load Q tile (128 x 64 fp32), split to hi/lo bf16 ----
#pragma unroll
    for (int i = 0; i < 8; ++i) {
        int s = tid + 256 * i, r = s >> 4, c4 = s & 15;
        float4 v = *(const float4*)(Qg + (size_t)r * DH + c4 * 4);
        uint2 hw, lw;
        split4(v, hw, lw);
        *(uint2*)(sbuf + r * 144 + c4 * 8) = hw;
        *(uint2*)(sbuf + 18432 + r * 144 + c4 * 8) = lw;
    }
    __syncthreads();

    // ---- Q fragments into registers (held for whole kernel) ----
    const int flr = lane & 15, flc = lane >> 4;
    uint32_t qh[4][4], ql[4][4];
#pragma unroll
    for (int ks = 0; ks < 4; ++ks) {
        uint32_t off = (uint32_t)((16 * wid + flr) * 144 + ks * 32 + flc * 16);
        ldsm4(sb + off, qh[ks]);
        ldsm4(sb + 18432 + off, ql[ks]);
    }

    float oC[8][4];
#pragma unroll
    for (int j = 0; j < 8; ++j)
#pragma unroll
        for (int k = 0; k < 4; ++k) oC[j][k] = 0.f;
    float mi0 = -1e30f, mi1 = -1e30f, li0 = 0.f, li1 = 0.f;

    const int mode = g_mask_mode;
    const size_t mrow0 = ((size_t)bz * S_ + q0) * S_;

    const int r_in = lane >> 2;          // 0..7
    const int c_in = 2 * (lane & 3);     // 0,2,4,6

    for (int kt = 0; kt < S_ / 64; ++kt) {
        __syncthreads();
        // ---- load K/V tiles (64 x 64 fp32 each), split hi/lo ----
#pragma unroll
        for (int i = 0; i < 4; ++i) {
            int s = tid + 256 * i, r = s >> 4, c4 = s & 15;
            float4 kv = *(const float4*)(Kg + (size_t)(kt * 64 + r) * DH + c4 * 4);
            uint2 hw, lw;
            split4(kv, hw, lw);
            *(uint2*)(sbuf + r * 144 + c4 * 8) = hw;
            *(uint2*)(sbuf + 9216 + r * 144 + c4 * 8) = lw;
            float4 vv = *(const float4*)(Vg + (size_t)(kt * 64 + r) * DH + c4 * 4);
            split4(vv, hw, lw);
            *(uint2*)(sbuf + 18432 + r * 144 + c4 * 8) = hw;
            *(uint2*)(sbuf + 27648 + r * 144 + c4 * 8) = lw;
        }
        // ---- stage mask tile (128 q x 64 k) as bytes ----
        if (mode == 0) {
            const int* mp = (const int*)mask + mrow0 + kt * 64;
#pragma unroll
            for (int i = 0; i < 8; ++i) {
                int g = tid + 256 * i, r = g >> 4, c4 = g & 15;
                int4 mw = *(const int4*)(mp + (size_t)r * S_ + c4 * 4);
                uint32_t pk = (mw.x ? 1u : 0u) | ((mw.y ? 1u : 0u) << 8) |
                              ((mw.z ? 1u : 0u) << 16) | ((mw.w ? 1u : 0u) << 24);
                *(uint32_t*)(sbuf + 36864 + r * 64 + c4 * 4) = pk;
            }
        } else if (mode == 1) {
            const unsigned char* mp = (const unsigned char*)mask + mrow0 + kt * 64;
#pragma unroll
            for (int i = 0; i < 4; ++i) {
                int g = tid + 256 * i, r = g >> 3, c8 = g & 7;
                uint2 mv = *(const uint2*)(mp + (size_t)r * S_ + c8 * 8);
                *(uint2*)(sbuf + 36864 + r * 64 + c8 * 8) = mv;
            }
        } else {
            const float* mp = (const float*)mask + mrow0 + kt * 64;
#pragma unroll
            for (int i = 0; i < 8; ++i) {
                int g = tid + 256 * i, r = g >> 4, c4 = g & 15;
                float4 mw = *(const float4*)(mp + (size_t)r * S_ + c4 * 4);
                uint32_t pk = (mw.x != 0.f ? 1u : 0u) | ((mw.y != 0.f ? 1u : 0u) << 8) |
                              ((mw.z != 0.f ? 1u : 0u) << 16) | ((mw.w != 0.f ? 1u : 0u) << 24);
                *(uint32_t*)(sbuf + 36864 + r * 64 + c4 * 4) = pk;
            }
        }
        __syncthreads();

        // ---- S = Q K^T ----
        float sC[8][4];
#pragma unroll
        for (int j = 0; j < 8; ++j)
#pragma unroll
            for (int k = 0; k < 4; ++k) sC[j][k] = 0.f;

#pragma unroll
        for (int ks = 0; ks < 4; ++ks) {
#pragma unroll
            for (int ntp = 0; ntp < 4; ++ntp) {
                uint32_t boff = (uint32_t)((16 * ntp + flr) * 144 + ks * 32 + flc * 16);
                uint32_t bh4[4], bl4[4];
                ldsm4(sb + boff, bh4);
                ldsm4(sb + 9216 + boff, bl4);
                mma16816(sC[2 * ntp],     qh[ks], bh4[0], bh4[2]);
                mma16816(sC[2 * ntp],     qh[ks], bl4[0], bl4[2]);
                mma16816(sC[2 * ntp],     ql[ks], bh4[0], bh4[2]);
                mma16816(sC[2 * ntp + 1], qh[ks], bh4[1], bh4[3]);
                mma16816(sC[2 * ntp + 1], qh[ks], bl4[1], bl4[3]);
                mma16816(sC[2 * ntp + 1], ql[ks], bh4[1], bh4[3]);
            }
        }

        // ---- mask apply ----
        const int r0 = 16 * wid + r_in;
#pragma unroll
        for (int nt = 0; nt < 8; ++nt) {
            unsigned short mA = *(const unsigned short*)(sbuf + 36864 + r0 * 64 + 8 * nt + c_in);
            unsigned short mB = *(const unsigned short*)(sbuf + 36864 + (r0 + 8) * 64 + 8 * nt + c_in);
            if (mA & 0x00FF) sC[nt][0] = -1e30f;
            if (mA & 0xFF00) sC[nt][1] = -1e30f;
            if (mB & 0x00FF) sC[nt][2] = -1e30f;
            if (mB & 0xFF00) sC[nt][3] = -1e30f;
        }

        // ---- online softmax (rows r0 via c0,c1 and r0+8 via c2,c3) ----
        float mx0 = -1e30f, mx1 = -1e30f;
#pragma unroll
        for (int nt = 0; nt < 8; ++nt) {
            mx0 = fmaxf(mx0, fmaxf(sC[nt][0], sC[nt][1]));
            mx1 = fmaxf(mx1, fmaxf(sC[nt][2], sC[nt][3]));
        }
        mx0 = fmaxf(mx0, __shfl_xor_sync(0xffffffffu, mx0, 1));
        mx0 = fmaxf(mx0, __shfl_xor_sync(0xffffffffu, mx0, 2));
        mx1 = fmaxf(mx1, __shfl_xor_sync(0xffffffffu, mx1, 1));
        mx1 = fmaxf(mx1, __shfl_xor_sync(0xffffffffu, mx1, 2));

        float mn0 = fmaxf(mi0, mx0), mn1 = fmaxf(mi1, mx1);
        float f0 = __expf(mi0 - mn0), f1 = __expf(mi1 - mn1);
        float sum0 = 0.f, sum1 = 0.f;
#pragma unroll
        for (int nt = 0; nt < 8; ++nt) {
            sC[nt][0] = __expf(sC[nt][0] - mn0);
            sC[nt][1] = __expf(sC[nt][1] - mn0);
            sC[nt][2] = __expf(sC[nt][2] - mn1);
            sC[nt][3] = __expf(sC[nt][3] - mn1);
            sum0 += sC[nt][0] + sC[nt][1];
            sum1 += sC[nt][2] + sC[nt][3];
        }
        sum0 += __shfl_xor_sync(0xffffffffu, sum0, 1);
        sum0 += __shfl_xor_sync(0xffffffffu, sum0, 2);
        sum1 += __shfl_xor_sync(0xffffffffu, sum1, 1);
        sum1 += __shfl_xor_sync(0xffffffffu, sum1, 2);
        li0 = li0 * f0 + sum0;
        li1 = li1 * f1 + sum1;
        mi0 = mn0; mi1 = mn1;
#pragma unroll
        for (int nt = 0; nt < 8; ++nt) {
            oC[nt][0] *= f0; oC[nt][1] *= f0;
            oC[nt][2] *= f1; oC[nt][3] *= f1;
        }

        // ---- O += P V ----
#pragma unroll
        for (int kp = 0; kp < 4; ++kp) {
            uint32_t pa_h[4], pa_l[4];
            split_pair(sC[2 * kp][0],     sC[2 * kp][1],     pa_h[0], pa_l[0]);
            split_pair(sC[2 * kp][2],     sC[2 * kp][3],     pa_h[1], pa_l[1]);
            split_pair(sC[2 * kp + 1][0], sC[2 * kp + 1][1], pa_h[2], pa_l[2]);
            split_pair(sC[2 * kp + 1][2], sC[2 * kp + 1][3], pa_h[3], pa_l[3]);

            const int trow = kp * 16 + ((lane >> 3) & 1) * 8 + (lane & 7);
            const int tcolh = (lane >> 4) * 8;
#pragma unroll
            for (int ntp = 0; ntp < 4; ++ntp) {
                uint32_t voff = (uint32_t)(trow * 144 + (16 * ntp + tcolh) * 2);
                uint32_t vh4[4], vl4[4];
                ldsm4t(sb + 18432 + voff, vh4);
                ldsm4t(sb + 27648 + voff, vl4);
                mma16816(oC[2 * ntp],     pa_h, vh4[0], vh4[1]);
                mma16816(oC[2 * ntp],     pa_h, vl4[0], vl4[1]);
                mma16816(oC[2 * ntp],     pa_l, vh4[0], vh4[1]);
                mma16816(oC[2 * ntp + 1], pa_h, vh4[2], vh4[3]);
                mma16816(oC[2 * ntp + 1], pa_h, vl4[2], vl4[3]);
                mma16816(oC[2 * ntp + 1], pa_l, vh4[2], vh4[3]);
            }
        }
    }

    // ---- epilogue ----
    float inv0 = (li0 > 0.f) ? 1.0f / li0 : 0.f;
    float inv1 = (li1 > 0.f) ? 1.0f / li1 : 0.f;
    const int qr = q0 + 16 * wid + r_in;
    const int d0 = h * DH + c_in;
#pragma unroll
    for (int nt = 0; nt < 8; ++nt) {
        float2 v0, v1;
        v0.x = oC[nt][0] * inv0; v0.y = oC[nt][1] * inv0;
        v1.x = oC[nt][2] * inv1; v1.y = oC[nt][3] * inv1;
        *(float2*)(out + (size_t)(bz * S_ + qr) * DM + d0 + 8 * nt) = v0;
        *(float2*)(out + (size_t)(bz * S_ + qr + 8) * DM + d0 + 8 * nt) = v1;
    }
}

// ---------------------------------------------------------------------------
extern "C" void kernel_launch(void* const* d_in, const int* in_sizes, int n_in,
                              void* d_out, int out_size) {
    const float* query = (const float*)d_in[0];
    const float* key   = (const float*)d_in[1];
    const float* value = (const float*)d_in[2];
    const void*  mask  = d_in[3];
    const float* Wq = (const float*)d_in[4];
    const float* bq = (const float*)d_in[5];
    const float* Wk = (const float*)d_in[6];
    const float* bk = (const float*)d_in[7];
    const float* Wv = (const float*)d_in[8];
    const float* bv = (const float*)d_in[9];
    float* out = (float*)d_out;

    float *gq, *gk, *gv;
    cudaGetSymbolAddress((void**)&gq, g_q);
    cudaGetSymbolAddress((void**)&gk, g_k);
    cudaGetSymbolAddress((void**)&gv, g_v);

    detect_mask_kernel<<<1, 256>>>((const unsigned int*)mask);

    dim3 pgrid(DM / 128, M_ / 128);   // (8, 32)
    proj_mma_kernel<<<pgrid, 256>>>(query, Wq, bq, gq, 0.125f);  // 1/sqrt(64)
    proj_mma_kernel<<<pgrid, 256>>>(key,   Wk, bk, gk, 1.0f);
    proj_mma_kernel<<<pgrid, 256>>>(value, Wv, bv, gv, 1.0f);

    dim3 agrid(S_ / 128, H_, B_);     // (16, 16, 2)
    attn_mma_kernel<<<agrid, 256>>>(gq, gk, gv, mask, out);
}

// round 4
// speedup vs baseline: 2.3198x; 1.0414x over previous
#include <cuda_runtime.h>
#include <cuda_bf16.h>
#include <cstdint>
#include <cstddef>

#define B_  2
#define S_  2048
#define DM  1024
#define H_  16
#define DH  64
#define M_  (B_*S_)   // 4096
#define NEGINF -1e30f
// Q projection scale: (1/sqrt(DH)) * log2(e)  -> softmax computed via exp2
#define QSCALE (0.125f * 1.44269504088896f)

__device__ float g_q[B_*H_*S_*DH];
__device__ float g_k[B_*H_*S_*DH];
__device__ float g_v[B_*H_*S_*DH];
__device__ int   g_mask_mode;

// ---------------------------------------------------------------------------
// Helpers
// ---------------------------------------------------------------------------
__device__ __forceinline__ uint32_t smem_u32(const void* p) {
    uint32_t a;
    asm("{ .reg .u64 t; cvta.to.shared.u64 t, %1; cvt.u32.u64 %0, t; }"
        : "=r"(a) : "l"(p));
    return a;
}
__device__ __forceinline__ void ldsm4(uint32_t addr, uint32_t* r) {
    asm volatile("ldmatrix.sync.aligned.m8n8.x4.shared.b16 {%0,%1,%2,%3}, [%4];"
        : "=r"(r[0]), "=r"(r[1]), "=r"(r[2]), "=r"(r[3]) : "r"(addr));
}
__device__ __forceinline__ void ldsm4t(uint32_t addr, uint32_t* r) {
    asm volatile("ldmatrix.sync.aligned.m8n8.x4.trans.shared.b16 {%0,%1,%2,%3}, [%4];"
        : "=r"(r[0]), "=r"(r[1]), "=r"(r[2]), "=r"(r[3]) : "r"(addr));
}
__device__ __forceinline__ void mma16816(float* c, const uint32_t* a,
                                         uint32_t b0, uint32_t b1) {
    asm volatile(
        "mma.sync.aligned.m16n8k16.row.col.f32.bf16.bf16.f32 "
        "{%0,%1,%2,%3}, {%4,%5,%6,%7}, {%8,%9}, {%0,%1,%2,%3};"
        : "+f"(c[0]), "+f"(c[1]), "+f"(c[2]), "+f"(c[3])
        : "r"(a[0]), "r"(a[1]), "r"(a[2]), "r"(a[3]), "r"(b0), "r"(b1));
}
__device__ __forceinline__ uint32_t cvt2_bf16(float lo_elem, float hi_elem) {
    uint32_t r;
    asm("cvt.rn.bf16x2.f32 %0, %1, %2;" : "=r"(r) : "f"(hi_elem), "f"(lo_elem));
    return r;
}
__device__ __forceinline__ float bf16lo_f(uint32_t v) { return __uint_as_float(v << 16); }
__device__ __forceinline__ float bf16hi_f(uint32_t v) { return __uint_as_float(v & 0xFFFF0000u); }
__device__ __forceinline__ void split_pair(float x, float y, uint32_t& h, uint32_t& l) {
    h = cvt2_bf16(x, y);
    float rx = x - bf16lo_f(h);
    float ry = y - bf16hi_f(h);
    l = cvt2_bf16(rx, ry);
}
__device__ __forceinline__ void split4(float4 v, uint2& hw, uint2& lw) {
    uint32_t h0, l0, h1, l1;
    split_pair(v.x, v.y, h0, l0);
    split_pair(v.z, v.w, h1, l1);
    hw.x = h0; hw.y = h1; lw.x = l0; lw.y = l1;
}
__device__ __forceinline__ float ex2f(float x) {
    float y;
    asm("ex2.approx.f32 %0, %1;" : "=f"(y) : "f"(x));
    return y;
}

// ---------------------------------------------------------------------------
// Mask dtype detection
// ---------------------------------------------------------------------------
__global__ void detect_mask_kernel(const unsigned int* __restrict__ m) {
    int t = threadIdx.x;
    int ok_i32 = 1, ok_u8 = 1;
    for (int i = t; i < 4096; i += 256) {
        unsigned w = m[i];
        ok_i32 &= (w <= 1u);
        ok_u8  &= ((w & 0xFEFEFEFEu) == 0u);
    }
    ok_i32 = __syncthreads_and(ok_i32);
    ok_u8  = __syncthreads_and(ok_u8);
    if (t == 0) g_mask_mode = ok_i32 ? 0 : (ok_u8 ? 1 : 2);
}

// ---------------------------------------------------------------------------
// Merged projection GEMM (blockIdx.z selects Q/K/V), mma.sync bf16 3-term.
// BM=BN=128, BK=32, 512 threads (16 warps, 32x32 warp tiles),
// double-buffered smem, one __syncthreads per K-iter, reg prefetch.
// ---------------------------------------------------------------------------
#define PSTR 40                 // halves per row (32 + 8 pad) = 80 bytes
#define PBUF 40960u             // one buffer: 4 * 128*40*2 bytes
#define P_AH 0u
#define P_AL 10240u
#define P_BH 20480u
#define P_BL 30720u
#define PROJ_SMEM (2u * PBUF)   // 81920

struct ProjArgs {
    const float* X[3];
    const float* W[3];
    const float* bias[3];
    float*       out[3];
    float        scale[3];
};

__global__ __launch_bounds__(512) void proj_mma_kernel(ProjArgs args) {
    extern __shared__ char ps[];
    const int z = blockIdx.z;
    const float* __restrict__ X    = args.X[z];
    const float* __restrict__ W    = args.W[z];
    const float* __restrict__ bias = args.bias[z];
    float* __restrict__ out        = args.out[z];
    const float scale              = args.scale[z];

    const int tid  = threadIdx.x;
    const int lane = tid & 31;
    const int wid  = tid >> 5;
    const int wm   = wid & 3;
    const int wn   = wid >> 2;
    const int m0   = blockIdx.y * 128;
    const int n0   = blockIdx.x * 128;

    const int flr = lane & 15;
    const int flc = lane >> 4;

    // load slots: 1024 float4 per matrix, 512 threads -> 2 each
    const int r0s  = (tid + 0)   >> 3, c0s = (tid + 0)   & 7;
    const int r1s  = (tid + 512) >> 3, c1s = (tid + 512) & 7;

    float C[2][4][4];
#pragma unroll
    for (int i = 0; i < 2; ++i)
#pragma unroll
        for (int j = 0; j < 4; ++j)
#pragma unroll
            for (int k = 0; k < 4; ++k) C[i][j][k] = 0.f;

    // prologue: tile 0 -> regs -> buf0
    float4 ax0 = *(const float4*)(X + (size_t)(m0 + r0s) * DM + c0s * 4);
    float4 ax1 = *(const float4*)(X + (size_t)(m0 + r1s) * DM + c1s * 4);
    float4 bx0 = *(const float4*)(W + (size_t)(n0 + r0s) * DM + c0s * 4);
    float4 bx1 = *(const float4*)(W + (size_t)(n0 + r1s) * DM + c1s * 4);
    {
        char* buf = ps;
        uint2 hw, lw;
        split4(ax0, hw, lw);
        *(uint2*)(buf + P_AH + r0s * 80 + c0s * 8) = hw;
        *(uint2*)(buf + P_AL + r0s * 80 + c0s * 8) = lw;
        split4(ax1, hw, lw);
        *(uint2*)(buf + P_AH + r1s * 80 + c1s * 8) = hw;
        *(uint2*)(buf + P_AL + r1s * 80 + c1s * 8) = lw;
        split4(bx0, hw, lw);
        *(uint2*)(buf + P_BH + r0s * 80 + c0s * 8) = hw;
        *(uint2*)(buf + P_BL + r0s * 80 + c0s * 8) = lw;
        split4(bx1, hw, lw);
        *(uint2*)(buf + P_BH + r1s * 80 + c1s * 8) = hw;
        *(uint2*)(buf + P_BL + r1s * 80 + c1s * 8) = lw;
    }
    __syncthreads();

    for (int kt = 0; kt < DM / 32; ++kt) {
        // prefetch next k-slice
        if (kt + 1 < DM / 32) {
            const float* Xn = X + (size_t)m0 * DM + (kt + 1) * 32;
            const float* Wn = W + (size_t)n0 * DM + (kt + 1) * 32;
            ax0 = *(const float4*)(Xn + (size_t)r0s * DM + c0s * 4);
            ax1 = *(const float4*)(Xn + (size_t)r1s * DM + c1s * 4);
            bx0 = *(const float4*)(Wn + (size_t)r0s * DM + c0s * 4);
            bx1 = *(const float4*)(Wn + (size_t)r1s * DM + c1s * 4);
        }

        const uint32_t sbuf = smem_u32(ps) + (kt & 1) * PBUF;
#pragma unroll
        for (int ks = 0; ks < 2; ++ks) {
            uint32_t a_h[2][4], a_l[2][4];
#pragma unroll
            for (int mt = 0; mt < 2; ++mt) {
                uint32_t off = (uint32_t)((32 * wm + 16 * mt + flr) * PSTR + ks * 16 + flc * 8) * 2;
                ldsm4(sbuf + P_AH + off, a_h[mt]);
                ldsm4(sbuf + P_AL + off, a_l[mt]);
            }
#pragma unroll
            for (int ntp = 0; ntp < 2; ++ntp) {
                uint32_t boff = (uint32_t)((32 * wn + 16 * ntp + flr) * PSTR + ks * 16 + flc * 8) * 2;
                uint32_t bh4[4], bl4[4];
                ldsm4(sbuf + P_BH + boff, bh4);
                ldsm4(sbuf + P_BL + boff, bl4);
#pragma unroll
                for (int mt = 0; mt < 2; ++mt) {
                    mma16816(C[mt][2 * ntp],     a_h[mt], bh4[0], bh4[2]);
                    mma16816(C[mt][2 * ntp],     a_h[mt], bl4[0], bl4[2]);
                    mma16816(C[mt][2 * ntp],     a_l[mt], bh4[0], bh4[2]);
                    mma16816(C[mt][2 * ntp + 1], a_h[mt], bh4[1], bh4[3]);
                    mma16816(C[mt][2 * ntp + 1], a_h[mt], bl4[1], bl4[3]);
                    mma16816(C[mt][2 * ntp + 1], a_l[mt], bh4[1], bh4[3]);
                }
            }
        }

        // store prefetched slice into the other buffer
        if (kt + 1 < DM / 32) {
            char* buf = ps + ((kt + 1) & 1) * PBUF;
            uint2 hw, lw;
            split4(ax0, hw, lw);
            *(uint2*)(buf + P_AH + r0s * 80 + c0s * 8) = hw;
            *(uint2*)(buf + P_AL + r0s * 80 + c0s * 8) = lw;
            split4(ax1, hw, lw);
            *(uint2*)(buf + P_AH + r1s * 80 + c1s * 8) = hw;
            *(uint2*)(buf + P_AL + r1s * 80 + c1s * 8) = lw;
            split4(bx0, hw, lw);
            *(uint2*)(buf + P_BH + r0s * 80 + c0s * 8) = hw;
            *(uint2*)(buf + P_BL + r0s * 80 + c0s * 8) = lw;
            split4(bx1, hw, lw);
            *(uint2*)(buf + P_BH + r1s * 80 + c1s * 8) = hw;
            *(uint2*)(buf + P_BL + r1s * 80 + c1s * 8) = lw;
        }
        __syncthreads();
    }

    // epilogue: bias + scale, head-split stores
#pragma unroll
    for (int nt = 0; nt < 4; ++nt) {
        int n = n0 + 32 * wn + 8 * nt + 2 * (lane & 3);
        int h = n >> 6, d = n & 63;
        float2 bv = *(const float2*)(bias + n);
#pragma unroll
        for (int mt = 0; mt < 2; ++mt) {
            int mbase = m0 + 32 * wm + 16 * mt + (lane >> 2);
#pragma unroll
            for (int half = 0; half < 2; ++half) {
                int m = mbase + 8 * half;
                int b = m >> 11, s = m & (S_ - 1);
                float2 r;
                r.x = (C[mt][nt][2 * half + 0] + bv.x) * scale;
                r.y = (C[mt][nt][2 * half + 1] + bv.y) * scale;
                *(float2*)(out + ((size_t)(b * H_ + h) * S_ + s) * DH + d) = r;
            }
        }
    }
}

// ---------------------------------------------------------------------------
// Flash attention, mma.sync bf16 3-term, double-buffered K/V,
// direct-to-fragment mask loads, exp2-domain softmax.
// CTA: 128 q-rows, 8 warps (16 rows each), K-tile 64. grid (S/128, H, B).
// ---------------------------------------------------------------------------
// dynamic smem: buf0 @0, buf1 @36864; each buf: Kh 0 | Kl 9216 | Vh 18432 | Vl 27648
// Q staged in buf1 region during prologue only.
#define ABUF   36864u
#define A_KH   0u
#define A_KL   9216u
#define A_VH   18432u
#define A_VL   27648u
#define ATTN_SMEM (2u * ABUF)   // 73728

__global__ __launch_bounds__(256) void attn_mma_kernel(
    const float* __restrict__ qg, const float* __restrict__ kg,
    const float* __restrict__ vg, const void* __restrict__ mask,
    float* __restrict__ out)
{
    extern __shared__ char asm_[];
    const uint32_t sb = smem_u32(asm_);

    const int tid  = threadIdx.x;
    const int lane = tid & 31;
    const int wid  = tid >> 5;
    const int bz   = blockIdx.z;
    const int h    = blockIdx.y;
    const int q0   = blockIdx.x * 128;

    const size_t bh = (size_t)(bz * H_ + h);
    const float* Qg = qg + (bh * S_ + q0) * DH;
    const float* Kg = kg + bh * S_ * DH;
    const float* Vg = vg + bh * S_ * DH;

    const int flr = lane & 15, flc = lane >> 4;
    const int r_in = lane >> 2;
    const int c_in = 2 * (lane & 3);

    // ---- stage Q into buf1 region, extract fragments ----
#pragma unroll
    for (int i = 0; i < 8; ++i) {
        int s = tid + 256 * i, r = s >> 4, c4 = s & 15;
        float4 v = *(const float4*)(Qg + (size_t)r * DH + c4 * 4);
        uint2 hw, lw;
        split4(v, hw, lw);
        *(uint2*)(asm_ + ABUF + r * 144 + c4 * 8) = hw;                 // Q hi
        *(uint2*)(asm_ + ABUF + 18432 + r * 144 + c4 * 8) = lw;         // Q lo
    }
    __syncthreads();
    uint32_t qh[4][4], ql[4][4];
#pragma unroll
    for (int ks = 0; ks < 4; ++ks) {
        uint32_t off = (uint32_t)((16 * wid + flr) * 144 + ks * 32 + flc * 16);
        ldsm4(sb + ABUF + off, qh[ks]);
        ldsm4(sb + ABUF + 18432 + off, ql[ks]);
    }
    __syncthreads();   // everyone done reading Q from buf1 region

    // ---- KV tile 0 -> buf0 ----
    const int rks = (tid >> 4), cks = tid & 15;   // 16 rows x 16 f4cols? no: r = tid>>4 (0..15)
    // 64x16 float4 slots = 1024, 256 threads -> 4 slots: s = tid + 256*i
    {
        char* buf = asm_;
#pragma unroll
        for (int i = 0; i < 4; ++i) {
            int s = tid + 256 * i, r = s >> 4, c4 = s & 15;
            float4 kv = *(const float4*)(Kg + (size_t)r * DH + c4 * 4);
            uint2 hw, lw;
            split4(kv, hw, lw);
            *(uint2*)(buf + A_KH + r * 144 + c4 * 8) = hw;
            *(uint2*)(buf + A_KL + r * 144 + c4 * 8) = lw;
            float4 vv = *(const float4*)(Vg + (size_t)r * DH + c4 * 4);
            split4(vv, hw, lw);
            *(uint2*)(buf + A_VH + r * 144 + c4 * 8) = hw;
            *(uint2*)(buf + A_VL + r * 144 + c4 * 8) = lw;
        }
    }
    __syncthreads();

    float oC[8][4];
#pragma unroll
    for (int j = 0; j < 8; ++j)
#pragma unroll
        for (int k = 0; k < 4; ++k) oC[j][k] = 0.f;
    float mi0 = NEGINF, mi1 = NEGINF, li0 = 0.f, li1 = 0.f;

    const int mode = g_mask_mode;
    const int rA = q0 + 16 * wid + r_in;       // first fragment row (global q)
    const size_t mrowA = ((size_t)bz * S_ + rA) * S_;
    const size_t mrowB = mrowA + 8 * (size_t)S_;

    for (int kt = 0; kt < S_ / 64; ++kt) {
        const int cur = kt & 1;
        const uint32_t sbuf = sb + (uint32_t)cur * ABUF;
        const bool more = (kt + 1 < S_ / 64);

        // -- prefetch next K/V tile into regs --
        float4 kpre[4], vpre[4];
        if (more) {
            const float* Kn = Kg + (size_t)(kt + 1) * 64 * DH;
            const float* Vn = Vg + (size_t)(kt + 1) * 64 * DH;
#pragma unroll
            for (int i = 0; i < 4; ++i) {
                int s = tid + 256 * i, r = s >> 4, c4 = s & 15;
                kpre[i] = *(const float4*)(Kn + (size_t)r * DH + c4 * 4);
                vpre[i] = *(const float4*)(Vn + (size_t)r * DH + c4 * 4);
            }
        }

        // -- mask loads for this tile (direct to fragments) --
        int2  mi2A[8], mi2B[8];
        unsigned short mu16A[8], mu16B[8];
        float2 mf2A[8], mf2B[8];
        if (mode == 0) {
            const int* mp = (const int*)mask;
#pragma unroll
            for (int nt = 0; nt < 8; ++nt) {
                int col = kt * 64 + 8 * nt + c_in;
                mi2A[nt] = *(const int2*)(mp + mrowA + col);
                mi2B[nt] = *(const int2*)(mp + mrowB + col);
            }
        } else if (mode == 1) {
            const unsigned char* mp = (const unsigned char*)mask;
#pragma unroll
            for (int nt = 0; nt < 8; ++nt) {
                int col = kt * 64 + 8 * nt + c_in;
                mu16A[nt] = *(const unsigned short*)(mp + mrowA + col);
                mu16B[nt] = *(const unsigned short*)(mp + mrowB + col);
            }
        } else {
            const float* mp = (const float*)mask;
#pragma unroll
            for (int nt = 0; nt < 8; ++nt) {
                int col = kt * 64 + 8 * nt + c_in;
                mf2A[nt] = *(const float2*)(mp + mrowA + col);
                mf2B[nt] = *(const float2*)(mp + mrowB + col);
            }
        }

        // -- S = Q K^T --
        float sC[8][4];
#pragma unroll
        for (int j = 0; j < 8; ++j)
#pragma unroll
            for (int k = 0; k < 4; ++k) sC[j][k] = 0.f;

#pragma unroll
        for (int ks = 0; ks < 4; ++ks) {
#pragma unroll
            for (int ntp = 0; ntp < 4; ++ntp) {
                uint32_t boff = (uint32_t)((16 * ntp + flr) * 144 + ks * 32 + flc * 16);
                uint32_t bh4[4], bl4[4];
                ldsm4(sbuf + A_KH + boff, bh4);
                ldsm4(sbuf + A_KL + boff, bl4);
                mma16816(sC[2 * ntp],     qh[ks], bh4[0], bh4[2]);
                mma16816(sC[2 * ntp],     qh[ks], bl4[0], bl4[2]);
                mma16816(sC[2 * ntp],     ql[ks], bh4[0], bh4[2]);
                mma16816(sC[2 * ntp + 1], qh[ks], bh4[1], bh4[3]);
                mma16816(sC[2 * ntp + 1], qh[ks], bl4[1], bl4[3]);
                mma16816(sC[2 * ntp + 1], ql[ks], bh4[1], bh4[3]);
            }
        }

        // -- apply mask --
        if (mode == 0) {
#pragma unroll
            for (int nt = 0; nt < 8; ++nt) {
                if (mi2A[nt].x) sC[nt][0] = NEGINF;
                if (mi2A[nt].y) sC[nt][1] = NEGINF;
                if (mi2B[nt].x) sC[nt][2] = NEGINF;
                if (mi2B[nt].y) sC[nt][3] = NEGINF;
            }
        } else if (mode == 1) {
#pragma unroll
            for (int nt = 0; nt < 8; ++nt) {
                if (mu16A[nt] & 0x00FF) sC[nt][0] = NEGINF;
                if (mu16A[nt] & 0xFF00) sC[nt][1] = NEGINF;
                if (mu16B[nt] & 0x00FF) sC[nt][2] = NEGINF;
                if (mu16B[nt] & 0xFF00) sC[nt][3] = NEGINF;
            }
        } else {
#pragma unroll
            for (int nt = 0; nt < 8; ++nt) {
                if (mf2A[nt].x != 0.f) sC[nt][0] = NEGINF;
                if (mf2A[nt].y != 0.f) sC[nt][1] = NEGINF;
                if (mf2B[nt].x != 0.f) sC[nt][2] = NEGINF;
                if (mf2B[nt].y != 0.f) sC[nt][3] = NEGINF;
            }
        }

        // -- online softmax (log2 domain; Q pre-scaled by log2e/8) --
        float mx0 = NEGINF, mx1 = NEGINF;
#pragma unroll
        for (int nt = 0; nt < 8; ++nt) {
            mx0 = fmaxf(mx0, fmaxf(sC[nt][0], sC[nt][1]));
            mx1 = fmaxf(mx1, fmaxf(sC[nt][2], sC[nt][3]));
        }
        mx0 = fmaxf(mx0, __shfl_xor_sync(0xffffffffu, mx0, 1));
        mx0 = fmaxf(mx0, __shfl_xor_sync(0xffffffffu, mx0, 2));
        mx1 = fmaxf(mx1, __shfl_xor_sync(0xffffffffu, mx1, 1));
        mx1 = fmaxf(mx1, __shfl_xor_sync(0xffffffffu, mx1, 2));

        float mn0 = fmaxf(mi0, mx0), mn1 = fmaxf(mi1, mx1);
        float f0 = ex2f(mi0 - mn0), f1 = ex2f(mi1 - mn1);
        float sum0 = 0.f, sum1 = 0.f;
#pragma unroll
        for (int nt = 0; nt < 8; ++nt) {
            sC[nt][0] = ex2f(sC[nt][0] - mn0);
            sC[nt][1] = ex2f(sC[nt][1] - mn0);
            sC[nt][2] = ex2f(sC[nt][2] - mn1);
            sC[nt][3] = ex2f(sC[nt][3] - mn1);
            sum0 += sC[nt][0] + sC[nt][1];
            sum1 += sC[nt][2] + sC[nt][3];
        }
        sum0 += __shfl_xor_sync(0xffffffffu, sum0, 1);
        sum0 += __shfl_xor_sync(0xffffffffu, sum0, 2);
        sum1 += __shfl_xor_sync(0xffffffffu, sum1, 1);
        sum1 += __shfl_xor_sync(0xffffffffu, sum1, 2);
        li0 = li0 * f0 + sum0;
        li1 = li1 * f1 + sum1;
        mi0 = mn0; mi1 = mn1;
#pragma unroll
        for (int nt = 0; nt < 8; ++nt) {
            oC[nt][0] *= f0; oC[nt][1] *= f0;
            oC[nt][2] *= f1; oC[nt][3] *= f1;
        }

        // -- O += P V --
#pragma unroll
        for (int kp = 0; kp < 4; ++kp) {
            uint32_t pa_h[4], pa_l[4];
            split_pair(sC[2 * kp][0],     sC[2 * kp][1],     pa_h[0], pa_l[0]);
            split_pair(sC[2 * kp][2],     sC[2 * kp][3],     pa_h[1], pa_l[1]);
            split_pair(sC[2 * kp + 1][0], sC[2 * kp + 1][1], pa_h[2], pa_l[2]);
            split_pair(sC[2 * kp + 1][2], sC[2 * kp + 1][3], pa_h[3], pa_l[3]);

            const int trow = kp * 16 + ((lane >> 3) & 1) * 8 + (lane & 7);
            const int tcolh = (lane >> 4) * 8;
#pragma unroll
            for (int ntp = 0; ntp < 4; ++ntp) {
                uint32_t voff = (uint32_t)(trow * 144 + (16 * ntp + tcolh) * 2);
                uint32_t vh4[4], vl4[4];
                ldsm4t(sbuf + A_VH + voff, vh4);
                ldsm4t(sbuf + A_VL + voff, vl4);
                mma16816(oC[2 * ntp],     pa_h, vh4[0], vh4[1]);
                mma16816(oC[2 * ntp],     pa_h, vl4[0], vl4[1]);
                mma16816(oC[2 * ntp],     pa_l, vh4[0], vh4[1]);
                mma16816(oC[2 * ntp + 1], pa_h, vh4[2], vh4[3]);
                mma16816(oC[2 * ntp + 1], pa_h, vl4[2], vl4[3]);
                mma16816(oC[2 * ntp + 1], pa_l, vh4[2], vh4[3]);
            }
        }

        // -- store prefetched K/V into other buffer --
        if (more) {
            char* buf = asm_ + (cur ^ 1) * ABUF;
#pragma unroll
            for (int i = 0; i < 4; ++i) {
                int s = tid + 256 * i, r = s >> 4, c4 = s & 15;
                uint2 hw, lw;
                split4(kpre[i], hw, lw);
                *(uint2*)(buf + A_KH + r * 144 + c4 * 8) = hw;
                *(uint2*)(buf + A_KL + r * 144 + c4 * 8) = lw;
                split4(vpre[i], hw, lw);
                *(uint2*)(buf + A_VH + r * 144 + c4 * 8) = hw;
                *(uint2*)(buf + A_VL + r * 144 + c4 * 8) = lw;
            }
        }
        __syncthreads();
    }

    // ---- epilogue ----
    float inv0 = (li0 > 0.f) ? 1.0f / li0 : 0.f;
    float inv1 = (li1 > 0.f) ? 1.0f / li1 : 0.f;
    const int qr = q0 + 16 * wid + r_in;
    const int d0 = h * DH + c_in;
#pragma unroll
    for (int nt = 0; nt < 8; ++nt) {
        float2 v0, v1;
        v0.x = oC[nt][0] * inv0; v0.y = oC[nt][1] * inv0;
        v1.x = oC[nt][2] * inv1; v1.y = oC[nt][3] * inv1;
        *(float2*)(out + (size_t)(bz * S_ + qr) * DM + d0 + 8 * nt) = v0;
        *(float2*)(out + (size_t)(bz * S_ + qr + 8) * DM + d0 + 8 * nt) = v1;
    }
    (void)rks; (void)cks;
}

// ---------------------------------------------------------------------------
extern "C" void kernel_launch(void* const* d_in, const int* in_sizes, int n_in,
                              void* d_out, int out_size) {
    const float* query = (const float*)d_in[0];
    const float* key   = (const float*)d_in[1];
    const float* value = (const float*)d_in[2];
    const void*  mask  = d_in[3];
    float* out = (float*)d_out;

    float *gq, *gk, *gv;
    cudaGetSymbolAddress((void**)&gq, g_q);
    cudaGetSymbolAddress((void**)&gk, g_k);
    cudaGetSymbolAddress((void**)&gv, g_v);

    detect_mask_kernel<<<1, 256>>>((const unsigned int*)mask);

    ProjArgs pa;
    pa.X[0] = query;                 pa.X[1] = key;                   pa.X[2] = value;
    pa.W[0] = (const float*)d_in[4]; pa.W[1] = (const float*)d_in[6]; pa.W[2] = (const float*)d_in[8];
    pa.bias[0] = (const float*)d_in[5]; pa.bias[1] = (const float*)d_in[7]; pa.bias[2] = (const float*)d_in[9];
    pa.out[0] = gq; pa.out[1] = gk; pa.out[2] = gv;
    pa.scale[0] = QSCALE; pa.scale[1] = 1.0f; pa.scale[2] = 1.0f;

    static int attr_done = 0;
    if (!attr_done) {
        cudaFuncSetAttribute(proj_mma_kernel,
                             cudaFuncAttributeMaxDynamicSharedMemorySize, PROJ_SMEM);
        cudaFuncSetAttribute(attn_mma_kernel,
                             cudaFuncAttributeMaxDynamicSharedMemorySize, ATTN_SMEM);
        attr_done = 1;
    }

    dim3 pgrid(DM / 128, M_ / 128, 3);   // (8, 32, 3) = 768 CTAs
    proj_mma_kernel<<<pgrid, 512, PROJ_SMEM>>>(pa);

    dim3 agrid(S_ / 128, H_, B_);        // (16, 16, 2) = 512 CTAs
    attn_mma_kernel<<<agrid, 256, ATTN_SMEM>>>(gq, gk, gv, mask, out);
}

// round 5
// speedup vs baseline: 2.4636x; 1.0620x over previous
#include <cuda_runtime.h>
#include <cuda_bf16.h>
#include <cstdint>
#include <cstddef>

#define B_  2
#define S_  2048
#define DM  1024
#define H_  16
#define DH  64
#define M_  (B_*S_)   // 4096
#define NEGINF -1e30f
// Q projection scale: (1/sqrt(DH)) * log2(e) -> softmax via exp2
#define QSCALE (0.125f * 1.44269504088896f)

#define XSEG (M_*DM)      // 4194304
#define WSEG (DM*DM)      // 1048576
#define QKV  (B_*H_*S_*DH)

// split-bf16 planes (hi + lo), written once
__device__ unsigned short g_xh[3*XSEG], g_xl[3*XSEG];
__device__ unsigned short g_wh[3*WSEG], g_wl[3*WSEG];
__device__ unsigned short g_qh[QKV], g_ql[QKV];
__device__ unsigned short g_kh[QKV], g_kl[QKV];
__device__ unsigned short g_vh[QKV], g_vl[QKV];
__device__ int g_mask_mode;

// ---------------------------------------------------------------------------
// Helpers
// ---------------------------------------------------------------------------
__device__ __forceinline__ uint32_t smem_u32(const void* p) {
    uint32_t a;
    asm("{ .reg .u64 t; cvta.to.shared.u64 t, %1; cvt.u32.u64 %0, t; }"
        : "=r"(a) : "l"(p));
    return a;
}
__device__ __forceinline__ void ldsm4(uint32_t addr, uint32_t* r) {
    asm volatile("ldmatrix.sync.aligned.m8n8.x4.shared.b16 {%0,%1,%2,%3}, [%4];"
        : "=r"(r[0]), "=r"(r[1]), "=r"(r[2]), "=r"(r[3]) : "r"(addr));
}
__device__ __forceinline__ void ldsm4t(uint32_t addr, uint32_t* r) {
    asm volatile("ldmatrix.sync.aligned.m8n8.x4.trans.shared.b16 {%0,%1,%2,%3}, [%4];"
        : "=r"(r[0]), "=r"(r[1]), "=r"(r[2]), "=r"(r[3]) : "r"(addr));
}
__device__ __forceinline__ void mma16816(float* c, const uint32_t* a,
                                         uint32_t b0, uint32_t b1) {
    asm volatile(
        "mma.sync.aligned.m16n8k16.row.col.f32.bf16.bf16.f32 "
        "{%0,%1,%2,%3}, {%4,%5,%6,%7}, {%8,%9}, {%0,%1,%2,%3};"
        : "+f"(c[0]), "+f"(c[1]), "+f"(c[2]), "+f"(c[3])
        : "r"(a[0]), "r"(a[1]), "r"(a[2]), "r"(a[3]), "r"(b0), "r"(b1));
}
__device__ __forceinline__ uint32_t cvt2_bf16(float lo_elem, float hi_elem) {
    uint32_t r;
    asm("cvt.rn.bf16x2.f32 %0, %1, %2;" : "=r"(r) : "f"(hi_elem), "f"(lo_elem));
    return r;
}
__device__ __forceinline__ float bf16lo_f(uint32_t v) { return __uint_as_float(v << 16); }
__device__ __forceinline__ float bf16hi_f(uint32_t v) { return __uint_as_float(v & 0xFFFF0000u); }
__device__ __forceinline__ void split_pair(float x, float y, uint32_t& h, uint32_t& l) {
    h = cvt2_bf16(x, y);
    float rx = x - bf16lo_f(h);
    float ry = y - bf16hi_f(h);
    l = cvt2_bf16(rx, ry);
}
__device__ __forceinline__ void split4(float4 v, uint2& hw, uint2& lw) {
    uint32_t h0, l0, h1, l1;
    split_pair(v.x, v.y, h0, l0);
    split_pair(v.z, v.w, h1, l1);
    hw.x = h0; hw.y = h1; lw.x = l0; lw.y = l1;
}
__device__ __forceinline__ float ex2f(float x) {
    float y;
    asm("ex2.approx.f32 %0, %1;" : "=f"(y) : "f"(x));
    return y;
}
#define CP16(dst, src) \
    asm volatile("cp.async.cg.shared.global [%0], [%1], 16;" :: "r"(dst), "l"(src))
#define CP_COMMIT() asm volatile("cp.async.commit_group;")
#define CP_WAIT1()  asm volatile("cp.async.wait_group 1;")
#define CP_WAIT0()  asm volatile("cp.async.wait_group 0;")

// ---------------------------------------------------------------------------
// Convert: fp32 -> split bf16 planes; z==6 slice does mask dtype detection.
// ---------------------------------------------------------------------------
struct ConvArgs { const float* src[6]; };

__global__ __launch_bounds__(256) void convert_kernel(ConvArgs a,
                                                      const unsigned int* mask) {
    const int z = blockIdx.z;
    const int tid = threadIdx.x;
    if (z == 6) {
        if (blockIdx.x != 0) return;
        int ok_i32 = 1, ok_u8 = 1;
        for (int i = tid; i < 4096; i += 256) {
            unsigned w = mask[i];
            ok_i32 &= (w <= 1u);
            ok_u8  &= ((w & 0xFEFEFEFEu) == 0u);
        }
        ok_i32 = __syncthreads_and(ok_i32);
        ok_u8  = __syncthreads_and(ok_u8);
        if (tid == 0) g_mask_mode = ok_i32 ? 0 : (ok_u8 ? 1 : 2);
        return;
    }
    const float4* src = (const float4*)a.src[z];
    int nf4;
    unsigned short *dh, *dl;
    if (z < 3) { nf4 = XSEG / 4; dh = g_xh + (size_t)z * XSEG; dl = g_xl + (size_t)z * XSEG; }
    else       { nf4 = WSEG / 4; dh = g_wh + (size_t)(z - 3) * WSEG; dl = g_wl + (size_t)(z - 3) * WSEG; }
    for (int i = blockIdx.x * 256 + tid; i < nf4; i += 1024 * 256) {
        float4 v = src[i];
        uint2 hw, lw;
        split4(v, hw, lw);
        ((uint2*)dh)[i] = hw;
        ((uint2*)dl)[i] = lw;
    }
}

// ---------------------------------------------------------------------------
// Projection GEMM: bf16 planes in, 3-stage cp.async pipeline, mma.sync 3-term.
// BM=BN=128, BK=32, 256 threads (8 warps: 4m x 2n, warp tile 32x64).
// Output: split bf16 hi/lo planes in head-split layout [B,H,S,Dh].
// Stage (32KB): Ah@0 | Al@8K | Bh@16K | Bl@24K; rows 64B, XOR-swizzled.
// ---------------------------------------------------------------------------
#define PROJ_SMEM 98304u

struct ProjArgs { const float* bias[3]; float scale[3]; };

__device__ __forceinline__ void proj_issue(
    uint32_t sb, int st, int kt, int tid, int m0, int n0,
    const unsigned short* Xh, const unsigned short* Xl,
    const unsigned short* Wh, const unsigned short* Wl)
{
#pragma unroll
    for (int j = 0; j < 8; ++j) {
        int cid = tid + 256 * j;
        int sub = cid >> 9, w = cid & 511, row = w >> 2, c = w & 3;
        const unsigned short* plane = (sub == 0) ? Xh : (sub == 1) ? Xl
                                     : (sub == 2) ? Wh : Wl;
        int rb = (sub < 2) ? m0 : n0;
        const void* src = plane + (size_t)(rb + row) * DM + kt * 32 + c * 8;
        uint32_t dst = sb + (uint32_t)st * 32768u + (uint32_t)sub * 8192u
                     + (uint32_t)row * 64u + (uint32_t)((c ^ ((row >> 1) & 3)) << 4);
        CP16(dst, src);
    }
    CP_COMMIT();
}

__global__ __launch_bounds__(256) void proj_mma_kernel(ProjArgs args) {
    extern __shared__ char ps[];
    const uint32_t sb = smem_u32(ps);
    const int z = blockIdx.z;
    const unsigned short* __restrict__ Xh = g_xh + (size_t)z * XSEG;
    const unsigned short* __restrict__ Xl = g_xl + (size_t)z * XSEG;
    const unsigned short* __restrict__ Wh = g_wh + (size_t)z * WSEG;
    const unsigned short* __restrict__ Wl = g_wl + (size_t)z * WSEG;
    const float* __restrict__ bias = args.bias[z];
    unsigned short* __restrict__ oh = (z == 0) ? g_qh : (z == 1) ? g_kh : g_vh;
    unsigned short* __restrict__ ol = (z == 0) ? g_ql : (z == 1) ? g_kl : g_vl;
    const float scale = args.scale[z];

    const int tid = threadIdx.x, lane = tid & 31, wid = tid >> 5;
    const int wm = wid & 3, wn = wid >> 2;
    const int m0 = blockIdx.y * 128, n0 = blockIdx.x * 128;
    const int flr = lane & 15, flc = lane >> 4;

    float C[2][8][4];
#pragma unroll
    for (int i = 0; i < 2; ++i)
#pragma unroll
        for (int j = 0; j < 8; ++j)
#pragma unroll
            for (int k = 0; k < 4; ++k) C[i][j][k] = 0.f;

    proj_issue(sb, 0, 0, tid, m0, n0, Xh, Xl, Wh, Wl);
    proj_issue(sb, 1, 1, tid, m0, n0, Xh, Xl, Wh, Wl);

    for (int kt = 0; kt < 32; ++kt) {
        if (kt < 31) CP_WAIT1(); else CP_WAIT0();
        __syncthreads();
        if (kt + 2 < 32)
            proj_issue(sb, (kt + 2) % 3, kt + 2, tid, m0, n0, Xh, Xl, Wh, Wl);

        const uint32_t base = sb + (uint32_t)(kt % 3) * 32768u;
#pragma unroll
        for (int ks = 0; ks < 2; ++ks) {
            const uint32_t csw = (uint32_t)(((2 * ks + flc) ^ ((flr >> 1) & 3)) << 4);
            uint32_t a_h[2][4], a_l[2][4];
#pragma unroll
            for (int mt = 0; mt < 2; ++mt) {
                uint32_t off = (uint32_t)((32 * wm + 16 * mt + flr) * 64) + csw;
                ldsm4(base + off, a_h[mt]);
                ldsm4(base + 8192u + off, a_l[mt]);
            }
#pragma unroll
            for (int ntp = 0; ntp < 4; ++ntp) {
                uint32_t boff = (uint32_t)((64 * wn + 16 * ntp + flr) * 64) + csw;
                uint32_t bh4[4], bl4[4];
                ldsm4(base + 16384u + boff, bh4);
                ldsm4(base + 24576u + boff, bl4);
#pragma unroll
                for (int mt = 0; mt < 2; ++mt) {
                    mma16816(C[mt][2 * ntp],     a_h[mt], bh4[0], bh4[2]);
                    mma16816(C[mt][2 * ntp],     a_h[mt], bl4[0], bl4[2]);
                    mma16816(C[mt][2 * ntp],     a_l[mt], bh4[0], bh4[2]);
                    mma16816(C[mt][2 * ntp + 1], a_h[mt], bh4[1], bh4[3]);
                    mma16816(C[mt][2 * ntp + 1], a_h[mt], bl4[1], bl4[3]);
                    mma16816(C[mt][2 * ntp + 1], a_l[mt], bh4[1], bh4[3]);
                }
            }
        }
    }

    // epilogue: bias + scale, split to hi/lo, head-split stores
#pragma unroll
    for (int nt = 0; nt < 8; ++nt) {
        int n = n0 + 64 * wn + 8 * nt + 2 * (lane & 3);
        int h = n >> 6, d = n & 63;
        float2 bv = *(const float2*)(bias + n);
#pragma unroll
        for (int mt = 0; mt < 2; ++mt) {
            int mbase = m0 + 32 * wm + 16 * mt + (lane >> 2);
#pragma unroll
            for (int half = 0; half < 2; ++half) {
                int m = mbase + 8 * half;
                int b = m >> 11, s = m & (S_ - 1);
                float vx = (C[mt][nt][2 * half + 0] + bv.x) * scale;
                float vy = (C[mt][nt][2 * half + 1] + bv.y) * scale;
                uint32_t hw, lw;
                split_pair(vx, vy, hw, lw);
                size_t off = ((size_t)(b * H_ + h) * S_ + s) * DH + d;
                *(uint32_t*)(oh + off) = hw;
                *(uint32_t*)(ol + off) = lw;
            }
        }
    }
}

// ---------------------------------------------------------------------------
// Flash attention: pre-split bf16 Q/K/V planes, 3-stage cp.async K/V pipeline,
// direct-to-fragment mask, exp2 softmax. CTA: 128 q-rows, 8 warps, K-tile 64.
// smem: KV stages 0..2 @ st*32768 (Kh|Kl|Vh|Vl, 8KB each, 128B rows, swizzled)
//       Qh @ 98304, Ql @ 114688.  Total 131072.
// ---------------------------------------------------------------------------
#define ATTN_SMEM 131072u

__device__ __forceinline__ void attn_issue_kv(uint32_t sb, int st, int kt,
                                              int tid, size_t bhS) {
#pragma unroll
    for (int j = 0; j < 8; ++j) {
        int cid = tid + 256 * j;
        int sub = cid >> 9, w = cid & 511, row = w >> 3, c = w & 7;
        const unsigned short* plane = (sub == 0) ? g_kh : (sub == 1) ? g_kl
                                     : (sub == 2) ? g_vh : g_vl;
        const void* src = plane + (bhS + (size_t)(kt * 64 + row)) * DH + c * 8;
        uint32_t dst = sb + (uint32_t)st * 32768u + (uint32_t)sub * 8192u
                     + (uint32_t)row * 128u + (uint32_t)((c ^ (row & 7)) << 4);
        CP16(dst, src);
    }
    CP_COMMIT();
}

__global__ __launch_bounds__(256) void attn_mma_kernel(
    const void* __restrict__ mask, float* __restrict__ out)
{
    extern __shared__ char as_[];
    const uint32_t sb = smem_u32(as_);

    const int tid = threadIdx.x, lane = tid & 31, wid = tid >> 5;
    const int bz = blockIdx.z, h = blockIdx.y;
    const int q0 = blockIdx.x * 128;
    const size_t bhS = (size_t)(bz * H_ + h) * S_;

    const int flr = lane & 15, flc = lane >> 4;
    const int r_in = lane >> 2;
    const int c_in = 2 * (lane & 3);

    // prologue: Q planes + first two K/V tiles
    {
#pragma unroll
        for (int j = 0; j < 8; ++j) {
            int cid = tid + 256 * j;
            int sub = cid >> 10, w = cid & 1023, row = w >> 3, c = w & 7;
            const unsigned short* plane = sub ? g_ql : g_qh;
            const void* src = plane + (bhS + (size_t)(q0 + row)) * DH + c * 8;
            uint32_t dst = sb + 98304u + (uint32_t)sub * 16384u
                         + (uint32_t)row * 128u + (uint32_t)((c ^ (row & 7)) << 4);
            CP16(dst, src);
        }
    }
    attn_issue_kv(sb, 0, 0, tid, bhS);   // commits group 0 (Q + tile0)
    attn_issue_kv(sb, 1, 1, tid, bhS);   // group 1
    CP_WAIT1();
    __syncthreads();

    // Q fragments (held in registers for whole kernel)
    uint32_t qh[4][4], ql[4][4];
#pragma unroll
    for (int ks = 0; ks < 4; ++ks) {
        uint32_t off = 98304u + (uint32_t)((16 * wid + flr) * 128)
                     + (uint32_t)(((2 * ks + flc) ^ (flr & 7)) << 4);
        ldsm4(sb + off, qh[ks]);
        ldsm4(sb + off + 16384u, ql[ks]);
    }

    float oC[8][4];
#pragma unroll
    for (int j = 0; j < 8; ++j)
#pragma unroll
        for (int k = 0; k < 4; ++k) oC[j][k] = 0.f;
    float mi0 = NEGINF, mi1 = NEGINF, li0 = 0.f, li1 = 0.f;

    const int mode = g_mask_mode;
    const int rA = q0 + 16 * wid + r_in;
    const size_t mrowA = ((size_t)bz * S_ + rA) * S_;
    const size_t mrowB = mrowA + 8 * (size_t)S_;

    for (int kt = 0; kt < 32; ++kt) {
        if (kt) {
            if (kt < 31) CP_WAIT1(); else CP_WAIT0();
            __syncthreads();
        }
        if (kt + 2 < 32) attn_issue_kv(sb, (kt + 2) % 3, kt + 2, tid, bhS);

        const uint32_t base = sb + (uint32_t)(kt % 3) * 32768u;

        // -- mask loads (direct to fragments) --
        int2  mi2A[8], mi2B[8];
        unsigned short mu16A[8], mu16B[8];
        float2 mf2A[8], mf2B[8];
        if (mode == 0) {
            const int* mp = (const int*)mask;
#pragma unroll
            for (int nt = 0; nt < 8; ++nt) {
                int col = kt * 64 + 8 * nt + c_in;
                mi2A[nt] = *(const int2*)(mp + mrowA + col);
                mi2B[nt] = *(const int2*)(mp + mrowB + col);
            }
        } else if (mode == 1) {
            const unsigned char* mp = (const unsigned char*)mask;
#pragma unroll
            for (int nt = 0; nt < 8; ++nt) {
                int col = kt * 64 + 8 * nt + c_in;
                mu16A[nt] = *(const unsigned short*)(mp + mrowA + col);
                mu16B[nt] = *(const unsigned short*)(mp + mrowB + col);
            }
        } else {
            const float* mp = (const float*)mask;
#pragma unroll
            for (int nt = 0; nt < 8; ++nt) {
                int col = kt * 64 + 8 * nt + c_in;
                mf2A[nt] = *(const float2*)(mp + mrowA + col);
                mf2B[nt] = *(const float2*)(mp + mrowB + col);
            }
        }

        // -- S = Q K^T --
        float sC[8][4];
#pragma unroll
        for (int j = 0; j < 8; ++j)
#pragma unroll
            for (int k = 0; k < 4; ++k) sC[j][k] = 0.f;

#pragma unroll
        for (int ks = 0; ks < 4; ++ks) {
#pragma unroll
            for (int ntp = 0; ntp < 4; ++ntp) {
                uint32_t koff = (uint32_t)((16 * ntp + flr) * 128)
                              + (uint32_t)(((2 * ks + flc) ^ (flr & 7)) << 4);
                uint32_t bh4[4], bl4[4];
                ldsm4(base + koff, bh4);
                ldsm4(base + 8192u + koff, bl4);
                mma16816(sC[2 * ntp],     qh[ks], bh4[0], bh4[2]);
                mma16816(sC[2 * ntp],     qh[ks], bl4[0], bl4[2]);
                mma16816(sC[2 * ntp],     ql[ks], bh4[0], bh4[2]);
                mma16816(sC[2 * ntp + 1], qh[ks], bh4[1], bh4[3]);
                mma16816(sC[2 * ntp + 1], qh[ks], bl4[1], bl4[3]);
                mma16816(sC[2 * ntp + 1], ql[ks], bh4[1], bh4[3]);
            }
        }

        // -- apply mask --
        if (mode == 0) {
#pragma unroll
            for (int nt = 0; nt < 8; ++nt) {
                if (mi2A[nt].x) sC[nt][0] = NEGINF;
                if (mi2A[nt].y) sC[nt][1] = NEGINF;
                if (mi2B[nt].x) sC[nt][2] = NEGINF;
                if (mi2B[nt].y) sC[nt][3] = NEGINF;
            }
        } else if (mode == 1) {
#pragma unroll
            for (int nt = 0; nt < 8; ++nt) {
                if (mu16A[nt] & 0x00FF) sC[nt][0] = NEGINF;
                if (mu16A[nt] & 0xFF00) sC[nt][1] = NEGINF;
                if (mu16B[nt] & 0x00FF) sC[nt][2] = NEGINF;
                if (mu16B[nt] & 0xFF00) sC[nt][3] = NEGINF;
            }
        } else {
#pragma unroll
            for (int nt = 0; nt < 8; ++nt) {
                if (mf2A[nt].x != 0.f) sC[nt][0] = NEGINF;
                if (mf2A[nt].y != 0.f) sC[nt][1] = NEGINF;
                if (mf2B[nt].x != 0.f) sC[nt][2] = NEGINF;
                if (mf2B[nt].y != 0.f) sC[nt][3] = NEGINF;
            }
        }

        // -- online softmax (log2 domain) --
        float mx0 = NEGINF, mx1 = NEGINF;
#pragma unroll
        for (int nt = 0; nt < 8; ++nt) {
            mx0 = fmaxf(mx0, fmaxf(sC[nt][0], sC[nt][1]));
            mx1 = fmaxf(mx1, fmaxf(sC[nt][2], sC[nt][3]));
        }
        mx0 = fmaxf(mx0, __shfl_xor_sync(0xffffffffu, mx0, 1));
        mx0 = fmaxf(mx0, __shfl_xor_sync(0xffffffffu, mx0, 2));
        mx1 = fmaxf(mx1, __shfl_xor_sync(0xffffffffu, mx1, 1));
        mx1 = fmaxf(mx1, __shfl_xor_sync(0xffffffffu, mx1, 2));

        float mn0 = fmaxf(mi0, mx0), mn1 = fmaxf(mi1, mx1);
        float f0 = ex2f(mi0 - mn0), f1 = ex2f(mi1 - mn1);
        float sum0 = 0.f, sum1 = 0.f;
#pragma unroll
        for (int nt = 0; nt < 8; ++nt) {
            sC[nt][0] = ex2f(sC[nt][0] - mn0);
            sC[nt][1] = ex2f(sC[nt][1] - mn0);
            sC[nt][2] = ex2f(sC[nt][2] - mn1);
            sC[nt][3] = ex2f(sC[nt][3] - mn1);
            sum0 += sC[nt][0] + sC[nt][1];
            sum1 += sC[nt][2] + sC[nt][3];
        }
        sum0 += __shfl_xor_sync(0xffffffffu, sum0, 1);
        sum0 += __shfl_xor_sync(0xffffffffu, sum0, 2);
        sum1 += __shfl_xor_sync(0xffffffffu, sum1, 1);
        sum1 += __shfl_xor_sync(0xffffffffu, sum1, 2);
        li0 = li0 * f0 + sum0;
        li1 = li1 * f1 + sum1;
        mi0 = mn0; mi1 = mn1;
#pragma unroll
        for (int nt = 0; nt < 8; ++nt) {
            oC[nt][0] *= f0; oC[nt][1] *= f0;
            oC[nt][2] *= f1; oC[nt][3] *= f1;
        }

        // -- O += P V --
#pragma unroll
        for (int kp = 0; kp < 4; ++kp) {
            uint32_t pa_h[4], pa_l[4];
            split_pair(sC[2 * kp][0],     sC[2 * kp][1],     pa_h[0], pa_l[0]);
            split_pair(sC[2 * kp][2],     sC[2 * kp][3],     pa_h[1], pa_l[1]);
            split_pair(sC[2 * kp + 1][0], sC[2 * kp + 1][1], pa_h[2], pa_l[2]);
            split_pair(sC[2 * kp + 1][2], sC[2 * kp + 1][3], pa_h[3], pa_l[3]);

            const int trow = kp * 16 + ((lane >> 3) & 1) * 8 + (lane & 7);
            const int cb = lane >> 4;
#pragma unroll
            for (int ntp = 0; ntp < 4; ++ntp) {
                uint32_t voff = (uint32_t)(trow * 128)
                              + (uint32_t)(((2 * ntp + cb) ^ (trow & 7)) << 4);
                uint32_t vh4[4], vl4[4];
                ldsm4t(base + 16384u + voff, vh4);
                ldsm4t(base + 24576u + voff, vl4);
                mma16816(oC[2 * ntp],     pa_h, vh4[0], vh4[1]);
                mma16816(oC[2 * ntp],     pa_h, vl4[0], vl4[1]);
                mma16816(oC[2 * ntp],     pa_l, vh4[0], vh4[1]);
                mma16816(oC[2 * ntp + 1], pa_h, vh4[2], vh4[3]);
                mma16816(oC[2 * ntp + 1], pa_h, vl4[2], vl4[3]);
                mma16816(oC[2 * ntp + 1], pa_l, vh4[2], vh4[3]);
            }
        }
    }

    // ---- epilogue ----
    float inv0 = (li0 > 0.f) ? 1.0f / li0 : 0.f;
    float inv1 = (li1 > 0.f) ? 1.0f / li1 : 0.f;
    const int qr = q0 + 16 * wid + r_in;
    const int d0 = h * DH + c_in;
#pragma unroll
    for (int nt = 0; nt < 8; ++nt) {
        float2 v0, v1;
        v0.x = oC[nt][0] * inv0; v0.y = oC[nt][1] * inv0;
        v1.x = oC[nt][2] * inv1; v1.y = oC[nt][3] * inv1;
        *(float2*)(out + (size_t)(bz * S_ + qr) * DM + d0 + 8 * nt) = v0;
        *(float2*)(out + (size_t)(bz * S_ + qr + 8) * DM + d0 + 8 * nt) = v1;
    }
}

// ---------------------------------------------------------------------------
extern "C" void kernel_launch(void* const* d_in, const int* in_sizes, int n_in,
                              void* d_out, int out_size) {
    const void* mask = d_in[3];
    float* out = (float*)d_out;

    static int attr_done = 0;
    if (!attr_done) {
        cudaFuncSetAttribute(proj_mma_kernel,
                             cudaFuncAttributeMaxDynamicSharedMemorySize, PROJ_SMEM);
        cudaFuncSetAttribute(attn_mma_kernel,
                             cudaFuncAttributeMaxDynamicSharedMemorySize, ATTN_SMEM);
        attr_done = 1;
    }

    ConvArgs ca;
    ca.src[0] = (const float*)d_in[0];   // query
    ca.src[1] = (const float*)d_in[1];   // key
    ca.src[2] = (const float*)d_in[2];   // value
    ca.src[3] = (const float*)d_in[4];   // Wq
    ca.src[4] = (const float*)d_in[6];   // Wk
    ca.src[5] = (const float*)d_in[8];   // Wv
    convert_kernel<<<dim3(1024, 1, 7), 256>>>(ca, (const unsigned int*)mask);

    ProjArgs pa;
    pa.bias[0] = (const float*)d_in[5];
    pa.bias[1] = (const float*)d_in[7];
    pa.bias[2] = (const float*)d_in[9];
    pa.scale[0] = QSCALE; pa.scale[1] = 1.0f; pa.scale[2] = 1.0f;
    proj_mma_kernel<<<dim3(8, 32, 3), 256, PROJ_SMEM>>>(pa);

    attn_mma_kernel<<<dim3(16, 16, 2), 256, ATTN_SMEM>>>(mask, out);
}

// round 6
// speedup vs baseline: 2.4759x; 1.0050x over previous
#include <cuda_runtime.h>
#include <cuda_bf16.h>
#include <cstdint>
#include <cstddef>

#define B_  2
#define S_  2048
#define DM  1024
#define H_  16
#define DH  64
#define M_  (B_*S_)   // 4096
#define NEGINF -1e30f
// Q projection scale: (1/sqrt(DH)) * log2(e) -> softmax via exp2
#define QSCALE (0.125f * 1.44269504088896f)

#define XSEG (M_*DM)      // 4194304
#define WSEG (DM*DM)      // 1048576
#define QKV  (B_*H_*S_*DH)

// split-bf16 planes (hi + lo), written once
__device__ unsigned short g_xh[3*XSEG], g_xl[3*XSEG];
__device__ unsigned short g_wh[3*WSEG], g_wl[3*WSEG];
__device__ unsigned short g_qh[QKV], g_ql[QKV];
__device__ unsigned short g_kh[QKV], g_kl[QKV];
__device__ unsigned short g_vh[QKV], g_vl[QKV];
__device__ int g_mask_mode;

// ---------------------------------------------------------------------------
// Helpers
// ---------------------------------------------------------------------------
__device__ __forceinline__ uint32_t smem_u32(const void* p) {
    uint32_t a;
    asm("{ .reg .u64 t; cvta.to.shared.u64 t, %1; cvt.u32.u64 %0, t; }"
        : "=r"(a) : "l"(p));
    return a;
}
__device__ __forceinline__ void ldsm4(uint32_t addr, uint32_t* r) {
    asm volatile("ldmatrix.sync.aligned.m8n8.x4.shared.b16 {%0,%1,%2,%3}, [%4];"
        : "=r"(r[0]), "=r"(r[1]), "=r"(r[2]), "=r"(r[3]) : "r"(addr));
}
__device__ __forceinline__ void ldsm4t(uint32_t addr, uint32_t* r) {
    asm volatile("ldmatrix.sync.aligned.m8n8.x4.trans.shared.b16 {%0,%1,%2,%3}, [%4];"
        : "=r"(r[0]), "=r"(r[1]), "=r"(r[2]), "=r"(r[3]) : "r"(addr));
}
__device__ __forceinline__ void mma16816(float* c, const uint32_t* a,
                                         uint32_t b0, uint32_t b1) {
    asm volatile(
        "mma.sync.aligned.m16n8k16.row.col.f32.bf16.bf16.f32 "
        "{%0,%1,%2,%3}, {%4,%5,%6,%7}, {%8,%9}, {%0,%1,%2,%3};"
        : "+f"(c[0]), "+f"(c[1]), "+f"(c[2]), "+f"(c[3])
        : "r"(a[0]), "r"(a[1]), "r"(a[2]), "r"(a[3]), "r"(b0), "r"(b1));
}
__device__ __forceinline__ uint32_t cvt2_bf16(float lo_elem, float hi_elem) {
    uint32_t r;
    asm("cvt.rn.bf16x2.f32 %0, %1, %2;" : "=r"(r) : "f"(hi_elem), "f"(lo_elem));
    return r;
}
__device__ __forceinline__ float bf16lo_f(uint32_t v) { return __uint_as_float(v << 16); }
__device__ __forceinline__ float bf16hi_f(uint32_t v) { return __uint_as_float(v & 0xFFFF0000u); }
__device__ __forceinline__ void split_pair(float x, float y, uint32_t& h, uint32_t& l) {
    h = cvt2_bf16(x, y);
    float rx = x - bf16lo_f(h);
    float ry = y - bf16hi_f(h);
    l = cvt2_bf16(rx, ry);
}
__device__ __forceinline__ void split4(float4 v, uint2& hw, uint2& lw) {
    uint32_t h0, l0, h1, l1;
    split_pair(v.x, v.y, h0, l0);
    split_pair(v.z, v.w, h1, l1);
    hw.x = h0; hw.y = h1; lw.x = l0; lw.y = l1;
}
__device__ __forceinline__ float ex2f(float x) {
    float y;
    asm("ex2.approx.f32 %0, %1;" : "=f"(y) : "f"(x));
    return y;
}
#define CP16(dst, src) \
    asm volatile("cp.async.cg.shared.global [%0], [%1], 16;" :: "r"(dst), "l"(src))
#define CP_COMMIT() asm volatile("cp.async.commit_group;")
#define CP_WAIT1()  asm volatile("cp.async.wait_group 1;")
#define CP_WAIT0()  asm volatile("cp.async.wait_group 0;")

// ---------------------------------------------------------------------------
// Convert: fp32 -> split bf16 planes (paired float4: 32B in, 2x16B out).
// z==6 slice does mask dtype detection.
// ---------------------------------------------------------------------------
struct ConvArgs { const float* src[6]; };

__global__ __launch_bounds__(256) void convert_kernel(ConvArgs a,
                                                      const unsigned int* mask) {
    const int z = blockIdx.z;
    const int tid = threadIdx.x;
    if (z == 6) {
        if (blockIdx.x != 0) return;
        int ok_i32 = 1, ok_u8 = 1;
        for (int i = tid; i < 4096; i += 256) {
            unsigned w = mask[i];
            ok_i32 &= (w <= 1u);
            ok_u8  &= ((w & 0xFEFEFEFEu) == 0u);
        }
        ok_i32 = __syncthreads_and(ok_i32);
        ok_u8  = __syncthreads_and(ok_u8);
        if (tid == 0) g_mask_mode = ok_i32 ? 0 : (ok_u8 ? 1 : 2);
        return;
    }
    const float4* src = (const float4*)a.src[z];
    int nf8;   // number of 8-float chunks
    unsigned short *dh, *dl;
    if (z < 3) { nf8 = XSEG / 8; dh = g_xh + (size_t)z * XSEG; dl = g_xl + (size_t)z * XSEG; }
    else       { nf8 = WSEG / 8; dh = g_wh + (size_t)(z - 3) * WSEG; dl = g_wl + (size_t)(z - 3) * WSEG; }
    for (int i = blockIdx.x * 256 + tid; i < nf8; i += 1024 * 256) {
        float4 v0 = src[2 * i];
        float4 v1 = src[2 * i + 1];
        uint2 h0, l0, h1, l1;
        split4(v0, h0, l0);
        split4(v1, h1, l1);
        uint4 hv, lv;
        hv.x = h0.x; hv.y = h0.y; hv.z = h1.x; hv.w = h1.y;
        lv.x = l0.x; lv.y = l0.y; lv.z = l1.x; lv.w = l1.y;
        ((uint4*)dh)[i] = hv;
        ((uint4*)dl)[i] = lv;
    }
}

// ---------------------------------------------------------------------------
// Projection GEMM: bf16 planes in, 3-stage cp.async pipeline, mma.sync 3-term.
// BM=BN=128, BK=32, 256 threads (8 warps: 4m x 2n, warp tile 32x64).
// Output: split bf16 hi/lo planes in head-split layout [B,H,S,Dh].
// Stage (32KB): Ah@0 | Al@8K | Bh@16K | Bl@24K; rows 64B, XOR-swizzled.
// ---------------------------------------------------------------------------
#define PROJ_SMEM 98304u

struct ProjArgs { const float* bias[3]; float scale[3]; };

__device__ __forceinline__ void proj_issue(
    uint32_t sb, int st, int kt, int tid, int m0, int n0,
    const unsigned short* Xh, const unsigned short* Xl,
    const unsigned short* Wh, const unsigned short* Wl)
{
#pragma unroll
    for (int j = 0; j < 8; ++j) {
        int cid = tid + 256 * j;
        int sub = cid >> 9, w = cid & 511, row = w >> 2, c = w & 3;
        const unsigned short* plane = (sub == 0) ? Xh : (sub == 1) ? Xl
                                     : (sub == 2) ? Wh : Wl;
        int rb = (sub < 2) ? m0 : n0;
        const void* src = plane + (size_t)(rb + row) * DM + kt * 32 + c * 8;
        uint32_t dst = sb + (uint32_t)st * 32768u + (uint32_t)sub * 8192u
                     + (uint32_t)row * 64u + (uint32_t)((c ^ ((row >> 1) & 3)) << 4);
        CP16(dst, src);
    }
    CP_COMMIT();
}

__global__ __launch_bounds__(256, 2) void proj_mma_kernel(ProjArgs args) {
    extern __shared__ char ps[];
    const uint32_t sb = smem_u32(ps);
    const int z = blockIdx.z;
    const unsigned short* __restrict__ Xh = g_xh + (size_t)z * XSEG;
    const unsigned short* __restrict__ Xl = g_xl + (size_t)z * XSEG;
    const unsigned short* __restrict__ Wh = g_wh + (size_t)z * WSEG;
    const unsigned short* __restrict__ Wl = g_wl + (size_t)z * WSEG;
    const float* __restrict__ bias = args.bias[z];
    unsigned short* __restrict__ oh = (z == 0) ? g_qh : (z == 1) ? g_kh : g_vh;
    unsigned short* __restrict__ ol = (z == 0) ? g_ql : (z == 1) ? g_kl : g_vl;
    const float scale = args.scale[z];

    const int tid = threadIdx.x, lane = tid & 31, wid = tid >> 5;
    const int wm = wid & 3, wn = wid >> 2;
    const int m0 = blockIdx.y * 128, n0 = blockIdx.x * 128;
    const int flr = lane & 15, flc = lane >> 4;

    float C[2][8][4];
#pragma unroll
    for (int i = 0; i < 2; ++i)
#pragma unroll
        for (int j = 0; j < 8; ++j)
#pragma unroll
            for (int k = 0; k < 4; ++k) C[i][j][k] = 0.f;

    proj_issue(sb, 0, 0, tid, m0, n0, Xh, Xl, Wh, Wl);
    proj_issue(sb, 1, 1, tid, m0, n0, Xh, Xl, Wh, Wl);

    for (int kt = 0; kt < 32; ++kt) {
        if (kt < 31) CP_WAIT1(); else CP_WAIT0();
        __syncthreads();
        if (kt + 2 < 32)
            proj_issue(sb, (kt + 2) % 3, kt + 2, tid, m0, n0, Xh, Xl, Wh, Wl);

        const uint32_t base = sb + (uint32_t)(kt % 3) * 32768u;
#pragma unroll
        for (int ks = 0; ks < 2; ++ks) {
            const uint32_t csw = (uint32_t)(((2 * ks + flc) ^ ((flr >> 1) & 3)) << 4);
            uint32_t a_h[2][4], a_l[2][4];
#pragma unroll
            for (int mt = 0; mt < 2; ++mt) {
                uint32_t off = (uint32_t)((32 * wm + 16 * mt + flr) * 64) + csw;
                ldsm4(base + off, a_h[mt]);
                ldsm4(base + 8192u + off, a_l[mt]);
            }
#pragma unroll
            for (int ntp = 0; ntp < 4; ++ntp) {
                uint32_t boff = (uint32_t)((64 * wn + 16 * ntp + flr) * 64) + csw;
                uint32_t bh4[4], bl4[4];
                ldsm4(base + 16384u + boff, bh4);
                ldsm4(base + 24576u + boff, bl4);
#pragma unroll
                for (int mt = 0; mt < 2; ++mt) {
                    mma16816(C[mt][2 * ntp],     a_h[mt], bh4[0], bh4[2]);
                    mma16816(C[mt][2 * ntp],     a_h[mt], bl4[0], bl4[2]);
                    mma16816(C[mt][2 * ntp],     a_l[mt], bh4[0], bh4[2]);
                    mma16816(C[mt][2 * ntp + 1], a_h[mt], bh4[1], bh4[3]);
                    mma16816(C[mt][2 * ntp + 1], a_h[mt], bl4[1], bl4[3]);
                    mma16816(C[mt][2 * ntp + 1], a_l[mt], bh4[1], bh4[3]);
                }
            }
        }
    }

    // epilogue: bias + scale, split to hi/lo, head-split stores
#pragma unroll
    for (int nt = 0; nt < 8; ++nt) {
        int n = n0 + 64 * wn + 8 * nt + 2 * (lane & 3);
        int h = n >> 6, d = n & 63;
        float2 bv = *(const float2*)(bias + n);
#pragma unroll
        for (int mt = 0; mt < 2; ++mt) {
            int mbase = m0 + 32 * wm + 16 * mt + (lane >> 2);
#pragma unroll
            for (int half = 0; half < 2; ++half) {
                int m = mbase + 8 * half;
                int b = m >> 11, s = m & (S_ - 1);
                float vx = (C[mt][nt][2 * half + 0] + bv.x) * scale;
                float vy = (C[mt][nt][2 * half + 1] + bv.y) * scale;
                uint32_t hw, lw;
                split_pair(vx, vy, hw, lw);
                size_t off = ((size_t)(b * H_ + h) * S_ + s) * DH + d;
                *(uint32_t*)(oh + off) = hw;
                *(uint32_t*)(ol + off) = lw;
            }
        }
    }
}

// ---------------------------------------------------------------------------
// Flash attention: pre-split bf16 Q/K/V planes, 3-stage cp.async K/V pipeline.
// Q staging OVERLAYS stage 2 (dead after fragment extraction) -> 96KB smem
// -> 2 CTAs/SM (4 warps/SMSP). CTA: 128 q-rows, 8 warps, K-tile 64.
// smem: KV stages 0..2 @ st*32768 (Kh|Kl|Vh|Vl, 8KB each, swizzled);
//       Q staged at stage2: Qh @65536, Ql @81920. Total 98304.
// ---------------------------------------------------------------------------
#define ATTN_SMEM 98304u

__device__ __forceinline__ void attn_issue_kv(uint32_t sb, int st, int kt,
                                              int tid, size_t bhS) {
#pragma unroll
    for (int j = 0; j < 8; ++j) {
        int cid = tid + 256 * j;
        int sub = cid >> 9, w = cid & 511, row = w >> 3, c = w & 7;
        const unsigned short* plane = (sub == 0) ? g_kh : (sub == 1) ? g_kl
                                     : (sub == 2) ? g_vh : g_vl;
        const void* src = plane + (bhS + (size_t)(kt * 64 + row)) * DH + c * 8;
        uint32_t dst = sb + (uint32_t)st * 32768u + (uint32_t)sub * 8192u
                     + (uint32_t)row * 128u + (uint32_t)((c ^ (row & 7)) << 4);
        CP16(dst, src);
    }
    CP_COMMIT();
}

__global__ __launch_bounds__(256, 2) void attn_mma_kernel(
    const void* __restrict__ mask, float* __restrict__ out)
{
    extern __shared__ char as_[];
    const uint32_t sb = smem_u32(as_);

    const int tid = threadIdx.x, lane = tid & 31, wid = tid >> 5;
    const int bz = blockIdx.z, h = blockIdx.y;
    const int q0 = blockIdx.x * 128;
    const size_t bhS = (size_t)(bz * H_ + h) * S_;

    const int flr = lane & 15, flc = lane >> 4;
    const int r_in = lane >> 2;
    const int c_in = 2 * (lane & 3);

    // prologue: Q planes into the stage-2 region, first two K/V tiles
    {
#pragma unroll
        for (int j = 0; j < 8; ++j) {
            int cid = tid + 256 * j;
            int sub = cid >> 10, w = cid & 1023, row = w >> 3, c = w & 7;
            const unsigned short* plane = sub ? g_ql : g_qh;
            const void* src = plane + (bhS + (size_t)(q0 + row)) * DH + c * 8;
            uint32_t dst = sb + 65536u + (uint32_t)sub * 16384u
                         + (uint32_t)row * 128u + (uint32_t)((c ^ (row & 7)) << 4);
            CP16(dst, src);
        }
    }
    attn_issue_kv(sb, 0, 0, tid, bhS);   // group 0 (Q + tile0)
    attn_issue_kv(sb, 1, 1, tid, bhS);   // group 1
    CP_WAIT1();                          // Q + tile0 resident
    __syncthreads();

    // Q fragments (held in registers for whole kernel)
    uint32_t qh[4][4], ql[4][4];
#pragma unroll
    for (int ks = 0; ks < 4; ++ks) {
        uint32_t off = 65536u + (uint32_t)((16 * wid + flr) * 128)
                     + (uint32_t)(((2 * ks + flc) ^ (flr & 7)) << 4);
        ldsm4(sb + off, qh[ks]);
        ldsm4(sb + off + 16384u, ql[ks]);
    }
    __syncthreads();   // all warps done reading Q before stage2 is reused

    float oC[8][4];
#pragma unroll
    for (int j = 0; j < 8; ++j)
#pragma unroll
        for (int k = 0; k < 4; ++k) oC[j][k] = 0.f;
    float mi0 = NEGINF, mi1 = NEGINF, li0 = 0.f, li1 = 0.f;

    const int mode = g_mask_mode;
    const int rA = q0 + 16 * wid + r_in;
    const size_t mrowA = ((size_t)bz * S_ + rA) * S_;
    const size_t mrowB = mrowA + 8 * (size_t)S_;

    for (int kt = 0; kt < 32; ++kt) {
        if (kt) {
            if (kt < 31) CP_WAIT1(); else CP_WAIT0();
            __syncthreads();
        }
        if (kt + 2 < 32) attn_issue_kv(sb, (kt + 2) % 3, kt + 2, tid, bhS);

        const uint32_t base = sb + (uint32_t)(kt % 3) * 32768u;

        // -- mask loads (direct to fragments) --
        int2  mi2A[8], mi2B[8];
        unsigned short mu16A[8], mu16B[8];
        float2 mf2A[8], mf2B[8];
        if (mode == 0) {
            const int* mp = (const int*)mask;
#pragma unroll
            for (int nt = 0; nt < 8; ++nt) {
                int col = kt * 64 + 8 * nt + c_in;
                mi2A[nt] = *(const int2*)(mp + mrowA + col);
                mi2B[nt] = *(const int2*)(mp + mrowB + col);
            }
        } else if (mode == 1) {
            const unsigned char* mp = (const unsigned char*)mask;
#pragma unroll
            for (int nt = 0; nt < 8; ++nt) {
                int col = kt * 64 + 8 * nt + c_in;
                mu16A[nt] = *(const unsigned short*)(mp + mrowA + col);
                mu16B[nt] = *(const unsigned short*)(mp + mrowB + col);
            }
        } else {
            const float* mp = (const float*)mask;
#pragma unroll
            for (int nt = 0; nt < 8; ++nt) {
                int col = kt * 64 + 8 * nt + c_in;
                mf2A[nt] = *(const float2*)(mp + mrowA + col);
                mf2B[nt] = *(const float2*)(mp + mrowB + col);
            }
        }

        // -- S = Q K^T --
        float sC[8][4];
#pragma unroll
        for (int j = 0; j < 8; ++j)
#pragma unroll
            for (int k = 0; k < 4; ++k) sC[j][k] = 0.f;

#pragma unroll
        for (int ks = 0; ks < 4; ++ks) {
#pragma unroll
            for (int ntp = 0; ntp < 4; ++ntp) {
                uint32_t koff = (uint32_t)((16 * ntp + flr) * 128)
                              + (uint32_t)(((2 * ks + flc) ^ (flr & 7)) << 4);
                uint32_t bh4[4], bl4[4];
                ldsm4(base + koff, bh4);
                ldsm4(base + 8192u + koff, bl4);
                mma16816(sC[2 * ntp],     qh[ks], bh4[0], bh4[2]);
                mma16816(sC[2 * ntp],     qh[ks], bl4[0], bl4[2]);
                mma16816(sC[2 * ntp],     ql[ks], bh4[0], bh4[2]);
                mma16816(sC[2 * ntp + 1], qh[ks], bh4[1], bh4[3]);
                mma16816(sC[2 * ntp + 1], qh[ks], bl4[1], bl4[3]);
                mma16816(sC[2 * ntp + 1], ql[ks], bh4[1], bh4[3]);
            }
        }

        // -- apply mask --
        if (mode == 0) {
#pragma unroll
            for (int nt = 0; nt < 8; ++nt) {
                if (mi2A[nt].x) sC[nt][0] = NEGINF;
                if (mi2A[nt].y) sC[nt][1] = NEGINF;
                if (mi2B[nt].x) sC[nt][2] = NEGINF;
                if (mi2B[nt].y) sC[nt][3] = NEGINF;
            }
        } else if (mode == 1) {
#pragma unroll
            for (int nt = 0; nt < 8; ++nt) {
                if (mu16A[nt] & 0x00FF) sC[nt][0] = NEGINF;
                if (mu16A[nt] & 0xFF00) sC[nt][1] = NEGINF;
                if (mu16B[nt] & 0x00FF) sC[nt][2] = NEGINF;
                if (mu16B[nt] & 0xFF00) sC[nt][3] = NEGINF;
            }
        } else {
#pragma unroll
            for (int nt = 0; nt < 8; ++nt) {
                if (mf2A[nt].x != 0.f) sC[nt][0] = NEGINF;
                if (mf2A[nt].y != 0.f) sC[nt][1] = NEGINF;
                if (mf2B[nt].x != 0.f) sC[nt][2] = NEGINF;
                if (mf2B[nt].y != 0.f) sC[nt][3] = NEGINF;
            }
        }

        // -- online softmax (log2 domain) --
        float mx0 = NEGINF, mx1 = NEGINF;
#pragma unroll
        for (int nt = 0; nt < 8; ++nt) {
            mx0 = fmaxf(mx0, fmaxf(sC[nt][0], sC[nt][1]));
            mx1 = fmaxf(mx1, fmaxf(sC[nt][2], sC[nt][3]));
        }
        mx0 = fmaxf(mx0, __shfl_xor_sync(0xffffffffu, mx0, 1));
        mx0 = fmaxf(mx0, __shfl_xor_sync(0xffffffffu, mx0, 2));
        mx1 = fmaxf(mx1, __shfl_xor_sync(0xffffffffu, mx1, 1));
        mx1 = fmaxf(mx1, __shfl_xor_sync(0xffffffffu, mx1, 2));

        float mn0 = fmaxf(mi0, mx0), mn1 = fmaxf(mi1, mx1);
        float f0 = ex2f(mi0 - mn0), f1 = ex2f(mi1 - mn1);
        float sum0 = 0.f, sum1 = 0.f;
#pragma unroll
        for (int nt = 0; nt < 8; ++nt) {
            sC[nt][0] = ex2f(sC[nt][0] - mn0);
            sC[nt][1] = ex2f(sC[nt][1] - mn0);
            sC[nt][2] = ex2f(sC[nt][2] - mn1);
            sC[nt][3] = ex2f(sC[nt][3] - mn1);
            sum0 += sC[nt][0] + sC[nt][1];
            sum1 += sC[nt][2] + sC[nt][3];
        }
        sum0 += __shfl_xor_sync(0xffffffffu, sum0, 1);
        sum0 += __shfl_xor_sync(0xffffffffu, sum0, 2);
        sum1 += __shfl_xor_sync(0xffffffffu, sum1, 1);
        sum1 += __shfl_xor_sync(0xffffffffu, sum1, 2);
        li0 = li0 * f0 + sum0;
        li1 = li1 * f1 + sum1;
        mi0 = mn0; mi1 = mn1;
#pragma unroll
        for (int nt = 0; nt < 8; ++nt) {
            oC[nt][0] *= f0; oC[nt][1] *= f0;
            oC[nt][2] *= f1; oC[nt][3] *= f1;
        }

        // -- O += P V --
#pragma unroll
        for (int kp = 0; kp < 4; ++kp) {
            uint32_t pa_h[4], pa_l[4];
            split_pair(sC[2 * kp][0],     sC[2 * kp][1],     pa_h[0], pa_l[0]);
            split_pair(sC[2 * kp][2],     sC[2 * kp][3],     pa_h[1], pa_l[1]);
            split_pair(sC[2 * kp + 1][0], sC[2 * kp + 1][1], pa_h[2], pa_l[2]);
            split_pair(sC[2 * kp + 1][2], sC[2 * kp + 1][3], pa_h[3], pa_l[3]);

            const int trow = kp * 16 + ((lane >> 3) & 1) * 8 + (lane & 7);
            const int cb = lane >> 4;
#pragma unroll
            for (int ntp = 0; ntp < 4; ++ntp) {
                uint32_t voff = (uint32_t)(trow * 128)
                              + (uint32_t)(((2 * ntp + cb) ^ (trow & 7)) << 4);
                uint32_t vh4[4], vl4[4];
                ldsm4t(base + 16384u + voff, vh4);
                ldsm4t(base + 24576u + voff, vl4);
                mma16816(oC[2 * ntp],     pa_h, vh4[0], vh4[1]);
                mma16816(oC[2 * ntp],     pa_h, vl4[0], vl4[1]);
                mma16816(oC[2 * ntp],     pa_l, vh4[0], vh4[1]);
                mma16816(oC[2 * ntp + 1], pa_h, vh4[2], vh4[3]);
                mma16816(oC[2 * ntp + 1], pa_h, vl4[2], vl4[3]);
                mma16816(oC[2 * ntp + 1], pa_l, vh4[2], vh4[3]);
            }
        }
    }

    // ---- epilogue ----
    float inv0 = (li0 > 0.f) ? 1.0f / li0 : 0.f;
    float inv1 = (li1 > 0.f) ? 1.0f / li1 : 0.f;
    const int qr = q0 + 16 * wid + r_in;
    const int d0 = h * DH + c_in;
#pragma unroll
    for (int nt = 0; nt < 8; ++nt) {
        float2 v0, v1;
        v0.x = oC[nt][0] * inv0; v0.y = oC[nt][1] * inv0;
        v1.x = oC[nt][2] * inv1; v1.y = oC[nt][3] * inv1;
        *(float2*)(out + (size_t)(bz * S_ + qr) * DM + d0 + 8 * nt) = v0;
        *(float2*)(out + (size_t)(bz * S_ + qr + 8) * DM + d0 + 8 * nt) = v1;
    }
}

// ---------------------------------------------------------------------------
extern "C" void kernel_launch(void* const* d_in, const int* in_sizes, int n_in,
                              void* d_out, int out_size) {
    const void* mask = d_in[3];
    float* out = (float*)d_out;

    static int attr_done = 0;
    if (!attr_done) {
        cudaFuncSetAttribute(proj_mma_kernel,
                             cudaFuncAttributeMaxDynamicSharedMemorySize, PROJ_SMEM);
        cudaFuncSetAttribute(attn_mma_kernel,
                             cudaFuncAttributeMaxDynamicSharedMemorySize, ATTN_SMEM);
        attr_done = 1;
    }

    ConvArgs ca;
    ca.src[0] = (const float*)d_in[0];   // query
    ca.src[1] = (const float*)d_in[1];   // key
    ca.src[2] = (const float*)d_in[2];   // value
    ca.src[3] = (const float*)d_in[4];   // Wq
    ca.src[4] = (const float*)d_in[6];   // Wk
    ca.src[5] = (const float*)d_in[8];   // Wv
    convert_kernel<<<dim3(1024, 1, 7), 256>>>(ca, (const unsigned int*)mask);

    ProjArgs pa;
    pa.bias[0] = (const float*)d_in[5];
    pa.bias[1] = (const float*)d_in[7];
    pa.bias[2] = (const float*)d_in[9];
    pa.scale[0] = QSCALE; pa.scale[1] = 1.0f; pa.scale[2] = 1.0f;
    proj_mma_kernel<<<dim3(8, 32, 3), 256, PROJ_SMEM>>>(pa);

    attn_mma_kernel<<<dim3(16, 16, 2), 256, ATTN_SMEM>>>(mask, out);
}

// round 7
// speedup vs baseline: 2.4875x; 1.0047x over previous
#include <cuda_runtime.h>
#include <cuda_bf16.h>
#include <cstdint>
#include <cstddef>

#define B_  2
#define S_  2048
#define DM  1024
#define H_  16
#define DH  64
#define M_  (B_*S_)   // 4096
#define NEGINF -1e30f
// Q projection scale: (1/sqrt(DH)) * log2(e) -> softmax via exp2
#define QSCALE (0.125f * 1.44269504088896f)

#define XSEG (M_*DM)      // 4194304
#define WSEG (DM*DM)      // 1048576
#define QKV  (B_*H_*S_*DH)

// split-bf16 planes (hi + lo), written once
__device__ unsigned short g_xh[3*XSEG], g_xl[3*XSEG];
__device__ unsigned short g_wh[3*WSEG], g_wl[3*WSEG];
__device__ unsigned short g_qh[QKV], g_ql[QKV];
__device__ unsigned short g_kh[QKV], g_kl[QKV];
__device__ unsigned short g_vh[QKV], g_vl[QKV];
__device__ unsigned short g_mb[(size_t)B_*S_*S_];   // mask bias (0 or bf16(-1e30))
__device__ int g_mask_mode;

// ---------------------------------------------------------------------------
// Helpers
// ---------------------------------------------------------------------------
__device__ __forceinline__ uint32_t smem_u32(const void* p) {
    uint32_t a;
    asm("{ .reg .u64 t; cvta.to.shared.u64 t, %1; cvt.u32.u64 %0, t; }"
        : "=r"(a) : "l"(p));
    return a;
}
__device__ __forceinline__ void ldsm4(uint32_t addr, uint32_t* r) {
    asm volatile("ldmatrix.sync.aligned.m8n8.x4.shared.b16 {%0,%1,%2,%3}, [%4];"
        : "=r"(r[0]), "=r"(r[1]), "=r"(r[2]), "=r"(r[3]) : "r"(addr));
}
__device__ __forceinline__ void ldsm4t(uint32_t addr, uint32_t* r) {
    asm volatile("ldmatrix.sync.aligned.m8n8.x4.trans.shared.b16 {%0,%1,%2,%3}, [%4];"
        : "=r"(r[0]), "=r"(r[1]), "=r"(r[2]), "=r"(r[3]) : "r"(addr));
}
__device__ __forceinline__ void mma16816(float* c, const uint32_t* a,
                                         uint32_t b0, uint32_t b1) {
    asm volatile(
        "mma.sync.aligned.m16n8k16.row.col.f32.bf16.bf16.f32 "
        "{%0,%1,%2,%3}, {%4,%5,%6,%7}, {%8,%9}, {%0,%1,%2,%3};"
        : "+f"(c[0]), "+f"(c[1]), "+f"(c[2]), "+f"(c[3])
        : "r"(a[0]), "r"(a[1]), "r"(a[2]), "r"(a[3]), "r"(b0), "r"(b1));
}
__device__ __forceinline__ uint32_t cvt2_bf16(float lo_elem, float hi_elem) {
    uint32_t r;
    asm("cvt.rn.bf16x2.f32 %0, %1, %2;" : "=r"(r) : "f"(hi_elem), "f"(lo_elem));
    return r;
}
__device__ __forceinline__ float bf16lo_f(uint32_t v) { return __uint_as_float(v << 16); }
__device__ __forceinline__ float bf16hi_f(uint32_t v) { return __uint_as_float(v & 0xFFFF0000u); }
__device__ __forceinline__ void split_pair(float x, float y, uint32_t& h, uint32_t& l) {
    h = cvt2_bf16(x, y);
    float rx = x - bf16lo_f(h);
    float ry = y - bf16hi_f(h);
    l = cvt2_bf16(rx, ry);
}
__device__ __forceinline__ void split4(float4 v, uint2& hw, uint2& lw) {
    uint32_t h0, l0, h1, l1;
    split_pair(v.x, v.y, h0, l0);
    split_pair(v.z, v.w, h1, l1);
    hw.x = h0; hw.y = h1; lw.x = l0; lw.y = l1;
}
__device__ __forceinline__ float ex2f(float x) {
    float y;
    asm("ex2.approx.f32 %0, %1;" : "=f"(y) : "f"(x));
    return y;
}
#define CP16(dst, src) \
    asm volatile("cp.async.cg.shared.global [%0], [%1], 16;" :: "r"(dst), "l"(src))
#define CP_COMMIT() asm volatile("cp.async.commit_group;")
#define CP_WAIT1()  asm volatile("cp.async.wait_group 1;")
#define CP_WAIT0()  asm volatile("cp.async.wait_group 0;")

// ---------------------------------------------------------------------------
// Convert: fp32 -> split bf16 planes; z==6 slice does mask dtype detection.
// ---------------------------------------------------------------------------
struct ConvArgs { const float* src[6]; };

__global__ __launch_bounds__(256) void convert_kernel(ConvArgs a,
                                                      const unsigned int* mask) {
    const int z = blockIdx.z;
    const int tid = threadIdx.x;
    if (z == 6) {
        if (blockIdx.x != 0) return;
        int ok_i32 = 1, ok_u8 = 1;
        for (int i = tid; i < 4096; i += 256) {
            unsigned w = mask[i];
            ok_i32 &= (w <= 1u);
            ok_u8  &= ((w & 0xFEFEFEFEu) == 0u);
        }
        ok_i32 = __syncthreads_and(ok_i32);
        ok_u8  = __syncthreads_and(ok_u8);
        if (tid == 0) g_mask_mode = ok_i32 ? 0 : (ok_u8 ? 1 : 2);
        return;
    }
    const float4* src = (const float4*)a.src[z];
    int nf8;
    unsigned short *dh, *dl;
    if (z < 3) { nf8 = XSEG / 8; dh = g_xh + (size_t)z * XSEG; dl = g_xl + (size_t)z * XSEG; }
    else       { nf8 = WSEG / 8; dh = g_wh + (size_t)(z - 3) * WSEG; dl = g_wl + (size_t)(z - 3) * WSEG; }
    for (int i = blockIdx.x * 256 + tid; i < nf8; i += 1024 * 256) {
        float4 v0 = src[2 * i];
        float4 v1 = src[2 * i + 1];
        uint2 h0, l0, h1, l1;
        split4(v0, h0, l0);
        split4(v1, h1, l1);
        uint4 hv, lv;
        hv.x = h0.x; hv.y = h0.y; hv.z = h1.x; hv.w = h1.y;
        lv.x = l0.x; lv.y = l0.y; lv.z = l1.x; lv.w = l1.y;
        ((uint4*)dh)[i] = hv;
        ((uint4*)dl)[i] = lv;
    }
}

// ---------------------------------------------------------------------------
// Mask -> bf16 additive bias plane (0 or bf16(-1e30)), packed pairs.
// ---------------------------------------------------------------------------
__global__ __launch_bounds__(256) void mask_conv_kernel(const void* mask) {
    const int mode = g_mask_mode;
    __nv_bfloat16 nb = __float2bfloat16(NEGINF);
    const uint32_t neg = (uint32_t)*(unsigned short*)&nb;
    const int n8 = (int)(((size_t)B_ * S_ * S_) / 8);
    for (int i = blockIdx.x * 256 + threadIdx.x; i < n8; i += gridDim.x * 256) {
        unsigned m[8];
        if (mode == 0) {
            int4 a = ((const int4*)mask)[2 * i];
            int4 b = ((const int4*)mask)[2 * i + 1];
            m[0] = a.x != 0; m[1] = a.y != 0; m[2] = a.z != 0; m[3] = a.w != 0;
            m[4] = b.x != 0; m[5] = b.y != 0; m[6] = b.z != 0; m[7] = b.w != 0;
        } else if (mode == 1) {
            uint2 a = ((const uint2*)mask)[i];
#pragma unroll
            for (int j = 0; j < 4; ++j) m[j] = (a.x >> (8 * j)) & 255u;
#pragma unroll
            for (int j = 0; j < 4; ++j) m[4 + j] = (a.y >> (8 * j)) & 255u;
        } else {
            float4 a = ((const float4*)mask)[2 * i];
            float4 b = ((const float4*)mask)[2 * i + 1];
            m[0] = a.x != 0.f; m[1] = a.y != 0.f; m[2] = a.z != 0.f; m[3] = a.w != 0.f;
            m[4] = b.x != 0.f; m[5] = b.y != 0.f; m[6] = b.z != 0.f; m[7] = b.w != 0.f;
        }
        uint4 o;
        o.x = (m[0] ? neg : 0u) | ((m[1] ? neg : 0u) << 16);
        o.y = (m[2] ? neg : 0u) | ((m[3] ? neg : 0u) << 16);
        o.z = (m[4] ? neg : 0u) | ((m[5] ? neg : 0u) << 16);
        o.w = (m[6] ? neg : 0u) | ((m[7] ? neg : 0u) << 16);
        ((uint4*)g_mb)[i] = o;
    }
}

// ---------------------------------------------------------------------------
// Projection GEMM: BM=128, BN=256, BK=32, 8 warps, 64x64 warp tiles,
// 3-stage cp.async (48KB/stage, 144KB). mma.sync bf16 3-term.
// Stage: Ah@0(8K) | Al@8K | Bh@16K(16K) | Bl@32K. Rows 64B, XOR-swizzled.
// ---------------------------------------------------------------------------
#define PSTG 49152u
#define PROJ_SMEM (3u * PSTG)   // 147456

struct ProjArgs { const float* bias[3]; float scale[3]; };

__device__ __forceinline__ void proj_issue(
    uint32_t sb, int st, int kt, int tid, int m0, int n0,
    const unsigned short* Xh, const unsigned short* Xl,
    const unsigned short* Wh, const unsigned short* Wl)
{
    const uint32_t stage = sb + (uint32_t)st * PSTG;
#pragma unroll
    for (int j = 0; j < 2; ++j) {      // Ah, Al : 512 lines each
        int line = tid + 256 * j;
        int row = line >> 2, c = line & 3;
        uint32_t doff = (uint32_t)row * 64u + (uint32_t)((c ^ ((row >> 1) & 3)) << 4);
        CP16(stage + doff,           Xh + (size_t)(m0 + row) * DM + kt * 32 + c * 8);
        CP16(stage + 8192u + doff,   Xl + (size_t)(m0 + row) * DM + kt * 32 + c * 8);
    }
#pragma unroll
    for (int j = 0; j < 4; ++j) {      // Bh, Bl : 1024 lines each
        int line = tid + 256 * j;
        int row = line >> 2, c = line & 3;
        uint32_t doff = (uint32_t)row * 64u + (uint32_t)((c ^ ((row >> 1) & 3)) << 4);
        CP16(stage + 16384u + doff,  Wh + (size_t)(n0 + row) * DM + kt * 32 + c * 8);
        CP16(stage + 32768u + doff,  Wl + (size_t)(n0 + row) * DM + kt * 32 + c * 8);
    }
    CP_COMMIT();
}

__global__ __launch_bounds__(256) void proj_mma_kernel(ProjArgs args) {
    extern __shared__ char ps[];
    const uint32_t sb = smem_u32(ps);
    const int z = blockIdx.z;
    const unsigned short* __restrict__ Xh = g_xh + (size_t)z * XSEG;
    const unsigned short* __restrict__ Xl = g_xl + (size_t)z * XSEG;
    const unsigned short* __restrict__ Wh = g_wh + (size_t)z * WSEG;
    const unsigned short* __restrict__ Wl = g_wl + (size_t)z * WSEG;
    const float* __restrict__ bias = args.bias[z];
    unsigned short* __restrict__ oh = (z == 0) ? g_qh : (z == 1) ? g_kh : g_vh;
    unsigned short* __restrict__ ol = (z == 0) ? g_ql : (z == 1) ? g_kl : g_vl;
    const float scale = args.scale[z];

    const int tid = threadIdx.x, lane = tid & 31, wid = tid >> 5;
    const int wm = wid & 1, wn = wid >> 1;       // warp tile 64m x 64n
    const int m0 = blockIdx.y * 128, n0 = blockIdx.x * 256;
    const int flr = lane & 15, flc = lane >> 4;

    float C[4][8][4];
#pragma unroll
    for (int i = 0; i < 4; ++i)
#pragma unroll
        for (int j = 0; j < 8; ++j)
#pragma unroll
            for (int k = 0; k < 4; ++k) C[i][j][k] = 0.f;

    proj_issue(sb, 0, 0, tid, m0, n0, Xh, Xl, Wh, Wl);
    proj_issue(sb, 1, 1, tid, m0, n0, Xh, Xl, Wh, Wl);

    for (int kt = 0; kt < 32; ++kt) {
        if (kt < 31) CP_WAIT1(); else CP_WAIT0();
        __syncthreads();
        if (kt + 2 < 32)
            proj_issue(sb, (kt + 2) % 3, kt + 2, tid, m0, n0, Xh, Xl, Wh, Wl);

        const uint32_t base = sb + (uint32_t)(kt % 3) * PSTG;
#pragma unroll
        for (int ks = 0; ks < 2; ++ks) {
            const uint32_t csw = (uint32_t)(((2 * ks + flc) ^ ((flr >> 1) & 3)) << 4);
            uint32_t a_h[4][4], a_l[4][4];
#pragma unroll
            for (int mt = 0; mt < 4; ++mt) {
                uint32_t off = (uint32_t)((64 * wm + 16 * mt + flr) * 64) + csw;
                ldsm4(base + off, a_h[mt]);
                ldsm4(base + 8192u + off, a_l[mt]);
            }
#pragma unroll
            for (int ntp = 0; ntp < 4; ++ntp) {
                uint32_t boff = (uint32_t)((64 * wn + 16 * ntp + flr) * 64) + csw;
                uint32_t bh4[4], bl4[4];
                ldsm4(base + 16384u + boff, bh4);
                ldsm4(base + 32768u + boff, bl4);
#pragma unroll
                for (int mt = 0; mt < 4; ++mt) {
                    mma16816(C[mt][2 * ntp],     a_h[mt], bh4[0], bh4[2]);
                    mma16816(C[mt][2 * ntp],     a_h[mt], bl4[0], bl4[2]);
                    mma16816(C[mt][2 * ntp],     a_l[mt], bh4[0], bh4[2]);
                    mma16816(C[mt][2 * ntp + 1], a_h[mt], bh4[1], bh4[3]);
                    mma16816(C[mt][2 * ntp + 1], a_h[mt], bl4[1], bl4[3]);
                    mma16816(C[mt][2 * ntp + 1], a_l[mt], bh4[1], bh4[3]);
                }
            }
        }
    }

    // epilogue: bias + scale, split hi/lo, head-split stores
#pragma unroll
    for (int nt = 0; nt < 8; ++nt) {
        int n = n0 + 64 * wn + 8 * nt + 2 * (lane & 3);
        int h = n >> 6, d = n & 63;
        float2 bv = *(const float2*)(bias + n);
#pragma unroll
        for (int mt = 0; mt < 4; ++mt) {
            int mbase = m0 + 64 * wm + 16 * mt + (lane >> 2);
#pragma unroll
            for (int half = 0; half < 2; ++half) {
                int m = mbase + 8 * half;
                int b = m >> 11, s = m & (S_ - 1);
                float vx = (C[mt][nt][2 * half + 0] + bv.x) * scale;
                float vy = (C[mt][nt][2 * half + 1] + bv.y) * scale;
                uint32_t hw, lw;
                split_pair(vx, vy, hw, lw);
                size_t off = ((size_t)(b * H_ + h) * S_ + s) * DH + d;
                *(uint32_t*)(oh + off) = hw;
                *(uint32_t*)(ol + off) = lw;
            }
        }
    }
}

// ---------------------------------------------------------------------------
// Flash attention: 8 warps x 32 q-rows (CTA = 256 q-rows), K-tile 64.
// Q fragments direct LDG. 3-stage cp.async K/V (96KB). K/V fragments reused
// across 2 A-tiles. Mask bias initializes S accumulators.
// Stage: Kh@0 | Kl@8K | Vh@16K | Vl@24K, 128B rows, swizzled.
// ---------------------------------------------------------------------------
#define ASTG 32768u
#define ATTN_SMEM (3u * ASTG)   // 98304

__device__ __forceinline__ void attn_issue_kv(uint32_t sb, int st, int kt,
                                              int tid, size_t bhS) {
#pragma unroll
    for (int j = 0; j < 8; ++j) {
        int cid = tid + 256 * j;
        int sub = cid >> 9, w = cid & 511, row = w >> 3, c = w & 7;
        const unsigned short* plane = (sub == 0) ? g_kh : (sub == 1) ? g_kl
                                     : (sub == 2) ? g_vh : g_vl;
        const void* src = plane + (bhS + (size_t)(kt * 64 + row)) * DH + c * 8;
        uint32_t dst = sb + (uint32_t)st * ASTG + (uint32_t)sub * 8192u
                     + (uint32_t)row * 128u + (uint32_t)((c ^ (row & 7)) << 4);
        CP16(dst, src);
    }
    CP_COMMIT();
}

__global__ __launch_bounds__(256) void attn_mma_kernel(float* __restrict__ out)
{
    extern __shared__ char as_[];
    const uint32_t sb = smem_u32(as_);

    const int tid = threadIdx.x, lane = tid & 31, wid = tid >> 5;
    const int bz = blockIdx.z, h = blockIdx.y;
    const int q0 = blockIdx.x * 256;
    const size_t bhS = (size_t)(bz * H_ + h) * S_;

    const int flr = lane & 15, flc = lane >> 4;
    const int r_in = lane >> 2;
    const int c_in = 2 * (lane & 3);

    attn_issue_kv(sb, 0, 0, tid, bhS);
    attn_issue_kv(sb, 1, 1, tid, bhS);

    // Q fragments: direct 4B gmem loads (one-time)
    uint32_t qh[2][4][4], ql[2][4][4];
#pragma unroll
    for (int t = 0; t < 2; ++t)
#pragma unroll
        for (int ks = 0; ks < 4; ++ks)
#pragma unroll
            for (int j = 0; j < 4; ++j) {
                size_t off = (bhS + (size_t)(q0 + 32 * wid + 16 * t + r_in + 8 * (j & 1))) * DH
                           + 16 * ks + c_in + 8 * (j >> 1);
                qh[t][ks][j] = *(const uint32_t*)(g_qh + off);
                ql[t][ks][j] = *(const uint32_t*)(g_ql + off);
            }

    float oC[2][8][4];
#pragma unroll
    for (int t = 0; t < 2; ++t)
#pragma unroll
        for (int j = 0; j < 8; ++j)
#pragma unroll
            for (int k = 0; k < 4; ++k) oC[t][j][k] = 0.f;
    float mi[2][2], li[2][2];
#pragma unroll
    for (int t = 0; t < 2; ++t) {
        mi[t][0] = NEGINF; mi[t][1] = NEGINF;
        li[t][0] = 0.f;    li[t][1] = 0.f;
    }

    const int rowA0 = q0 + 32 * wid + r_in;
    const unsigned short* mb = g_mb + (size_t)bz * S_ * S_;

    for (int kt = 0; kt < 32; ++kt) {
        if (kt < 31) CP_WAIT1(); else CP_WAIT0();
        __syncthreads();
        if (kt + 2 < 32) attn_issue_kv(sb, (kt + 2) % 3, kt + 2, tid, bhS);

        const uint32_t base = sb + (uint32_t)(kt % 3) * ASTG;

        // S accumulators initialized with mask bias (MMA accumulates on top)
        float sC[2][8][4];
#pragma unroll
        for (int t = 0; t < 2; ++t)
#pragma unroll
            for (int nt = 0; nt < 8; ++nt) {
                size_t rA = (size_t)(rowA0 + 16 * t) * S_ + kt * 64 + 8 * nt + c_in;
                uint32_t bA = *(const uint32_t*)(mb + rA);
                uint32_t bB = *(const uint32_t*)(mb + rA + 8 * (size_t)S_);
                sC[t][nt][0] = bf16lo_f(bA); sC[t][nt][1] = bf16hi_f(bA);
                sC[t][nt][2] = bf16lo_f(bB); sC[t][nt][3] = bf16hi_f(bB);
            }

        // -- S += Q K^T (K fragments reused across both A-tiles) --
#pragma unroll
        for (int ks = 0; ks < 4; ++ks) {
#pragma unroll
            for (int ntp = 0; ntp < 4; ++ntp) {
                uint32_t koff = (uint32_t)((16 * ntp + flr) * 128)
                              + (uint32_t)(((2 * ks + flc) ^ (flr & 7)) << 4);
                uint32_t bh4[4], bl4[4];
                ldsm4(base + koff, bh4);
                ldsm4(base + 8192u + koff, bl4);
#pragma unroll
                for (int t = 0; t < 2; ++t) {
                    mma16816(sC[t][2 * ntp],     qh[t][ks], bh4[0], bh4[2]);
                    mma16816(sC[t][2 * ntp],     qh[t][ks], bl4[0], bl4[2]);
                    mma16816(sC[t][2 * ntp],     ql[t][ks], bh4[0], bh4[2]);
                    mma16816(sC[t][2 * ntp + 1], qh[t][ks], bh4[1], bh4[3]);
                    mma16816(sC[t][2 * ntp + 1], qh[t][ks], bl4[1], bl4[3]);
                    mma16816(sC[t][2 * ntp + 1], ql[t][ks], bh4[1], bh4[3]);
                }
            }
        }

        // -- online softmax per tile (log2 domain) --
#pragma unroll
        for (int t = 0; t < 2; ++t) {
            float mx0 = NEGINF, mx1 = NEGINF;
#pragma unroll
            for (int nt = 0; nt < 8; ++nt) {
                mx0 = fmaxf(mx0, fmaxf(sC[t][nt][0], sC[t][nt][1]));
                mx1 = fmaxf(mx1, fmaxf(sC[t][nt][2], sC[t][nt][3]));
            }
            mx0 = fmaxf(mx0, __shfl_xor_sync(0xffffffffu, mx0, 1));
            mx0 = fmaxf(mx0, __shfl_xor_sync(0xffffffffu, mx0, 2));
            mx1 = fmaxf(mx1, __shfl_xor_sync(0xffffffffu, mx1, 1));
            mx1 = fmaxf(mx1, __shfl_xor_sync(0xffffffffu, mx1, 2));

            float mn0 = fmaxf(mi[t][0], mx0), mn1 = fmaxf(mi[t][1], mx1);
            float f0 = ex2f(mi[t][0] - mn0), f1 = ex2f(mi[t][1] - mn1);
            float sum0 = 0.f, sum1 = 0.f;
#pragma unroll
            for (int nt = 0; nt < 8; ++nt) {
                sC[t][nt][0] = ex2f(sC[t][nt][0] - mn0);
                sC[t][nt][1] = ex2f(sC[t][nt][1] - mn0);
                sC[t][nt][2] = ex2f(sC[t][nt][2] - mn1);
                sC[t][nt][3] = ex2f(sC[t][nt][3] - mn1);
                sum0 += sC[t][nt][0] + sC[t][nt][1];
                sum1 += sC[t][nt][2] + sC[t][nt][3];
            }
            sum0 += __shfl_xor_sync(0xffffffffu, sum0, 1);
            sum0 += __shfl_xor_sync(0xffffffffu, sum0, 2);
            sum1 += __shfl_xor_sync(0xffffffffu, sum1, 1);
            sum1 += __shfl_xor_sync(0xffffffffu, sum1, 2);
            li[t][0] = li[t][0] * f0 + sum0;
            li[t][1] = li[t][1] * f1 + sum1;
            mi[t][0] = mn0; mi[t][1] = mn1;
#pragma unroll
            for (int nt = 0; nt < 8; ++nt) {
                oC[t][nt][0] *= f0; oC[t][nt][1] *= f0;
                oC[t][nt][2] *= f1; oC[t][nt][3] *= f1;
            }
        }

        // -- O += P V (V fragments reused across both A-tiles) --
#pragma unroll
        for (int kp = 0; kp < 4; ++kp) {
            uint32_t pah[2][4], pal[2][4];
#pragma unroll
            for (int t = 0; t < 2; ++t) {
                split_pair(sC[t][2 * kp][0],     sC[t][2 * kp][1],     pah[t][0], pal[t][0]);
                split_pair(sC[t][2 * kp][2],     sC[t][2 * kp][3],     pah[t][1], pal[t][1]);
                split_pair(sC[t][2 * kp + 1][0], sC[t][2 * kp + 1][1], pah[t][2], pal[t][2]);
                split_pair(sC[t][2 * kp + 1][2], sC[t][2 * kp + 1][3], pah[t][3], pal[t][3]);
            }
            const int trow = kp * 16 + ((lane >> 3) & 1) * 8 + (lane & 7);
            const int cb = lane >> 4;
#pragma unroll
            for (int ntp = 0; ntp < 4; ++ntp) {
                uint32_t voff = (uint32_t)(trow * 128)
                              + (uint32_t)(((2 * ntp + cb) ^ (trow & 7)) << 4);
                uint32_t vh4[4], vl4[4];
                ldsm4t(base + 16384u + voff, vh4);
                ldsm4t(base + 24576u + voff, vl4);
#pragma unroll
                for (int t = 0; t < 2; ++t) {
                    mma16816(oC[t][2 * ntp],     pah[t], vh4[0], vh4[1]);
                    mma16816(oC[t][2 * ntp],     pah[t], vl4[0], vl4[1]);
                    mma16816(oC[t][2 * ntp],     pal[t], vh4[0], vh4[1]);
                    mma16816(oC[t][2 * ntp + 1], pah[t], vh4[2], vh4[3]);
                    mma16816(oC[t][2 * ntp + 1], pah[t], vl4[2], vl4[3]);
                    mma16816(oC[t][2 * ntp + 1], pal[t], vh4[2], vh4[3]);
                }
            }
        }
    }

    // ---- epilogue ----
#pragma unroll
    for (int t = 0; t < 2; ++t) {
        float inv0 = (li[t][0] > 0.f) ? 1.0f / li[t][0] : 0.f;
        float inv1 = (li[t][1] > 0.f) ? 1.0f / li[t][1] : 0.f;
        const int qr = rowA0 + 16 * t;
        const int d0 = h * DH + c_in;
#pragma unroll
        for (int nt = 0; nt < 8; ++nt) {
            float2 v0, v1;
            v0.x = oC[t][nt][0] * inv0; v0.y = oC[t][nt][1] * inv0;
            v1.x = oC[t][nt][2] * inv1; v1.y = oC[t][nt][3] * inv1;
            *(float2*)(out + (size_t)(bz * S_ + qr) * DM + d0 + 8 * nt) = v0;
            *(float2*)(out + (size_t)(bz * S_ + qr + 8) * DM + d0 + 8 * nt) = v1;
        }
    }
}

// ---------------------------------------------------------------------------
extern "C" void kernel_launch(void* const* d_in, const int* in_sizes, int n_in,
                              void* d_out, int out_size) {
    const void* mask = d_in[3];
    float* out = (float*)d_out;

    static int attr_done = 0;
    if (!attr_done) {
        cudaFuncSetAttribute(proj_mma_kernel,
                             cudaFuncAttributeMaxDynamicSharedMemorySize, PROJ_SMEM);
        cudaFuncSetAttribute(attn_mma_kernel,
                             cudaFuncAttributeMaxDynamicSharedMemorySize, ATTN_SMEM);
        attr_done = 1;
    }

    ConvArgs ca;
    ca.src[0] = (const float*)d_in[0];   // query
    ca.src[1] = (const float*)d_in[1];   // key
    ca.src[2] = (const float*)d_in[2];   // value
    ca.src[3] = (const float*)d_in[4];   // Wq
    ca.src[4] = (const float*)d_in[6];   // Wk
    ca.src[5] = (const float*)d_in[8];   // Wv
    convert_kernel<<<dim3(1024, 1, 7), 256>>>(ca, (const unsigned int*)mask);

    mask_conv_kernel<<<2048, 256>>>(mask);

    ProjArgs pa;
    pa.bias[0] = (const float*)d_in[5];
    pa.bias[1] = (const float*)d_in[7];
    pa.bias[2] = (const float*)d_in[9];
    pa.scale[0] = QSCALE; pa.scale[1] = 1.0f; pa.scale[2] = 1.0f;
    proj_mma_kernel<<<dim3(4, 32, 3), 256, PROJ_SMEM>>>(pa);

    attn_mma_kernel<<<dim3(8, 16, 2), 256, ATTN_SMEM>>>(out);
}

// round 8
// speedup vs baseline: 2.6031x; 1.0465x over previous
#include <cuda_runtime.h>
#include <cuda_bf16.h>
#include <cstdint>
#include <cstddef>

#define B_  2
#define S_  2048
#define DM  1024
#define H_  16
#define DH  64
#define M_  (B_*S_)   // 4096
#define NEGINF -1e30f
#define QSCALE (0.125f * 1.44269504088896f)

#define XSEG (M_*DM)
#define WSEG (DM*DM)
#define QKV  (B_*H_*S_*DH)

__device__ unsigned short g_xh[3*XSEG], g_xl[3*XSEG];
__device__ unsigned short g_wh[3*WSEG], g_wl[3*WSEG];
__device__ unsigned short g_qh[QKV], g_ql[QKV];
__device__ unsigned short g_kh[QKV], g_kl[QKV];
__device__ unsigned short g_vh[QKV], g_vl[QKV];
__device__ unsigned short g_mb[(size_t)B_*S_*S_];   // mask bias (0 / bf16(-1e30))
__device__ int g_mask_mode;

// ---------------------------------------------------------------------------
__device__ __forceinline__ uint32_t smem_u32(const void* p) {
    uint32_t a;
    asm("{ .reg .u64 t; cvta.to.shared.u64 t, %1; cvt.u32.u64 %0, t; }"
        : "=r"(a) : "l"(p));
    return a;
}
__device__ __forceinline__ void ldsm4(uint32_t addr, uint32_t* r) {
    asm volatile("ldmatrix.sync.aligned.m8n8.x4.shared.b16 {%0,%1,%2,%3}, [%4];"
        : "=r"(r[0]), "=r"(r[1]), "=r"(r[2]), "=r"(r[3]) : "r"(addr));
}
__device__ __forceinline__ void ldsm4t(uint32_t addr, uint32_t* r) {
    asm volatile("ldmatrix.sync.aligned.m8n8.x4.trans.shared.b16 {%0,%1,%2,%3}, [%4];"
        : "=r"(r[0]), "=r"(r[1]), "=r"(r[2]), "=r"(r[3]) : "r"(addr));
}
__device__ __forceinline__ void mma16816(float* c, const uint32_t* a,
                                         uint32_t b0, uint32_t b1) {
    asm volatile(
        "mma.sync.aligned.m16n8k16.row.col.f32.bf16.bf16.f32 "
        "{%0,%1,%2,%3}, {%4,%5,%6,%7}, {%8,%9}, {%0,%1,%2,%3};"
        : "+f"(c[0]), "+f"(c[1]), "+f"(c[2]), "+f"(c[3])
        : "r"(a[0]), "r"(a[1]), "r"(a[2]), "r"(a[3]), "r"(b0), "r"(b1));
}
__device__ __forceinline__ uint32_t cvt2_bf16(float lo_elem, float hi_elem) {
    uint32_t r;
    asm("cvt.rn.bf16x2.f32 %0, %1, %2;" : "=r"(r) : "f"(hi_elem), "f"(lo_elem));
    return r;
}
__device__ __forceinline__ float bf16lo_f(uint32_t v) { return __uint_as_float(v << 16); }
__device__ __forceinline__ float bf16hi_f(uint32_t v) { return __uint_as_float(v & 0xFFFF0000u); }
__device__ __forceinline__ void split_pair(float x, float y, uint32_t& h, uint32_t& l) {
    h = cvt2_bf16(x, y);
    float rx = x - bf16lo_f(h);
    float ry = y - bf16hi_f(h);
    l = cvt2_bf16(rx, ry);
}
__device__ __forceinline__ void split4(float4 v, uint2& hw, uint2& lw) {
    uint32_t h0, l0, h1, l1;
    split_pair(v.x, v.y, h0, l0);
    split_pair(v.z, v.w, h1, l1);
    hw.x = h0; hw.y = h1; lw.x = l0; lw.y = l1;
}
__device__ __forceinline__ float ex2f(float x) {
    float y;
    asm("ex2.approx.f32 %0, %1;" : "=f"(y) : "f"(x));
    return y;
}
#define CP16(dst, src) \
    asm volatile("cp.async.cg.shared.global [%0], [%1], 16;" :: "r"(dst), "l"(src))
#define CP_COMMIT() asm volatile("cp.async.commit_group;")
#define CP_WAIT1()  asm volatile("cp.async.wait_group 1;")
#define CP_WAIT0()  asm volatile("cp.async.wait_group 0;")

// ---------------------------------------------------------------------------
// Convert fp32 -> split bf16 planes; z==6 detects mask dtype.
// ---------------------------------------------------------------------------
struct ConvArgs { const float* src[6]; };

__global__ __launch_bounds__(256) void convert_kernel(ConvArgs a,
                                                      const unsigned int* mask) {
    const int z = blockIdx.z;
    const int tid = threadIdx.x;
    if (z == 6) {
        if (blockIdx.x != 0) return;
        int ok_i32 = 1, ok_u8 = 1;
        for (int i = tid; i < 4096; i += 256) {
            unsigned w = mask[i];
            ok_i32 &= (w <= 1u);
            ok_u8  &= ((w & 0xFEFEFEFEu) == 0u);
        }
        ok_i32 = __syncthreads_and(ok_i32);
        ok_u8  = __syncthreads_and(ok_u8);
        if (tid == 0) g_mask_mode = ok_i32 ? 0 : (ok_u8 ? 1 : 2);
        return;
    }
    const float4* src = (const float4*)a.src[z];
    int nf8;
    unsigned short *dh, *dl;
    if (z < 3) { nf8 = XSEG / 8; dh = g_xh + (size_t)z * XSEG; dl = g_xl + (size_t)z * XSEG; }
    else       { nf8 = WSEG / 8; dh = g_wh + (size_t)(z - 3) * WSEG; dl = g_wl + (size_t)(z - 3) * WSEG; }
    for (int i = blockIdx.x * 256 + tid; i < nf8; i += 1024 * 256) {
        float4 v0 = src[2 * i];
        float4 v1 = src[2 * i + 1];
        uint2 h0, l0, h1, l1;
        split4(v0, h0, l0);
        split4(v1, h1, l1);
        uint4 hv, lv;
        hv.x = h0.x; hv.y = h0.y; hv.z = h1.x; hv.w = h1.y;
        lv.x = l0.x; lv.y = l0.y; lv.z = l1.x; lv.w = l1.y;
        ((uint4*)dh)[i] = hv;
        ((uint4*)dl)[i] = lv;
    }
}

// ---------------------------------------------------------------------------
// Mask -> bf16 additive bias plane.
// ---------------------------------------------------------------------------
__global__ __launch_bounds__(256) void mask_conv_kernel(const void* mask) {
    const int mode = g_mask_mode;
    __nv_bfloat16 nb = __float2bfloat16(NEGINF);
    const uint32_t neg = (uint32_t)*(unsigned short*)&nb;
    const int n8 = (int)(((size_t)B_ * S_ * S_) / 8);
    for (int i = blockIdx.x * 256 + threadIdx.x; i < n8; i += gridDim.x * 256) {
        unsigned m[8];
        if (mode == 0) {
            int4 a = ((const int4*)mask)[2 * i];
            int4 b = ((const int4*)mask)[2 * i + 1];
            m[0] = a.x != 0; m[1] = a.y != 0; m[2] = a.z != 0; m[3] = a.w != 0;
            m[4] = b.x != 0; m[5] = b.y != 0; m[6] = b.z != 0; m[7] = b.w != 0;
        } else if (mode == 1) {
            uint2 a = ((const uint2*)mask)[i];
#pragma unroll
            for (int j = 0; j < 4; ++j) m[j] = (a.x >> (8 * j)) & 255u;
#pragma unroll
            for (int j = 0; j < 4; ++j) m[4 + j] = (a.y >> (8 * j)) & 255u;
        } else {
            float4 a = ((const float4*)mask)[2 * i];
            float4 b = ((const float4*)mask)[2 * i + 1];
            m[0] = a.x != 0.f; m[1] = a.y != 0.f; m[2] = a.z != 0.f; m[3] = a.w != 0.f;
            m[4] = b.x != 0.f; m[5] = b.y != 0.f; m[6] = b.z != 0.f; m[7] = b.w != 0.f;
        }
        uint4 o;
        o.x = (m[0] ? neg : 0u) | ((m[1] ? neg : 0u) << 16);
        o.y = (m[2] ? neg : 0u) | ((m[3] ? neg : 0u) << 16);
        o.z = (m[4] ? neg : 0u) | ((m[5] ? neg : 0u) << 16);
        o.w = (m[6] ? neg : 0u) | ((m[7] ? neg : 0u) << 16);
        ((uint4*)g_mb)[i] = o;
    }
}

// ---------------------------------------------------------------------------
// Projection GEMM: BM=128, BN=256, BK=32, 512 threads (16 warps, 4m x 4n,
// 32x64 warp tiles), 3-stage cp.async (48KB/stage). mma.sync bf16 3-term.
// Stage: Ah@0 | Al@8K | Bh@16K | Bl@32K. Rows 64B, XOR-swizzled.
// ---------------------------------------------------------------------------
#define PSTG 49152u
#define PROJ_SMEM (3u * PSTG)   // 147456

struct ProjArgs { const float* bias[3]; float scale[3]; };

__device__ __forceinline__ void proj_issue(
    uint32_t sb, int st, int kt, int tid, int m0, int n0,
    const unsigned short* Xh, const unsigned short* Xl,
    const unsigned short* Wh, const unsigned short* Wl)
{
    const uint32_t stage = sb + (uint32_t)st * PSTG;
    {   // A planes: 512 lines each, one per thread
        int row = tid >> 2, c = tid & 3;
        uint32_t doff = (uint32_t)row * 64u + (uint32_t)((c ^ ((row >> 1) & 3)) << 4);
        CP16(stage + doff,          Xh + (size_t)(m0 + row) * DM + kt * 32 + c * 8);
        CP16(stage + 8192u + doff,  Xl + (size_t)(m0 + row) * DM + kt * 32 + c * 8);
    }
#pragma unroll
    for (int j = 0; j < 2; ++j) {   // B planes: 1024 lines each
        int line = tid + 512 * j;
        int row = line >> 2, c = line & 3;
        uint32_t doff = (uint32_t)row * 64u + (uint32_t)((c ^ ((row >> 1) & 3)) << 4);
        CP16(stage + 16384u + doff, Wh + (size_t)(n0 + row) * DM + kt * 32 + c * 8);
        CP16(stage + 32768u + doff, Wl + (size_t)(n0 + row) * DM + kt * 32 + c * 8);
    }
    CP_COMMIT();
}

__global__ __launch_bounds__(512) void proj_mma_kernel(ProjArgs args) {
    extern __shared__ char ps[];
    const uint32_t sb = smem_u32(ps);
    const int z = blockIdx.z;
    const unsigned short* __restrict__ Xh = g_xh + (size_t)z * XSEG;
    const unsigned short* __restrict__ Xl = g_xl + (size_t)z * XSEG;
    const unsigned short* __restrict__ Wh = g_wh + (size_t)z * WSEG;
    const unsigned short* __restrict__ Wl = g_wl + (size_t)z * WSEG;
    const float* __restrict__ bias = args.bias[z];
    unsigned short* __restrict__ oh = (z == 0) ? g_qh : (z == 1) ? g_kh : g_vh;
    unsigned short* __restrict__ ol = (z == 0) ? g_ql : (z == 1) ? g_kl : g_vl;
    const float scale = args.scale[z];

    const int tid = threadIdx.x, lane = tid & 31, wid = tid >> 5;
    const int wm = wid & 3, wn = wid >> 2;       // 32m x 64n warp tiles
    const int m0 = blockIdx.y * 128, n0 = blockIdx.x * 256;
    const int flr = lane & 15, flc = lane >> 4;

    float C[2][8][4];
#pragma unroll
    for (int i = 0; i < 2; ++i)
#pragma unroll
        for (int j = 0; j < 8; ++j)
#pragma unroll
            for (int k = 0; k < 4; ++k) C[i][j][k] = 0.f;

    proj_issue(sb, 0, 0, tid, m0, n0, Xh, Xl, Wh, Wl);
    proj_issue(sb, 1, 1, tid, m0, n0, Xh, Xl, Wh, Wl);

    for (int kt = 0; kt < 32; ++kt) {
        if (kt < 31) CP_WAIT1(); else CP_WAIT0();
        __syncthreads();
        if (kt + 2 < 32)
            proj_issue(sb, (kt + 2) % 3, kt + 2, tid, m0, n0, Xh, Xl, Wh, Wl);

        const uint32_t base = sb + (uint32_t)(kt % 3) * PSTG;
#pragma unroll
        for (int ks = 0; ks < 2; ++ks) {
            const uint32_t csw = (uint32_t)(((2 * ks + flc) ^ ((flr >> 1) & 3)) << 4);
            uint32_t a_h[2][4], a_l[2][4];
#pragma unroll
            for (int mt = 0; mt < 2; ++mt) {
                uint32_t off = (uint32_t)((32 * wm + 16 * mt + flr) * 64) + csw;
                ldsm4(base + off, a_h[mt]);
                ldsm4(base + 8192u + off, a_l[mt]);
            }
#pragma unroll
            for (int ntp = 0; ntp < 4; ++ntp) {
                uint32_t boff = (uint32_t)((64 * wn + 16 * ntp + flr) * 64) + csw;
                uint32_t bh4[4], bl4[4];
                ldsm4(base + 16384u + boff, bh4);
                ldsm4(base + 32768u + boff, bl4);
#pragma unroll
                for (int mt = 0; mt < 2; ++mt) {
                    mma16816(C[mt][2 * ntp],     a_h[mt], bh4[0], bh4[2]);
                    mma16816(C[mt][2 * ntp],     a_h[mt], bl4[0], bl4[2]);
                    mma16816(C[mt][2 * ntp],     a_l[mt], bh4[0], bh4[2]);
                    mma16816(C[mt][2 * ntp + 1], a_h[mt], bh4[1], bh4[3]);
                    mma16816(C[mt][2 * ntp + 1], a_h[mt], bl4[1], bl4[3]);
                    mma16816(C[mt][2 * ntp + 1], a_l[mt], bh4[1], bh4[3]);
                }
            }
        }
    }

    // epilogue
#pragma unroll
    for (int nt = 0; nt < 8; ++nt) {
        int n = n0 + 64 * wn + 8 * nt + 2 * (lane & 3);
        int h = n >> 6, d = n & 63;
        float2 bv = *(const float2*)(bias + n);
#pragma unroll
        for (int mt = 0; mt < 2; ++mt) {
            int mbase = m0 + 32 * wm + 16 * mt + (lane >> 2);
#pragma unroll
            for (int half = 0; half < 2; ++half) {
                int m = mbase + 8 * half;
                int b = m >> 11, s = m & (S_ - 1);
                float vx = (C[mt][nt][2 * half + 0] + bv.x) * scale;
                float vy = (C[mt][nt][2 * half + 1] + bv.y) * scale;
                uint32_t hw, lw;
                split_pair(vx, vy, hw, lw);
                size_t off = ((size_t)(b * H_ + h) * S_ + s) * DH + d;
                *(uint32_t*)(oh + off) = hw;
                *(uint32_t*)(ol + off) = lw;
            }
        }
    }
}

// ---------------------------------------------------------------------------
// Flash attention: 512 threads, 16 warps x 16 q-rows (CTA = 256 q-rows),
// K-tile 64, 3-stage cp.async (32KB/stage) + Q planes in smem (64KB).
// Q fragments re-ldsm'd per ks (8 live regs). Mask bias inits S accum.
// Stage: Kh@0 | Kl@8K | Vh@16K | Vl@24K, 128B rows, swizzled.
// Q: Qh @98304 (32KB), Ql @131072 (32KB). Total 163840.
// ---------------------------------------------------------------------------
#define ASTG 32768u
#define AQOFF 98304u
#define ATTN_SMEM 163840u

__device__ __forceinline__ void attn_issue_kv(uint32_t sb, int st, int kt,
                                              int tid, size_t bhS) {
#pragma unroll
    for (int j = 0; j < 4; ++j) {
        int cid = tid + 512 * j;
        int sub = cid >> 9, w = cid & 511, row = w >> 3, c = w & 7;
        const unsigned short* plane = (sub == 0) ? g_kh : (sub == 1) ? g_kl
                                     : (sub == 2) ? g_vh : g_vl;
        const void* src = plane + (bhS + (size_t)(kt * 64 + row)) * DH + c * 8;
        uint32_t dst = sb + (uint32_t)st * ASTG + (uint32_t)sub * 8192u
                     + (uint32_t)row * 128u + (uint32_t)((c ^ (row & 7)) << 4);
        CP16(dst, src);
    }
    CP_COMMIT();
}

__global__ __launch_bounds__(512) void attn_mma_kernel(float* __restrict__ out)
{
    extern __shared__ char as_[];
    const uint32_t sb = smem_u32(as_);

    const int tid = threadIdx.x, lane = tid & 31, wid = tid >> 5;
    const int bz = blockIdx.z, h = blockIdx.y;
    const int q0 = blockIdx.x * 256;
    const size_t bhS = (size_t)(bz * H_ + h) * S_;

    const int flr = lane & 15, flc = lane >> 4;
    const int r_in = lane >> 2;
    const int c_in = 2 * (lane & 3);

    // prologue: Q planes (256 rows x 64 cols x 2 planes) + first two K/V tiles
    {
#pragma unroll
        for (int j = 0; j < 8; ++j) {
            int cid = tid + 512 * j;
            int sub = cid >> 11, w = cid & 2047, row = w >> 3, c = w & 7;
            const unsigned short* plane = sub ? g_ql : g_qh;
            const void* src = plane + (bhS + (size_t)(q0 + row)) * DH + c * 8;
            uint32_t dst = sb + AQOFF + (uint32_t)sub * 32768u
                         + (uint32_t)row * 128u + (uint32_t)((c ^ (row & 7)) << 4);
            CP16(dst, src);
        }
    }
    attn_issue_kv(sb, 0, 0, tid, bhS);   // group 0 (Q + tile0)
    attn_issue_kv(sb, 1, 1, tid, bhS);   // group 1

    float oC[8][4];
#pragma unroll
    for (int j = 0; j < 8; ++j)
#pragma unroll
        for (int k = 0; k < 4; ++k) oC[j][k] = 0.f;
    float mi0 = NEGINF, mi1 = NEGINF, li0 = 0.f, li1 = 0.f;

    const int rowA0 = q0 + 16 * wid + r_in;
    const unsigned short* mb = g_mb + (size_t)bz * S_ * S_;
    const uint32_t qbase = sb + AQOFF;
    const int qrow = 16 * wid + flr;

    for (int kt = 0; kt < 32; ++kt) {
        if (kt < 31) CP_WAIT1(); else CP_WAIT0();
        __syncthreads();
        if (kt + 2 < 32) attn_issue_kv(sb, (kt + 2) % 3, kt + 2, tid, bhS);

        const uint32_t base = sb + (uint32_t)(kt % 3) * ASTG;

        // S accumulators initialized with mask bias
        float sC[8][4];
#pragma unroll
        for (int nt = 0; nt < 8; ++nt) {
            size_t rA = (size_t)rowA0 * S_ + kt * 64 + 8 * nt + c_in;
            uint32_t bA = *(const uint32_t*)(mb + rA);
            uint32_t bB = *(const uint32_t*)(mb + rA + 8 * (size_t)S_);
            sC[nt][0] = bf16lo_f(bA); sC[nt][1] = bf16hi_f(bA);
            sC[nt][2] = bf16lo_f(bB); sC[nt][3] = bf16hi_f(bB);
        }

        // -- S += Q K^T (Q frags re-ldsm'd per ks: 8 live regs) --
#pragma unroll
        for (int ks = 0; ks < 4; ++ks) {
            uint32_t qoff = (uint32_t)(qrow * 128)
                          + (uint32_t)(((2 * ks + flc) ^ (qrow & 7)) << 4);
            uint32_t qh4[4], ql4[4];
            ldsm4(qbase + qoff, qh4);
            ldsm4(qbase + 32768u + qoff, ql4);
#pragma unroll
            for (int ntp = 0; ntp < 4; ++ntp) {
                uint32_t koff = (uint32_t)((16 * ntp + flr) * 128)
                              + (uint32_t)(((2 * ks + flc) ^ (flr & 7)) << 4);
                uint32_t bh4[4], bl4[4];
                ldsm4(base + koff, bh4);
                ldsm4(base + 8192u + koff, bl4);
                mma16816(sC[2 * ntp],     qh4, bh4[0], bh4[2]);
                mma16816(sC[2 * ntp],     qh4, bl4[0], bl4[2]);
                mma16816(sC[2 * ntp],     ql4, bh4[0], bh4[2]);
                mma16816(sC[2 * ntp + 1], qh4, bh4[1], bh4[3]);
                mma16816(sC[2 * ntp + 1], qh4, bl4[1], bl4[3]);
                mma16816(sC[2 * ntp + 1], ql4, bh4[1], bh4[3]);
            }
        }

        // -- online softmax (log2 domain) --
        float mx0 = NEGINF, mx1 = NEGINF;
#pragma unroll
        for (int nt = 0; nt < 8; ++nt) {
            mx0 = fmaxf(mx0, fmaxf(sC[nt][0], sC[nt][1]));
            mx1 = fmaxf(mx1, fmaxf(sC[nt][2], sC[nt][3]));
        }
        mx0 = fmaxf(mx0, __shfl_xor_sync(0xffffffffu, mx0, 1));
        mx0 = fmaxf(mx0, __shfl_xor_sync(0xffffffffu, mx0, 2));
        mx1 = fmaxf(mx1, __shfl_xor_sync(0xffffffffu, mx1, 1));
        mx1 = fmaxf(mx1, __shfl_xor_sync(0xffffffffu, mx1, 2));

        float mn0 = fmaxf(mi0, mx0), mn1 = fmaxf(mi1, mx1);
        float f0 = ex2f(mi0 - mn0), f1 = ex2f(mi1 - mn1);
        float sum0 = 0.f, sum1 = 0.f;
#pragma unroll
        for (int nt = 0; nt < 8; ++nt) {
            sC[nt][0] = ex2f(sC[nt][0] - mn0);
            sC[nt][1] = ex2f(sC[nt][1] - mn0);
            sC[nt][2] = ex2f(sC[nt][2] - mn1);
            sC[nt][3] = ex2f(sC[nt][3] - mn1);
            sum0 += sC[nt][0] + sC[nt][1];
            sum1 += sC[nt][2] + sC[nt][3];
        }
        sum0 += __shfl_xor_sync(0xffffffffu, sum0, 1);
        sum0 += __shfl_xor_sync(0xffffffffu, sum0, 2);
        sum1 += __shfl_xor_sync(0xffffffffu, sum1, 1);
        sum1 += __shfl_xor_sync(0xffffffffu, sum1, 2);
        li0 = li0 * f0 + sum0;
        li1 = li1 * f1 + sum1;
        mi0 = mn0; mi1 = mn1;
#pragma unroll
        for (int nt = 0; nt < 8; ++nt) {
            oC[nt][0] *= f0; oC[nt][1] *= f0;
            oC[nt][2] *= f1; oC[nt][3] *= f1;
        }

        // -- O += P V --
#pragma unroll
        for (int kp = 0; kp < 4; ++kp) {
            uint32_t pa_h[4], pa_l[4];
            split_pair(sC[2 * kp][0],     sC[2 * kp][1],     pa_h[0], pa_l[0]);
            split_pair(sC[2 * kp][2],     sC[2 * kp][3],     pa_h[1], pa_l[1]);
            split_pair(sC[2 * kp + 1][0], sC[2 * kp + 1][1], pa_h[2], pa_l[2]);
            split_pair(sC[2 * kp + 1][2], sC[2 * kp + 1][3], pa_h[3], pa_l[3]);

            const int trow = kp * 16 + ((lane >> 3) & 1) * 8 + (lane & 7);
            const int cb = lane >> 4;
#pragma unroll
            for (int ntp = 0; ntp < 4; ++ntp) {
                uint32_t voff = (uint32_t)(trow * 128)
                              + (uint32_t)(((2 * ntp + cb) ^ (trow & 7)) << 4);
                uint32_t vh4[4], vl4[4];
                ldsm4t(base + 16384u + voff, vh4);
                ldsm4t(base + 24576u + voff, vl4);
                mma16816(oC[2 * ntp],     pa_h, vh4[0], vh4[1]);
                mma16816(oC[2 * ntp],     pa_h, vl4[0], vl4[1]);
                mma16816(oC[2 * ntp],     pa_l, vh4[0], vh4[1]);
                mma16816(oC[2 * ntp + 1], pa_h, vh4[2], vh4[3]);
                mma16816(oC[2 * ntp + 1], pa_h, vl4[2], vl4[3]);
                mma16816(oC[2 * ntp + 1], pa_l, vh4[2], vh4[3]);
            }
        }
    }

    // ---- epilogue ----
    float inv0 = (li0 > 0.f) ? 1.0f / li0 : 0.f;
    float inv1 = (li1 > 0.f) ? 1.0f / li1 : 0.f;
    const int qr = rowA0;
    const int d0 = h * DH + c_in;
#pragma unroll
    for (int nt = 0; nt < 8; ++nt) {
        float2 v0, v1;
        v0.x = oC[nt][0] * inv0; v0.y = oC[nt][1] * inv0;
        v1.x = oC[nt][2] * inv1; v1.y = oC[nt][3] * inv1;
        *(float2*)(out + (size_t)(bz * S_ + qr) * DM + d0 + 8 * nt) = v0;
        *(float2*)(out + (size_t)(bz * S_ + qr + 8) * DM + d0 + 8 * nt) = v1;
    }
}

// ---------------------------------------------------------------------------
extern "C" void kernel_launch(void* const* d_in, const int* in_sizes, int n_in,
                              void* d_out, int out_size) {
    const void* mask = d_in[3];
    float* out = (float*)d_out;

    static int attr_done = 0;
    if (!attr_done) {
        cudaFuncSetAttribute(proj_mma_kernel,
                             cudaFuncAttributeMaxDynamicSharedMemorySize, PROJ_SMEM);
        cudaFuncSetAttribute(attn_mma_kernel,
                             cudaFuncAttributeMaxDynamicSharedMemorySize, ATTN_SMEM);
        attr_done = 1;
    }

    ConvArgs ca;
    ca.src[0] = (const float*)d_in[0];
    ca.src[1] = (const float*)d_in[1];
    ca.src[2] = (const float*)d_in[2];
    ca.src[3] = (const float*)d_in[4];
    ca.src[4] = (const float*)d_in[6];
    ca.src[5] = (const float*)d_in[8];
    convert_kernel<<<dim3(1024, 1, 7), 256>>>(ca, (const unsigned int*)mask);

    mask_conv_kernel<<<1024, 256>>>(mask);

    ProjArgs pa;
    pa.bias[0] = (const float*)d_in[5];
    pa.bias[1] = (const float*)d_in[7];
    pa.bias[2] = (const float*)d_in[9];
    pa.scale[0] = QSCALE; pa.scale[1] = 1.0f; pa.scale[2] = 1.0f;
    proj_mma_kernel<<<dim3(4, 32, 3), 512, PROJ_SMEM>>>(pa);

    attn_mma_kernel<<<dim3(8, 16, 2), 512, ATTN_SMEM>>>(out);
}

// round 9
// speedup vs baseline: 2.6153x; 1.0047x over previous
#include <cuda_runtime.h>
#include <cuda_bf16.h>
#include <cstdint>
#include <cstddef>

#define B_  2
#define S_  2048
#define DM  1024
#define H_  16
#define DH  64
#define M_  (B_*S_)   // 4096
#define NEGINF -1e30f
#define QSCALE (0.125f * 1.44269504088896f)

#define XSEG (M_*DM)
#define WSEG (DM*DM)
#define QKV  (B_*H_*S_*DH)

__device__ unsigned short g_xh[3*XSEG], g_xl[3*XSEG];
__device__ unsigned short g_wh[3*WSEG], g_wl[3*WSEG];
__device__ unsigned short g_qh[QKV], g_ql[QKV];
__device__ unsigned short g_kh[QKV], g_kl[QKV];
__device__ unsigned short g_vh[QKV], g_vl[QKV];
__device__ unsigned short g_mb[(size_t)B_*S_*S_];   // mask bias (0 / bf16(-1e30))
__device__ int g_mask_mode;

// ---------------------------------------------------------------------------
__device__ __forceinline__ uint32_t smem_u32(const void* p) {
    uint32_t a;
    asm("{ .reg .u64 t; cvta.to.shared.u64 t, %1; cvt.u32.u64 %0, t; }"
        : "=r"(a) : "l"(p));
    return a;
}
__device__ __forceinline__ void ldsm4(uint32_t addr, uint32_t* r) {
    asm volatile("ldmatrix.sync.aligned.m8n8.x4.shared.b16 {%0,%1,%2,%3}, [%4];"
        : "=r"(r[0]), "=r"(r[1]), "=r"(r[2]), "=r"(r[3]) : "r"(addr));
}
__device__ __forceinline__ void ldsm4t(uint32_t addr, uint32_t* r) {
    asm volatile("ldmatrix.sync.aligned.m8n8.x4.trans.shared.b16 {%0,%1,%2,%3}, [%4];"
        : "=r"(r[0]), "=r"(r[1]), "=r"(r[2]), "=r"(r[3]) : "r"(addr));
}
__device__ __forceinline__ void mma16816(float* c, const uint32_t* a,
                                         uint32_t b0, uint32_t b1) {
    asm volatile(
        "mma.sync.aligned.m16n8k16.row.col.f32.bf16.bf16.f32 "
        "{%0,%1,%2,%3}, {%4,%5,%6,%7}, {%8,%9}, {%0,%1,%2,%3};"
        : "+f"(c[0]), "+f"(c[1]), "+f"(c[2]), "+f"(c[3])
        : "r"(a[0]), "r"(a[1]), "r"(a[2]), "r"(a[3]), "r"(b0), "r"(b1));
}
__device__ __forceinline__ uint32_t cvt2_bf16(float lo_elem, float hi_elem) {
    uint32_t r;
    asm("cvt.rn.bf16x2.f32 %0, %1, %2;" : "=r"(r) : "f"(hi_elem), "f"(lo_elem));
    return r;
}
__device__ __forceinline__ float bf16lo_f(uint32_t v) { return __uint_as_float(v << 16); }
__device__ __forceinline__ float bf16hi_f(uint32_t v) { return __uint_as_float(v & 0xFFFF0000u); }
__device__ __forceinline__ void split_pair(float x, float y, uint32_t& h, uint32_t& l) {
    h = cvt2_bf16(x, y);
    float rx = x - bf16lo_f(h);
    float ry = y - bf16hi_f(h);
    l = cvt2_bf16(rx, ry);
}
__device__ __forceinline__ void split4(float4 v, uint2& hw, uint2& lw) {
    uint32_t h0, l0, h1, l1;
    split_pair(v.x, v.y, h0, l0);
    split_pair(v.z, v.w, h1, l1);
    hw.x = h0; hw.y = h1; lw.x = l0; lw.y = l1;
}
__device__ __forceinline__ float ex2f(float x) {
    float y;
    asm("ex2.approx.f32 %0, %1;" : "=f"(y) : "f"(x));
    return y;
}
#define CP16(dst, src) \
    asm volatile("cp.async.cg.shared.global [%0], [%1], 16;" :: "r"(dst), "l"(src))
#define CP_COMMIT() asm volatile("cp.async.commit_group;")
#define CP_WAIT1()  asm volatile("cp.async.wait_group 1;")
#define CP_WAIT0()  asm volatile("cp.async.wait_group 0;")

// ---------------------------------------------------------------------------
// Convert fp32 -> split bf16 planes; z==6 detects mask dtype.
// ---------------------------------------------------------------------------
struct ConvArgs { const float* src[6]; };

__global__ __launch_bounds__(256) void convert_kernel(ConvArgs a,
                                                      const unsigned int* mask) {
    const int z = blockIdx.z;
    const int tid = threadIdx.x;
    if (z == 6) {
        if (blockIdx.x != 0) return;
        int ok_i32 = 1, ok_u8 = 1;
        for (int i = tid; i < 4096; i += 256) {
            unsigned w = mask[i];
            ok_i32 &= (w <= 1u);
            ok_u8  &= ((w & 0xFEFEFEFEu) == 0u);
        }
        ok_i32 = __syncthreads_and(ok_i32);
        ok_u8  = __syncthreads_and(ok_u8);
        if (tid == 0) g_mask_mode = ok_i32 ? 0 : (ok_u8 ? 1 : 2);
        return;
    }
    const float4* src = (const float4*)a.src[z];
    int nf8;
    unsigned short *dh, *dl;
    if (z < 3) { nf8 = XSEG / 8; dh = g_xh + (size_t)z * XSEG; dl = g_xl + (size_t)z * XSEG; }
    else       { nf8 = WSEG / 8; dh = g_wh + (size_t)(z - 3) * WSEG; dl = g_wl + (size_t)(z - 3) * WSEG; }
    for (int i = blockIdx.x * 256 + tid; i < nf8; i += 1024 * 256) {
        float4 v0 = src[2 * i];
        float4 v1 = src[2 * i + 1];
        uint2 h0, l0, h1, l1;
        split4(v0, h0, l0);
        split4(v1, h1, l1);
        uint4 hv, lv;
        hv.x = h0.x; hv.y = h0.y; hv.z = h1.x; hv.w = h1.y;
        lv.x = l0.x; lv.y = l0.y; lv.z = l1.x; lv.w = l1.y;
        ((uint4*)dh)[i] = hv;
        ((uint4*)dl)[i] = lv;
    }
}

// ---------------------------------------------------------------------------
// Mask -> bf16 additive bias plane.
// ---------------------------------------------------------------------------
__global__ __launch_bounds__(256) void mask_conv_kernel(const void* mask) {
    const int mode = g_mask_mode;
    __nv_bfloat16 nb = __float2bfloat16(NEGINF);
    const uint32_t neg = (uint32_t)*(unsigned short*)&nb;
    const int n8 = (int)(((size_t)B_ * S_ * S_) / 8);
    for (int i = blockIdx.x * 256 + threadIdx.x; i < n8; i += gridDim.x * 256) {
        unsigned m[8];
        if (mode == 0) {
            int4 a = ((const int4*)mask)[2 * i];
            int4 b = ((const int4*)mask)[2 * i + 1];
            m[0] = a.x != 0; m[1] = a.y != 0; m[2] = a.z != 0; m[3] = a.w != 0;
            m[4] = b.x != 0; m[5] = b.y != 0; m[6] = b.z != 0; m[7] = b.w != 0;
        } else if (mode == 1) {
            uint2 a = ((const uint2*)mask)[i];
#pragma unroll
            for (int j = 0; j < 4; ++j) m[j] = (a.x >> (8 * j)) & 255u;
#pragma unroll
            for (int j = 0; j < 4; ++j) m[4 + j] = (a.y >> (8 * j)) & 255u;
        } else {
            float4 a = ((const float4*)mask)[2 * i];
            float4 b = ((const float4*)mask)[2 * i + 1];
            m[0] = a.x != 0.f; m[1] = a.y != 0.f; m[2] = a.z != 0.f; m[3] = a.w != 0.f;
            m[4] = b.x != 0.f; m[5] = b.y != 0.f; m[6] = b.z != 0.f; m[7] = b.w != 0.f;
        }
        uint4 o;
        o.x = (m[0] ? neg : 0u) | ((m[1] ? neg : 0u) << 16);
        o.y = (m[2] ? neg : 0u) | ((m[3] ? neg : 0u) << 16);
        o.z = (m[4] ? neg : 0u) | ((m[5] ? neg : 0u) << 16);
        o.w = (m[6] ? neg : 0u) | ((m[7] ? neg : 0u) << 16);
        ((uint4*)g_mb)[i] = o;
    }
}

// ---------------------------------------------------------------------------
// Projection GEMM: BM=128, BN=256, BK=32, 512 threads (16 warps, 4m x 4n,
// 32x64 warp tiles), 3-stage cp.async. Term-major MMA ordering (distance 4).
// ---------------------------------------------------------------------------
#define PSTG 49152u
#define PROJ_SMEM (3u * PSTG)   // 147456

struct ProjArgs { const float* bias[3]; float scale[3]; };

__device__ __forceinline__ void proj_issue(
    uint32_t sb, int st, int kt, int tid, int m0, int n0,
    const unsigned short* Xh, const unsigned short* Xl,
    const unsigned short* Wh, const unsigned short* Wl)
{
    const uint32_t stage = sb + (uint32_t)st * PSTG;
    {
        int row = tid >> 2, c = tid & 3;
        uint32_t doff = (uint32_t)row * 64u + (uint32_t)((c ^ ((row >> 1) & 3)) << 4);
        CP16(stage + doff,          Xh + (size_t)(m0 + row) * DM + kt * 32 + c * 8);
        CP16(stage + 8192u + doff,  Xl + (size_t)(m0 + row) * DM + kt * 32 + c * 8);
    }
#pragma unroll
    for (int j = 0; j < 2; ++j) {
        int line = tid + 512 * j;
        int row = line >> 2, c = line & 3;
        uint32_t doff = (uint32_t)row * 64u + (uint32_t)((c ^ ((row >> 1) & 3)) << 4);
        CP16(stage + 16384u + doff, Wh + (size_t)(n0 + row) * DM + kt * 32 + c * 8);
        CP16(stage + 32768u + doff, Wl + (size_t)(n0 + row) * DM + kt * 32 + c * 8);
    }
    CP_COMMIT();
}

__global__ __launch_bounds__(512) void proj_mma_kernel(ProjArgs args) {
    extern __shared__ char ps[];
    const uint32_t sb = smem_u32(ps);
    const int z = blockIdx.z;
    const unsigned short* __restrict__ Xh = g_xh + (size_t)z * XSEG;
    const unsigned short* __restrict__ Xl = g_xl + (size_t)z * XSEG;
    const unsigned short* __restrict__ Wh = g_wh + (size_t)z * WSEG;
    const unsigned short* __restrict__ Wl = g_wl + (size_t)z * WSEG;
    const float* __restrict__ bias = args.bias[z];
    unsigned short* __restrict__ oh = (z == 0) ? g_qh : (z == 1) ? g_kh : g_vh;
    unsigned short* __restrict__ ol = (z == 0) ? g_ql : (z == 1) ? g_kl : g_vl;
    const float scale = args.scale[z];

    const int tid = threadIdx.x, lane = tid & 31, wid = tid >> 5;
    const int wm = wid & 3, wn = wid >> 2;
    const int m0 = blockIdx.y * 128, n0 = blockIdx.x * 256;
    const int flr = lane & 15, flc = lane >> 4;

    float C[2][8][4];
#pragma unroll
    for (int i = 0; i < 2; ++i)
#pragma unroll
        for (int j = 0; j < 8; ++j)
#pragma unroll
            for (int k = 0; k < 4; ++k) C[i][j][k] = 0.f;

    proj_issue(sb, 0, 0, tid, m0, n0, Xh, Xl, Wh, Wl);
    proj_issue(sb, 1, 1, tid, m0, n0, Xh, Xl, Wh, Wl);

    for (int kt = 0; kt < 32; ++kt) {
        if (kt < 31) CP_WAIT1(); else CP_WAIT0();
        __syncthreads();
        if (kt + 2 < 32)
            proj_issue(sb, (kt + 2) % 3, kt + 2, tid, m0, n0, Xh, Xl, Wh, Wl);

        const uint32_t base = sb + (uint32_t)(kt % 3) * PSTG;
#pragma unroll
        for (int ks = 0; ks < 2; ++ks) {
            const uint32_t csw = (uint32_t)(((2 * ks + flc) ^ ((flr >> 1) & 3)) << 4);
            uint32_t a_h[2][4], a_l[2][4];
#pragma unroll
            for (int mt = 0; mt < 2; ++mt) {
                uint32_t off = (uint32_t)((32 * wm + 16 * mt + flr) * 64) + csw;
                ldsm4(base + off, a_h[mt]);
                ldsm4(base + 8192u + off, a_l[mt]);
            }
#pragma unroll
            for (int ntp = 0; ntp < 4; ++ntp) {
                uint32_t boff = (uint32_t)((64 * wn + 16 * ntp + flr) * 64) + csw;
                uint32_t bh4[4], bl4[4];
                ldsm4(base + 16384u + boff, bh4);
                ldsm4(base + 32768u + boff, bl4);
                // term-major: same-accumulator distance = 4
                mma16816(C[0][2 * ntp],     a_h[0], bh4[0], bh4[2]);
                mma16816(C[1][2 * ntp],     a_h[1], bh4[0], bh4[2]);
                mma16816(C[0][2 * ntp + 1], a_h[0], bh4[1], bh4[3]);
                mma16816(C[1][2 * ntp + 1], a_h[1], bh4[1], bh4[3]);

                mma16816(C[0][2 * ntp],     a_h[0], bl4[0], bl4[2]);
                mma16816(C[1][2 * ntp],     a_h[1], bl4[0], bl4[2]);
                mma16816(C[0][2 * ntp + 1], a_h[0], bl4[1], bl4[3]);
                mma16816(C[1][2 * ntp + 1], a_h[1], bl4[1], bl4[3]);

                mma16816(C[0][2 * ntp],     a_l[0], bh4[0], bh4[2]);
                mma16816(C[1][2 * ntp],     a_l[1], bh4[0], bh4[2]);
                mma16816(C[0][2 * ntp + 1], a_l[0], bh4[1], bh4[3]);
                mma16816(C[1][2 * ntp + 1], a_l[1], bh4[1], bh4[3]);
            }
        }
    }

    // epilogue
#pragma unroll
    for (int nt = 0; nt < 8; ++nt) {
        int n = n0 + 64 * wn + 8 * nt + 2 * (lane & 3);
        int h = n >> 6, d = n & 63;
        float2 bv = *(const float2*)(bias + n);
#pragma unroll
        for (int mt = 0; mt < 2; ++mt) {
            int mbase = m0 + 32 * wm + 16 * mt + (lane >> 2);
#pragma unroll
            for (int half = 0; half < 2; ++half) {
                int m = mbase + 8 * half;
                int b = m >> 11, s = m & (S_ - 1);
                float vx = (C[mt][nt][2 * half + 0] + bv.x) * scale;
                float vy = (C[mt][nt][2 * half + 1] + bv.y) * scale;
                uint32_t hw, lw;
                split_pair(vx, vy, hw, lw);
                size_t off = ((size_t)(b * H_ + h) * S_ + s) * DH + d;
                *(uint32_t*)(oh + off) = hw;
                *(uint32_t*)(ol + off) = lw;
            }
        }
    }
}

// ---------------------------------------------------------------------------
// Flash attention: 512 threads, 16 warps x 16 q-rows, K-tile 64,
// 3-stage cp.async + Q planes in smem. Term-major MMA ordering (distance 8).
// ---------------------------------------------------------------------------
#define ASTG 32768u
#define AQOFF 98304u
#define ATTN_SMEM 163840u

__device__ __forceinline__ void attn_issue_kv(uint32_t sb, int st, int kt,
                                              int tid, size_t bhS) {
#pragma unroll
    for (int j = 0; j < 4; ++j) {
        int cid = tid + 512 * j;
        int sub = cid >> 9, w = cid & 511, row = w >> 3, c = w & 7;
        const unsigned short* plane = (sub == 0) ? g_kh : (sub == 1) ? g_kl
                                     : (sub == 2) ? g_vh : g_vl;
        const void* src = plane + (bhS + (size_t)(kt * 64 + row)) * DH + c * 8;
        uint32_t dst = sb + (uint32_t)st * ASTG + (uint32_t)sub * 8192u
                     + (uint32_t)row * 128u + (uint32_t)((c ^ (row & 7)) << 4);
        CP16(dst, src);
    }
    CP_COMMIT();
}

__global__ __launch_bounds__(512) void attn_mma_kernel(float* __restrict__ out)
{
    extern __shared__ char as_[];
    const uint32_t sb = smem_u32(as_);

    const int tid = threadIdx.x, lane = tid & 31, wid = tid >> 5;
    const int bz = blockIdx.z, h = blockIdx.y;
    const int q0 = blockIdx.x * 256;
    const size_t bhS = (size_t)(bz * H_ + h) * S_;

    const int flr = lane & 15, flc = lane >> 4;
    const int r_in = lane >> 2;
    const int c_in = 2 * (lane & 3);

    // prologue: Q planes + first two K/V tiles
    {
#pragma unroll
        for (int j = 0; j < 8; ++j) {
            int cid = tid + 512 * j;
            int sub = cid >> 11, w = cid & 2047, row = w >> 3, c = w & 7;
            const unsigned short* plane = sub ? g_ql : g_qh;
            const void* src = plane + (bhS + (size_t)(q0 + row)) * DH + c * 8;
            uint32_t dst = sb + AQOFF + (uint32_t)sub * 32768u
                         + (uint32_t)row * 128u + (uint32_t)((c ^ (row & 7)) << 4);
            CP16(dst, src);
        }
    }
    attn_issue_kv(sb, 0, 0, tid, bhS);
    attn_issue_kv(sb, 1, 1, tid, bhS);

    float oC[8][4];
#pragma unroll
    for (int j = 0; j < 8; ++j)
#pragma unroll
        for (int k = 0; k < 4; ++k) oC[j][k] = 0.f;
    float mi0 = NEGINF, mi1 = NEGINF, li0 = 0.f, li1 = 0.f;

    const int rowA0 = q0 + 16 * wid + r_in;
    const unsigned short* mb = g_mb + (size_t)bz * S_ * S_;
    const uint32_t qbase = sb + AQOFF;
    const int qrow = 16 * wid + flr;

    for (int kt = 0; kt < 32; ++kt) {
        if (kt < 31) CP_WAIT1(); else CP_WAIT0();
        __syncthreads();
        if (kt + 2 < 32) attn_issue_kv(sb, (kt + 2) % 3, kt + 2, tid, bhS);

        const uint32_t base = sb + (uint32_t)(kt % 3) * ASTG;

        // S accumulators initialized with mask bias
        float sC[8][4];
#pragma unroll
        for (int nt = 0; nt < 8; ++nt) {
            size_t rA = (size_t)rowA0 * S_ + kt * 64 + 8 * nt + c_in;
            uint32_t bA = *(const uint32_t*)(mb + rA);
            uint32_t bB = *(const uint32_t*)(mb + rA + 8 * (size_t)S_);
            sC[nt][0] = bf16lo_f(bA); sC[nt][1] = bf16hi_f(bA);
            sC[nt][2] = bf16lo_f(bB); sC[nt][3] = bf16hi_f(bB);
        }

        // -- S += Q K^T, term-major (same-accumulator distance 8) --
#pragma unroll
        for (int ks = 0; ks < 4; ++ks) {
            uint32_t qoff = (uint32_t)(qrow * 128)
                          + (uint32_t)(((2 * ks + flc) ^ (qrow & 7)) << 4);
            uint32_t qh4[4], ql4[4];
            ldsm4(qbase + qoff, qh4);
            ldsm4(qbase + 32768u + qoff, ql4);
            uint32_t bh4[4][4], bl4[4][4];
#pragma unroll
            for (int ntp = 0; ntp < 4; ++ntp) {
                uint32_t koff = (uint32_t)((16 * ntp + flr) * 128)
                              + (uint32_t)(((2 * ks + flc) ^ (flr & 7)) << 4);
                ldsm4(base + koff, bh4[ntp]);
                ldsm4(base + 8192u + koff, bl4[ntp]);
            }
#pragma unroll
            for (int ntp = 0; ntp < 4; ++ntp) {
                mma16816(sC[2 * ntp],     qh4, bh4[ntp][0], bh4[ntp][2]);
                mma16816(sC[2 * ntp + 1], qh4, bh4[ntp][1], bh4[ntp][3]);
            }
#pragma unroll
            for (int ntp = 0; ntp < 4; ++ntp) {
                mma16816(sC[2 * ntp],     qh4, bl4[ntp][0], bl4[ntp][2]);
                mma16816(sC[2 * ntp + 1], qh4, bl4[ntp][1], bl4[ntp][3]);
            }
#pragma unroll
            for (int ntp = 0; ntp < 4; ++ntp) {
                mma16816(sC[2 * ntp],     ql4, bh4[ntp][0], bh4[ntp][2]);
                mma16816(sC[2 * ntp + 1], ql4, bh4[ntp][1], bh4[ntp][3]);
            }
        }

        // -- online softmax (log2 domain) --
        float mx0 = NEGINF, mx1 = NEGINF;
#pragma unroll
        for (int nt = 0; nt < 8; ++nt) {
            mx0 = fmaxf(mx0, fmaxf(sC[nt][0], sC[nt][1]));
            mx1 = fmaxf(mx1, fmaxf(sC[nt][2], sC[nt][3]));
        }
        mx0 = fmaxf(mx0, __shfl_xor_sync(0xffffffffu, mx0, 1));
        mx0 = fmaxf(mx0, __shfl_xor_sync(0xffffffffu, mx0, 2));
        mx1 = fmaxf(mx1, __shfl_xor_sync(0xffffffffu, mx1, 1));
        mx1 = fmaxf(mx1, __shfl_xor_sync(0xffffffffu, mx1, 2));

        float mn0 = fmaxf(mi0, mx0), mn1 = fmaxf(mi1, mx1);
        float f0 = ex2f(mi0 - mn0), f1 = ex2f(mi1 - mn1);
        float sum0 = 0.f, sum1 = 0.f;
#pragma unroll
        for (int nt = 0; nt < 8; ++nt) {
            sC[nt][0] = ex2f(sC[nt][0] - mn0);
            sC[nt][1] = ex2f(sC[nt][1] - mn0);
            sC[nt][2] = ex2f(sC[nt][2] - mn1);
            sC[nt][3] = ex2f(sC[nt][3] - mn1);
            sum0 += sC[nt][0] + sC[nt][1];
            sum1 += sC[nt][2] + sC[nt][3];
        }
        sum0 += __shfl_xor_sync(0xffffffffu, sum0, 1);
        sum0 += __shfl_xor_sync(0xffffffffu, sum0, 2);
        sum1 += __shfl_xor_sync(0xffffffffu, sum1, 1);
        sum1 += __shfl_xor_sync(0xffffffffu, sum1, 2);
        li0 = li0 * f0 + sum0;
        li1 = li1 * f1 + sum1;
        mi0 = mn0; mi1 = mn1;
#pragma unroll
        for (int nt = 0; nt < 8; ++nt) {
            oC[nt][0] *= f0; oC[nt][1] *= f0;
            oC[nt][2] *= f1; oC[nt][3] *= f1;
        }

        // -- O += P V, term-major (same-accumulator distance 8) --
#pragma unroll
        for (int kp = 0; kp < 4; ++kp) {
            uint32_t pa_h[4], pa_l[4];
            split_pair(sC[2 * kp][0],     sC[2 * kp][1],     pa_h[0], pa_l[0]);
            split_pair(sC[2 * kp][2],     sC[2 * kp][3],     pa_h[1], pa_l[1]);
            split_pair(sC[2 * kp + 1][0], sC[2 * kp + 1][1], pa_h[2], pa_l[2]);
            split_pair(sC[2 * kp + 1][2], sC[2 * kp + 1][3], pa_h[3], pa_l[3]);

            const int trow = kp * 16 + ((lane >> 3) & 1) * 8 + (lane & 7);
            const int cb = lane >> 4;
            uint32_t vh4[4][4], vl4[4][4];
#pragma unroll
            for (int ntp = 0; ntp < 4; ++ntp) {
                uint32_t voff = (uint32_t)(trow * 128)
                              + (uint32_t)(((2 * ntp + cb) ^ (trow & 7)) << 4);
                ldsm4t(base + 16384u + voff, vh4[ntp]);
                ldsm4t(base + 24576u + voff, vl4[ntp]);
            }
#pragma unroll
            for (int ntp = 0; ntp < 4; ++ntp) {
                mma16816(oC[2 * ntp],     pa_h, vh4[ntp][0], vh4[ntp][1]);
                mma16816(oC[2 * ntp + 1], pa_h, vh4[ntp][2], vh4[ntp][3]);
            }
#pragma unroll
            for (int ntp = 0; ntp < 4; ++ntp) {
                mma16816(oC[2 * ntp],     pa_h, vl4[ntp][0], vl4[ntp][1]);
                mma16816(oC[2 * ntp + 1], pa_h, vl4[ntp][2], vl4[ntp][3]);
            }
#pragma unroll
            for (int ntp = 0; ntp < 4; ++ntp) {
                mma16816(oC[2 * ntp],     pa_l, vh4[ntp][0], vh4[ntp][1]);
                mma16816(oC[2 * ntp + 1], pa_l, vh4[ntp][2], vh4[ntp][3]);
            }
        }
    }

    // ---- epilogue ----
    float inv0 = (li0 > 0.f) ? 1.0f / li0 : 0.f;
    float inv1 = (li1 > 0.f) ? 1.0f / li1 : 0.f;
    const int qr = rowA0;
    const int d0 = h * DH + c_in;
#pragma unroll
    for (int nt = 0; nt < 8; ++nt) {
        float2 v0, v1;
        v0.x = oC[nt][0] * inv0; v0.y = oC[nt][1] * inv0;
        v1.x = oC[nt][2] * inv1; v1.y = oC[nt][3] * inv1;
        *(float2*)(out + (size_t)(bz * S_ + qr) * DM + d0 + 8 * nt) = v0;
        *(float2*)(out + (size_t)(bz * S_ + qr + 8) * DM + d0 + 8 * nt) = v1;
    }
}

// ---------------------------------------------------------------------------
extern "C" void kernel_launch(void* const* d_in, const int* in_sizes, int n_in,
                              void* d_out, int out_size) {
    const void* mask = d_in[3];
    float* out = (float*)d_out;

    static int attr_done = 0;
    if (!attr_done) {
        cudaFuncSetAttribute(proj_mma_kernel,
                             cudaFuncAttributeMaxDynamicSharedMemorySize, PROJ_SMEM);
        cudaFuncSetAttribute(attn_mma_kernel,
                             cudaFuncAttributeMaxDynamicSharedMemorySize, ATTN_SMEM);
        attr_done = 1;
    }

    ConvArgs ca;
    ca.src[0] = (const float*)d_in[0];
    ca.src[1] = (const float*)d_in[1];
    ca.src[2] = (const float*)d_in[2];
    ca.src[3] = (const float*)d_in[4];
    ca.src[4] = (const float*)d_in[6];
    ca.src[5] = (const float*)d_in[8];
    convert_kernel<<<dim3(1024, 1, 7), 256>>>(ca, (const unsigned int*)mask);

    mask_conv_kernel<<<1024, 256>>>(mask);

    ProjArgs pa;
    pa.bias[0] = (const float*)d_in[5];
    pa.bias[1] = (const float*)d_in[7];
    pa.bias[2] = (const float*)d_in[9];
    pa.scale[0] = QSCALE; pa.scale[1] = 1.0f; pa.scale[2] = 1.0f;
    proj_mma_kernel<<<dim3(4, 32, 3), 512, PROJ_SMEM>>>(pa);

    attn_mma_kernel<<<dim3(8, 16, 2), 512, ATTN_SMEM>>>(out);
}

// round 10
// speedup vs baseline: 3.2530x; 1.2438x over previous
#include <cuda_runtime.h>
#include <cuda_bf16.h>
#include <cuda_fp16.h>
#include <cstdint>
#include <cstddef>

#define B_  2
#define S_  2048
#define DM  1024
#define H_  16
#define DH  64
#define M_  (B_*S_)   // 4096
#define NEGINF -1e30f
#define QSCALE (0.125f * 1.44269504088896f)

#define XSEG (M_*DM)
#define WSEG (DM*DM)
#define QKV  (B_*H_*S_*DH)

__device__ unsigned short g_xh[3*XSEG], g_xl[3*XSEG];   // bf16 split inputs
__device__ unsigned short g_wh[3*WSEG], g_wl[3*WSEG];   // bf16 split weights
__device__ unsigned short g_qh[QKV], g_ql[QKV];         // Q: fp16 hi + fp16 residual
__device__ unsigned short g_kh[QKV];                    // K: single fp16
__device__ unsigned short g_vh[QKV];                    // V: single fp16
__device__ unsigned short g_mb[(size_t)B_*S_*S_];       // mask bias (0 / bf16(-1e30))
__device__ int g_mask_mode;

// ---------------------------------------------------------------------------
__device__ __forceinline__ uint32_t smem_u32(const void* p) {
    uint32_t a;
    asm("{ .reg .u64 t; cvta.to.shared.u64 t, %1; cvt.u32.u64 %0, t; }"
        : "=r"(a) : "l"(p));
    return a;
}
__device__ __forceinline__ void ldsm4(uint32_t addr, uint32_t* r) {
    asm volatile("ldmatrix.sync.aligned.m8n8.x4.shared.b16 {%0,%1,%2,%3}, [%4];"
        : "=r"(r[0]), "=r"(r[1]), "=r"(r[2]), "=r"(r[3]) : "r"(addr));
}
__device__ __forceinline__ void ldsm4t(uint32_t addr, uint32_t* r) {
    asm volatile("ldmatrix.sync.aligned.m8n8.x4.trans.shared.b16 {%0,%1,%2,%3}, [%4];"
        : "=r"(r[0]), "=r"(r[1]), "=r"(r[2]), "=r"(r[3]) : "r"(addr));
}
// bf16 mma (projections)
__device__ __forceinline__ void mma16816(float* c, const uint32_t* a,
                                         uint32_t b0, uint32_t b1) {
    asm volatile(
        "mma.sync.aligned.m16n8k16.row.col.f32.bf16.bf16.f32 "
        "{%0,%1,%2,%3}, {%4,%5,%6,%7}, {%8,%9}, {%0,%1,%2,%3};"
        : "+f"(c[0]), "+f"(c[1]), "+f"(c[2]), "+f"(c[3])
        : "r"(a[0]), "r"(a[1]), "r"(a[2]), "r"(a[3]), "r"(b0), "r"(b1));
}
// fp16 mma (attention)
__device__ __forceinline__ void mma16816f(float* c, const uint32_t* a,
                                          uint32_t b0, uint32_t b1) {
    asm volatile(
        "mma.sync.aligned.m16n8k16.row.col.f32.f16.f16.f32 "
        "{%0,%1,%2,%3}, {%4,%5,%6,%7}, {%8,%9}, {%0,%1,%2,%3};"
        : "+f"(c[0]), "+f"(c[1]), "+f"(c[2]), "+f"(c[3])
        : "r"(a[0]), "r"(a[1]), "r"(a[2]), "r"(a[3]), "r"(b0), "r"(b1));
}
__device__ __forceinline__ uint32_t cvt2_bf16(float lo_elem, float hi_elem) {
    uint32_t r;
    asm("cvt.rn.bf16x2.f32 %0, %1, %2;" : "=r"(r) : "f"(hi_elem), "f"(lo_elem));
    return r;
}
__device__ __forceinline__ uint32_t cvt2_f16(float lo_elem, float hi_elem) {
    uint32_t r;
    asm("cvt.rn.f16x2.f32 %0, %1, %2;" : "=r"(r) : "f"(hi_elem), "f"(lo_elem));
    return r;
}
__device__ __forceinline__ float bf16lo_f(uint32_t v) { return __uint_as_float(v << 16); }
__device__ __forceinline__ float bf16hi_f(uint32_t v) { return __uint_as_float(v & 0xFFFF0000u); }
__device__ __forceinline__ void split_pair(float x, float y, uint32_t& h, uint32_t& l) {
    h = cvt2_bf16(x, y);
    float rx = x - bf16lo_f(h);
    float ry = y - bf16hi_f(h);
    l = cvt2_bf16(rx, ry);
}
__device__ __forceinline__ void split4(float4 v, uint2& hw, uint2& lw) {
    uint32_t h0, l0, h1, l1;
    split_pair(v.x, v.y, h0, l0);
    split_pair(v.z, v.w, h1, l1);
    hw.x = h0; hw.y = h1; lw.x = l0; lw.y = l1;
}
__device__ __forceinline__ float ex2f(float x) {
    float y;
    asm("ex2.approx.f32 %0, %1;" : "=f"(y) : "f"(x));
    return y;
}
#define CP16(dst, src) \
    asm volatile("cp.async.cg.shared.global [%0], [%1], 16;" :: "r"(dst), "l"(src))
#define CP_COMMIT() asm volatile("cp.async.commit_group;")
#define CP_WAIT1()  asm volatile("cp.async.wait_group 1;")
#define CP_WAIT0()  asm volatile("cp.async.wait_group 0;")

// ---------------------------------------------------------------------------
// Convert fp32 -> split bf16 planes; z==6 detects mask dtype.
// ---------------------------------------------------------------------------
struct ConvArgs { const float* src[6]; };

__global__ __launch_bounds__(256) void convert_kernel(ConvArgs a,
                                                      const unsigned int* mask) {
    const int z = blockIdx.z;
    const int tid = threadIdx.x;
    if (z == 6) {
        if (blockIdx.x != 0) return;
        int ok_i32 = 1, ok_u8 = 1;
        for (int i = tid; i < 4096; i += 256) {
            unsigned w = mask[i];
            ok_i32 &= (w <= 1u);
            ok_u8  &= ((w & 0xFEFEFEFEu) == 0u);
        }
        ok_i32 = __syncthreads_and(ok_i32);
        ok_u8  = __syncthreads_and(ok_u8);
        if (tid == 0) g_mask_mode = ok_i32 ? 0 : (ok_u8 ? 1 : 2);
        return;
    }
    const float4* src = (const float4*)a.src[z];
    int nf8;
    unsigned short *dh, *dl;
    if (z < 3) { nf8 = XSEG / 8; dh = g_xh + (size_t)z * XSEG; dl = g_xl + (size_t)z * XSEG; }
    else       { nf8 = WSEG / 8; dh = g_wh + (size_t)(z - 3) * WSEG; dl = g_wl + (size_t)(z - 3) * WSEG; }
    for (int i = blockIdx.x * 256 + tid; i < nf8; i += 1024 * 256) {
        float4 v0 = src[2 * i];
        float4 v1 = src[2 * i + 1];
        uint2 h0, l0, h1, l1;
        split4(v0, h0, l0);
        split4(v1, h1, l1);
        uint4 hv, lv;
        hv.x = h0.x; hv.y = h0.y; hv.z = h1.x; hv.w = h1.y;
        lv.x = l0.x; lv.y = l0.y; lv.z = l1.x; lv.w = l1.y;
        ((uint4*)dh)[i] = hv;
        ((uint4*)dl)[i] = lv;
    }
}

// ---------------------------------------------------------------------------
// Mask -> bf16 additive bias plane.
// ---------------------------------------------------------------------------
__global__ __launch_bounds__(256) void mask_conv_kernel(const void* mask) {
    const int mode = g_mask_mode;
    __nv_bfloat16 nb = __float2bfloat16(NEGINF);
    const uint32_t neg = (uint32_t)*(unsigned short*)&nb;
    const int n8 = (int)(((size_t)B_ * S_ * S_) / 8);
    for (int i = blockIdx.x * 256 + threadIdx.x; i < n8; i += gridDim.x * 256) {
        unsigned m[8];
        if (mode == 0) {
            int4 a = ((const int4*)mask)[2 * i];
            int4 b = ((const int4*)mask)[2 * i + 1];
            m[0] = a.x != 0; m[1] = a.y != 0; m[2] = a.z != 0; m[3] = a.w != 0;
            m[4] = b.x != 0; m[5] = b.y != 0; m[6] = b.z != 0; m[7] = b.w != 0;
        } else if (mode == 1) {
            uint2 a = ((const uint2*)mask)[i];
#pragma unroll
            for (int j = 0; j < 4; ++j) m[j] = (a.x >> (8 * j)) & 255u;
#pragma unroll
            for (int j = 0; j < 4; ++j) m[4 + j] = (a.y >> (8 * j)) & 255u;
        } else {
            float4 a = ((const float4*)mask)[2 * i];
            float4 b = ((const float4*)mask)[2 * i + 1];
            m[0] = a.x != 0.f; m[1] = a.y != 0.f; m[2] = a.z != 0.f; m[3] = a.w != 0.f;
            m[4] = b.x != 0.f; m[5] = b.y != 0.f; m[6] = b.z != 0.f; m[7] = b.w != 0.f;
        }
        uint4 o;
        o.x = (m[0] ? neg : 0u) | ((m[1] ? neg : 0u) << 16);
        o.y = (m[2] ? neg : 0u) | ((m[3] ? neg : 0u) << 16);
        o.z = (m[4] ? neg : 0u) | ((m[5] ? neg : 0u) << 16);
        o.w = (m[6] ? neg : 0u) | ((m[7] ? neg : 0u) << 16);
        ((uint4*)g_mb)[i] = o;
    }
}

// ---------------------------------------------------------------------------
// Projection GEMM (bf16 3-term, unchanged math). Epilogue emits fp16 planes:
// z==0 (Q): fp16 hi + fp16 residual; z==1 (K), z==2 (V): single fp16.
// ---------------------------------------------------------------------------
#define PSTG 49152u
#define PROJ_SMEM (3u * PSTG)

struct ProjArgs { const float* bias[3]; float scale[3]; };

__device__ __forceinline__ void proj_issue(
    uint32_t sb, int st, int kt, int tid, int m0, int n0,
    const unsigned short* Xh, const unsigned short* Xl,
    const unsigned short* Wh, const unsigned short* Wl)
{
    const uint32_t stage = sb + (uint32_t)st * PSTG;
    {
        int row = tid >> 2, c = tid & 3;
        uint32_t doff = (uint32_t)row * 64u + (uint32_t)((c ^ ((row >> 1) & 3)) << 4);
        CP16(stage + doff,          Xh + (size_t)(m0 + row) * DM + kt * 32 + c * 8);
        CP16(stage + 8192u + doff,  Xl + (size_t)(m0 + row) * DM + kt * 32 + c * 8);
    }
#pragma unroll
    for (int j = 0; j < 2; ++j) {
        int line = tid + 512 * j;
        int row = line >> 2, c = line & 3;
        uint32_t doff = (uint32_t)row * 64u + (uint32_t)((c ^ ((row >> 1) & 3)) << 4);
        CP16(stage + 16384u + doff, Wh + (size_t)(n0 + row) * DM + kt * 32 + c * 8);
        CP16(stage + 32768u + doff, Wl + (size_t)(n0 + row) * DM + kt * 32 + c * 8);
    }
    CP_COMMIT();
}

__global__ __launch_bounds__(512) void proj_mma_kernel(ProjArgs args) {
    extern __shared__ char ps[];
    const uint32_t sb = smem_u32(ps);
    const int z = blockIdx.z;
    const unsigned short* __restrict__ Xh = g_xh + (size_t)z * XSEG;
    const unsigned short* __restrict__ Xl = g_xl + (size_t)z * XSEG;
    const unsigned short* __restrict__ Wh = g_wh + (size_t)z * WSEG;
    const unsigned short* __restrict__ Wl = g_wl + (size_t)z * WSEG;
    const float* __restrict__ bias = args.bias[z];
    const float scale = args.scale[z];

    const int tid = threadIdx.x, lane = tid & 31, wid = tid >> 5;
    const int wm = wid & 3, wn = wid >> 2;
    const int m0 = blockIdx.y * 128, n0 = blockIdx.x * 256;
    const int flr = lane & 15, flc = lane >> 4;

    float C[2][8][4];
#pragma unroll
    for (int i = 0; i < 2; ++i)
#pragma unroll
        for (int j = 0; j < 8; ++j)
#pragma unroll
            for (int k = 0; k < 4; ++k) C[i][j][k] = 0.f;

    proj_issue(sb, 0, 0, tid, m0, n0, Xh, Xl, Wh, Wl);
    proj_issue(sb, 1, 1, tid, m0, n0, Xh, Xl, Wh, Wl);

    for (int kt = 0; kt < 32; ++kt) {
        if (kt < 31) CP_WAIT1(); else CP_WAIT0();
        __syncthreads();
        if (kt + 2 < 32)
            proj_issue(sb, (kt + 2) % 3, kt + 2, tid, m0, n0, Xh, Xl, Wh, Wl);

        const uint32_t base = sb + (uint32_t)(kt % 3) * PSTG;
#pragma unroll
        for (int ks = 0; ks < 2; ++ks) {
            const uint32_t csw = (uint32_t)(((2 * ks + flc) ^ ((flr >> 1) & 3)) << 4);
            uint32_t a_h[2][4], a_l[2][4];
#pragma unroll
            for (int mt = 0; mt < 2; ++mt) {
                uint32_t off = (uint32_t)((32 * wm + 16 * mt + flr) * 64) + csw;
                ldsm4(base + off, a_h[mt]);
                ldsm4(base + 8192u + off, a_l[mt]);
            }
#pragma unroll
            for (int ntp = 0; ntp < 4; ++ntp) {
                uint32_t boff = (uint32_t)((64 * wn + 16 * ntp + flr) * 64) + csw;
                uint32_t bh4[4], bl4[4];
                ldsm4(base + 16384u + boff, bh4);
                ldsm4(base + 32768u + boff, bl4);
                mma16816(C[0][2 * ntp],     a_h[0], bh4[0], bh4[2]);
                mma16816(C[1][2 * ntp],     a_h[1], bh4[0], bh4[2]);
                mma16816(C[0][2 * ntp + 1], a_h[0], bh4[1], bh4[3]);
                mma16816(C[1][2 * ntp + 1], a_h[1], bh4[1], bh4[3]);

                mma16816(C[0][2 * ntp],     a_h[0], bl4[0], bl4[2]);
                mma16816(C[1][2 * ntp],     a_h[1], bl4[0], bl4[2]);
                mma16816(C[0][2 * ntp + 1], a_h[0], bl4[1], bl4[3]);
                mma16816(C[1][2 * ntp + 1], a_h[1], bl4[1], bl4[3]);

                mma16816(C[0][2 * ntp],     a_l[0], bh4[0], bh4[2]);
                mma16816(C[1][2 * ntp],     a_l[1], bh4[0], bh4[2]);
                mma16816(C[0][2 * ntp + 1], a_l[0], bh4[1], bh4[3]);
                mma16816(C[1][2 * ntp + 1], a_l[1], bh4[1], bh4[3]);
            }
        }
    }

    // epilogue: bias + scale -> fp16 planes
#pragma unroll
    for (int nt = 0; nt < 8; ++nt) {
        int n = n0 + 64 * wn + 8 * nt + 2 * (lane & 3);
        int h = n >> 6, d = n & 63;
        float2 bv = *(const float2*)(bias + n);
#pragma unroll
        for (int mt = 0; mt < 2; ++mt) {
            int mbase = m0 + 32 * wm + 16 * mt + (lane >> 2);
#pragma unroll
            for (int half = 0; half < 2; ++half) {
                int m = mbase + 8 * half;
                int b = m >> 11, s = m & (S_ - 1);
                float vx = (C[mt][nt][2 * half + 0] + bv.x) * scale;
                float vy = (C[mt][nt][2 * half + 1] + bv.y) * scale;
                size_t off = ((size_t)(b * H_ + h) * S_ + s) * DH + d;
                if (z == 0) {
                    __half hx = __float2half_rn(vx), hy = __float2half_rn(vy);
                    float rx = vx - __half2float(hx);
                    float ry = vy - __half2float(hy);
                    uint32_t hw = ((uint32_t)__half_as_ushort(hy) << 16) | __half_as_ushort(hx);
                    *(uint32_t*)(g_qh + off) = hw;
                    *(uint32_t*)(g_ql + off) = cvt2_f16(rx, ry);
                } else {
                    uint32_t hw = cvt2_f16(vx, vy);
                    unsigned short* dst = (z == 1) ? g_kh : g_vh;
                    *(uint32_t*)(dst + off) = hw;
                }
            }
        }
    }
}

// ---------------------------------------------------------------------------
// Flash attention: fp16 path. Q = 2-term fp16 (hi + residual), K/V single
// fp16. QK = 2 MMAs per tile-pair, PV = 1. 512 threads, 16 warps x 16 q-rows.
// Stage (16KB): Kh@0 | Vh@8K. 3 stages = 48K. Q: Qh@49152, Ql@81920. 112K.
// ---------------------------------------------------------------------------
#define ASTG 16384u
#define AQOFF 49152u
#define ATTN_SMEM 114688u

__device__ __forceinline__ void attn_issue_kv(uint32_t sb, int st, int kt,
                                              int tid, size_t bhS) {
#pragma unroll
    for (int j = 0; j < 2; ++j) {
        int cid = tid + 512 * j;
        int sub = cid >> 9, w = cid & 511, row = w >> 3, c = w & 7;
        const unsigned short* plane = sub ? g_vh : g_kh;
        const void* src = plane + (bhS + (size_t)(kt * 64 + row)) * DH + c * 8;
        uint32_t dst = sb + (uint32_t)st * ASTG + (uint32_t)sub * 8192u
                     + (uint32_t)row * 128u + (uint32_t)((c ^ (row & 7)) << 4);
        CP16(dst, src);
    }
    CP_COMMIT();
}

__global__ __launch_bounds__(512) void attn_mma_kernel(float* __restrict__ out)
{
    extern __shared__ char as_[];
    const uint32_t sb = smem_u32(as_);

    const int tid = threadIdx.x, lane = tid & 31, wid = tid >> 5;
    const int bz = blockIdx.z, h = blockIdx.y;
    const int q0 = blockIdx.x * 256;
    const size_t bhS = (size_t)(bz * H_ + h) * S_;

    const int flr = lane & 15, flc = lane >> 4;
    const int r_in = lane >> 2;
    const int c_in = 2 * (lane & 3);

    // prologue: Q planes + first two K/V tiles
    {
#pragma unroll
        for (int j = 0; j < 8; ++j) {
            int cid = tid + 512 * j;
            int sub = cid >> 11, w = cid & 2047, row = w >> 3, c = w & 7;
            const unsigned short* plane = sub ? g_ql : g_qh;
            const void* src = plane + (bhS + (size_t)(q0 + row)) * DH + c * 8;
            uint32_t dst = sb + AQOFF + (uint32_t)sub * 32768u
                         + (uint32_t)row * 128u + (uint32_t)((c ^ (row & 7)) << 4);
            CP16(dst, src);
        }
    }
    attn_issue_kv(sb, 0, 0, tid, bhS);
    attn_issue_kv(sb, 1, 1, tid, bhS);

    float oC[8][4];
#pragma unroll
    for (int j = 0; j < 8; ++j)
#pragma unroll
        for (int k = 0; k < 4; ++k) oC[j][k] = 0.f;
    float mi0 = NEGINF, mi1 = NEGINF, li0 = 0.f, li1 = 0.f;

    const int rowA0 = q0 + 16 * wid + r_in;
    const unsigned short* mb = g_mb + (size_t)bz * S_ * S_;
    const uint32_t qbase = sb + AQOFF;
    const int qrow = 16 * wid + flr;

    for (int kt = 0; kt < 32; ++kt) {
        if (kt < 31) CP_WAIT1(); else CP_WAIT0();
        __syncthreads();
        if (kt + 2 < 32) attn_issue_kv(sb, (kt + 2) % 3, kt + 2, tid, bhS);

        const uint32_t base = sb + (uint32_t)(kt % 3) * ASTG;

        // S accumulators initialized with mask bias
        float sC[8][4];
#pragma unroll
        for (int nt = 0; nt < 8; ++nt) {
            size_t rA = (size_t)rowA0 * S_ + kt * 64 + 8 * nt + c_in;
            uint32_t bA = *(const uint32_t*)(mb + rA);
            uint32_t bB = *(const uint32_t*)(mb + rA + 8 * (size_t)S_);
            sC[nt][0] = bf16lo_f(bA); sC[nt][1] = bf16hi_f(bA);
            sC[nt][2] = bf16lo_f(bB); sC[nt][3] = bf16hi_f(bB);
        }

        // -- S += Q K^T : (Qh + Ql) x Kh, term-major --
#pragma unroll
        for (int ks = 0; ks < 4; ++ks) {
            uint32_t qoff = (uint32_t)(qrow * 128)
                          + (uint32_t)(((2 * ks + flc) ^ (qrow & 7)) << 4);
            uint32_t qh4[4], ql4[4];
            ldsm4(qbase + qoff, qh4);
            ldsm4(qbase + 32768u + qoff, ql4);
            uint32_t kh4[4][4];
#pragma unroll
            for (int ntp = 0; ntp < 4; ++ntp) {
                uint32_t koff = (uint32_t)((16 * ntp + flr) * 128)
                              + (uint32_t)(((2 * ks + flc) ^ (flr & 7)) << 4);
                ldsm4(base + koff, kh4[ntp]);
            }
#pragma unroll
            for (int ntp = 0; ntp < 4; ++ntp) {
                mma16816f(sC[2 * ntp],     qh4, kh4[ntp][0], kh4[ntp][2]);
                mma16816f(sC[2 * ntp + 1], qh4, kh4[ntp][1], kh4[ntp][3]);
            }
#pragma unroll
            for (int ntp = 0; ntp < 4; ++ntp) {
                mma16816f(sC[2 * ntp],     ql4, kh4[ntp][0], kh4[ntp][2]);
                mma16816f(sC[2 * ntp + 1], ql4, kh4[ntp][1], kh4[ntp][3]);
            }
        }

        // -- online softmax (log2 domain) --
        float mx0 = NEGINF, mx1 = NEGINF;
#pragma unroll
        for (int nt = 0; nt < 8; ++nt) {
            mx0 = fmaxf(mx0, fmaxf(sC[nt][0], sC[nt][1]));
            mx1 = fmaxf(mx1, fmaxf(sC[nt][2], sC[nt][3]));
        }
        mx0 = fmaxf(mx0, __shfl_xor_sync(0xffffffffu, mx0, 1));
        mx0 = fmaxf(mx0, __shfl_xor_sync(0xffffffffu, mx0, 2));
        mx1 = fmaxf(mx1, __shfl_xor_sync(0xffffffffu, mx1, 1));
        mx1 = fmaxf(mx1, __shfl_xor_sync(0xffffffffu, mx1, 2));

        float mn0 = fmaxf(mi0, mx0), mn1 = fmaxf(mi1, mx1);
        float f0 = ex2f(mi0 - mn0), f1 = ex2f(mi1 - mn1);
        float sum0 = 0.f, sum1 = 0.f;
#pragma unroll
        for (int nt = 0; nt < 8; ++nt) {
            sC[nt][0] = ex2f(sC[nt][0] - mn0);
            sC[nt][1] = ex2f(sC[nt][1] - mn0);
            sC[nt][2] = ex2f(sC[nt][2] - mn1);
            sC[nt][3] = ex2f(sC[nt][3] - mn1);
            sum0 += sC[nt][0] + sC[nt][1];
            sum1 += sC[nt][2] + sC[nt][3];
        }
        sum0 += __shfl_xor_sync(0xffffffffu, sum0, 1);
        sum0 += __shfl_xor_sync(0xffffffffu, sum0, 2);
        sum1 += __shfl_xor_sync(0xffffffffu, sum1, 1);
        sum1 += __shfl_xor_sync(0xffffffffu, sum1, 2);
        li0 = li0 * f0 + sum0;
        li1 = li1 * f1 + sum1;
        mi0 = mn0; mi1 = mn1;
#pragma unroll
        for (int nt = 0; nt < 8; ++nt) {
            oC[nt][0] *= f0; oC[nt][1] *= f0;
            oC[nt][2] *= f1; oC[nt][3] *= f1;
        }

        // -- O += P V : single fp16 P x single fp16 V --
#pragma unroll
        for (int kp = 0; kp < 4; ++kp) {
            uint32_t pa[4];
            pa[0] = cvt2_f16(sC[2 * kp][0],     sC[2 * kp][1]);
            pa[1] = cvt2_f16(sC[2 * kp][2],     sC[2 * kp][3]);
            pa[2] = cvt2_f16(sC[2 * kp + 1][0], sC[2 * kp + 1][1]);
            pa[3] = cvt2_f16(sC[2 * kp + 1][2], sC[2 * kp + 1][3]);

            const int trow = kp * 16 + ((lane >> 3) & 1) * 8 + (lane & 7);
            const int cb = lane >> 4;
            uint32_t vh4[4][4];
#pragma unroll
            for (int ntp = 0; ntp < 4; ++ntp) {
                uint32_t voff = (uint32_t)(trow * 128)
                              + (uint32_t)(((2 * ntp + cb) ^ (trow & 7)) << 4);
                ldsm4t(base + 8192u + voff, vh4[ntp]);
            }
#pragma unroll
            for (int ntp = 0; ntp < 4; ++ntp) {
                mma16816f(oC[2 * ntp],     pa, vh4[ntp][0], vh4[ntp][1]);
                mma16816f(oC[2 * ntp + 1], pa, vh4[ntp][2], vh4[ntp][3]);
            }
        }
    }

    // ---- epilogue ----
    float inv0 = (li0 > 0.f) ? 1.0f / li0 : 0.f;
    float inv1 = (li1 > 0.f) ? 1.0f / li1 : 0.f;
    const int qr = rowA0;
    const int d0 = h * DH + c_in;
#pragma unroll
    for (int nt = 0; nt < 8; ++nt) {
        float2 v0, v1;
        v0.x = oC[nt][0] * inv0; v0.y = oC[nt][1] * inv0;
        v1.x = oC[nt][2] * inv1; v1.y = oC[nt][3] * inv1;
        *(float2*)(out + (size_t)(bz * S_ + qr) * DM + d0 + 8 * nt) = v0;
        *(float2*)(out + (size_t)(bz * S_ + qr + 8) * DM + d0 + 8 * nt) = v1;
    }
}

// ---------------------------------------------------------------------------
extern "C" void kernel_launch(void* const* d_in, const int* in_sizes, int n_in,
                              void* d_out, int out_size) {
    const void* mask = d_in[3];
    float* out = (float*)d_out;

    static int attr_done = 0;
    if (!attr_done) {
        cudaFuncSetAttribute(proj_mma_kernel,
                             cudaFuncAttributeMaxDynamicSharedMemorySize, PROJ_SMEM);
        cudaFuncSetAttribute(attn_mma_kernel,
                             cudaFuncAttributeMaxDynamicSharedMemorySize, ATTN_SMEM);
        attr_done = 1;
    }

    ConvArgs ca;
    ca.src[0] = (const float*)d_in[0];
    ca.src[1] = (const float*)d_in[1];
    ca.src[2] = (const float*)d_in[2];
    ca.src[3] = (const float*)d_in[4];
    ca.src[4] = (const float*)d_in[6];
    ca.src[5] = (const float*)d_in[8];
    convert_kernel<<<dim3(1024, 1, 7), 256>>>(ca, (const unsigned int*)mask);

    mask_conv_kernel<<<1024, 256>>>(mask);

    ProjArgs pa;
    pa.bias[0] = (const float*)d_in[5];
    pa.bias[1] = (const float*)d_in[7];
    pa.bias[2] = (const float*)d_in[9];
    pa.scale[0] = QSCALE; pa.scale[1] = 1.0f; pa.scale[2] = 1.0f;
    proj_mma_kernel<<<dim3(4, 32, 3), 512, PROJ_SMEM>>>(pa);

    attn_mma_kernel<<<dim3(8, 16, 2), 512, ATTN_SMEM>>>(out);
}

// round 11
// speedup vs baseline: 4.8870x; 1.5023x over previous
#include <cuda_runtime.h>
#include <cuda_bf16.h>
#include <cuda_fp16.h>
#include <cstdint>
#include <cstddef>

#define B_  2
#define S_  2048
#define DM  1024
#define H_  16
#define DH  64
#define M_  (B_*S_)   // 4096
#define NEGINF -1e30f
#define QSCALE (0.125f * 1.44269504088896f)

#define XSEG (M_*DM)
#define WSEG (DM*DM)
#define QKV  (B_*H_*S_*DH)

__device__ unsigned short g_xh[3*XSEG];                 // X: single fp16
__device__ unsigned short g_wh[3*WSEG];                 // W: single fp16
__device__ unsigned short g_qh[QKV];                    // Q: single fp16 (scaled)
__device__ unsigned short g_kh[QKV];                    // K: single fp16
__device__ unsigned short g_vh[QKV];                    // V: single fp16
__device__ unsigned short g_mb[(size_t)B_*S_*S_];       // mask bias (0 / bf16(-1e30))
__device__ int g_mask_mode;

// ---------------------------------------------------------------------------
__device__ __forceinline__ uint32_t smem_u32(const void* p) {
    uint32_t a;
    asm("{ .reg .u64 t; cvta.to.shared.u64 t, %1; cvt.u32.u64 %0, t; }"
        : "=r"(a) : "l"(p));
    return a;
}
__device__ __forceinline__ void ldsm4(uint32_t addr, uint32_t* r) {
    asm volatile("ldmatrix.sync.aligned.m8n8.x4.shared.b16 {%0,%1,%2,%3}, [%4];"
        : "=r"(r[0]), "=r"(r[1]), "=r"(r[2]), "=r"(r[3]) : "r"(addr));
}
__device__ __forceinline__ void ldsm4t(uint32_t addr, uint32_t* r) {
    asm volatile("ldmatrix.sync.aligned.m8n8.x4.trans.shared.b16 {%0,%1,%2,%3}, [%4];"
        : "=r"(r[0]), "=r"(r[1]), "=r"(r[2]), "=r"(r[3]) : "r"(addr));
}
// fp16 mma
__device__ __forceinline__ void mma16816f(float* c, const uint32_t* a,
                                          uint32_t b0, uint32_t b1) {
    asm volatile(
        "mma.sync.aligned.m16n8k16.row.col.f32.f16.f16.f32 "
        "{%0,%1,%2,%3}, {%4,%5,%6,%7}, {%8,%9}, {%0,%1,%2,%3};"
        : "+f"(c[0]), "+f"(c[1]), "+f"(c[2]), "+f"(c[3])
        : "r"(a[0]), "r"(a[1]), "r"(a[2]), "r"(a[3]), "r"(b0), "r"(b1));
}
__device__ __forceinline__ uint32_t cvt2_f16(float lo_elem, float hi_elem) {
    uint32_t r;
    asm("cvt.rn.f16x2.f32 %0, %1, %2;" : "=r"(r) : "f"(hi_elem), "f"(lo_elem));
    return r;
}
__device__ __forceinline__ float bf16lo_f(uint32_t v) { return __uint_as_float(v << 16); }
__device__ __forceinline__ float bf16hi_f(uint32_t v) { return __uint_as_float(v & 0xFFFF0000u); }
__device__ __forceinline__ float ex2f(float x) {
    float y;
    asm("ex2.approx.f32 %0, %1;" : "=f"(y) : "f"(x));
    return y;
}
#define CP16(dst, src) \
    asm volatile("cp.async.cg.shared.global [%0], [%1], 16;" :: "r"(dst), "l"(src))
#define CP_COMMIT() asm volatile("cp.async.commit_group;")
#define CP_WAIT1()  asm volatile("cp.async.wait_group 1;")
#define CP_WAIT0()  asm volatile("cp.async.wait_group 0;")

// ---------------------------------------------------------------------------
// Convert fp32 -> single fp16 planes; z==6 detects mask dtype.
// ---------------------------------------------------------------------------
struct ConvArgs { const float* src[6]; };

__global__ __launch_bounds__(256) void convert_kernel(ConvArgs a,
                                                      const unsigned int* mask) {
    const int z = blockIdx.z;
    const int tid = threadIdx.x;
    if (z == 6) {
        if (blockIdx.x != 0) return;
        int ok_i32 = 1, ok_u8 = 1;
        for (int i = tid; i < 4096; i += 256) {
            unsigned w = mask[i];
            ok_i32 &= (w <= 1u);
            ok_u8  &= ((w & 0xFEFEFEFEu) == 0u);
        }
        ok_i32 = __syncthreads_and(ok_i32);
        ok_u8  = __syncthreads_and(ok_u8);
        if (tid == 0) g_mask_mode = ok_i32 ? 0 : (ok_u8 ? 1 : 2);
        return;
    }
    const float4* src = (const float4*)a.src[z];
    int nf8;
    unsigned short* dh;
    if (z < 3) { nf8 = XSEG / 8; dh = g_xh + (size_t)z * XSEG; }
    else       { nf8 = WSEG / 8; dh = g_wh + (size_t)(z - 3) * WSEG; }
    for (int i = blockIdx.x * 256 + tid; i < nf8; i += 1024 * 256) {
        float4 v0 = src[2 * i];
        float4 v1 = src[2 * i + 1];
        uint4 hv;
        hv.x = cvt2_f16(v0.x, v0.y);
        hv.y = cvt2_f16(v0.z, v0.w);
        hv.z = cvt2_f16(v1.x, v1.y);
        hv.w = cvt2_f16(v1.z, v1.w);
        ((uint4*)dh)[i] = hv;
    }
}

// ---------------------------------------------------------------------------
// Mask -> bf16 additive bias plane.
// ---------------------------------------------------------------------------
__global__ __launch_bounds__(256) void mask_conv_kernel(const void* mask) {
    const int mode = g_mask_mode;
    __nv_bfloat16 nb = __float2bfloat16(NEGINF);
    const uint32_t neg = (uint32_t)*(unsigned short*)&nb;
    const int n8 = (int)(((size_t)B_ * S_ * S_) / 8);
    for (int i = blockIdx.x * 256 + threadIdx.x; i < n8; i += gridDim.x * 256) {
        unsigned m[8];
        if (mode == 0) {
            int4 a = ((const int4*)mask)[2 * i];
            int4 b = ((const int4*)mask)[2 * i + 1];
            m[0] = a.x != 0; m[1] = a.y != 0; m[2] = a.z != 0; m[3] = a.w != 0;
            m[4] = b.x != 0; m[5] = b.y != 0; m[6] = b.z != 0; m[7] = b.w != 0;
        } else if (mode == 1) {
            uint2 a = ((const uint2*)mask)[i];
#pragma unroll
            for (int j = 0; j < 4; ++j) m[j] = (a.x >> (8 * j)) & 255u;
#pragma unroll
            for (int j = 0; j < 4; ++j) m[4 + j] = (a.y >> (8 * j)) & 255u;
        } else {
            float4 a = ((const float4*)mask)[2 * i];
            float4 b = ((const float4*)mask)[2 * i + 1];
            m[0] = a.x != 0.f; m[1] = a.y != 0.f; m[2] = a.z != 0.f; m[3] = a.w != 0.f;
            m[4] = b.x != 0.f; m[5] = b.y != 0.f; m[6] = b.z != 0.f; m[7] = b.w != 0.f;
        }
        uint4 o;
        o.x = (m[0] ? neg : 0u) | ((m[1] ? neg : 0u) << 16);
        o.y = (m[2] ? neg : 0u) | ((m[3] ? neg : 0u) << 16);
        o.z = (m[4] ? neg : 0u) | ((m[5] ? neg : 0u) << 16);
        o.w = (m[6] ? neg : 0u) | ((m[7] ? neg : 0u) << 16);
        ((uint4*)g_mb)[i] = o;
    }
}

// ---------------------------------------------------------------------------
// Projection GEMM: single fp16 x single fp16, fp32 accumulate.
// BM=128, BN=256, BK=32, 512 threads (16 warps, 4m x 4n, 32x64 warp tiles),
// 3-stage cp.async. Stage (24KB): X@0 (8K) | W@8K (16K). 64B rows, swizzled.
// ---------------------------------------------------------------------------
#define PSTG 24576u
#define PROJ_SMEM (3u * PSTG)   // 73728

struct ProjArgs { const float* bias[3]; float scale[3]; };

__device__ __forceinline__ void proj_issue(
    uint32_t sb, int st, int kt, int tid, int m0, int n0,
    const unsigned short* Xh, const unsigned short* Wh)
{
    const uint32_t stage = sb + (uint32_t)st * PSTG;
    {   // X: 512 lines, one per thread
        int row = tid >> 2, c = tid & 3;
        uint32_t doff = (uint32_t)row * 64u + (uint32_t)((c ^ ((row >> 1) & 3)) << 4);
        CP16(stage + doff, Xh + (size_t)(m0 + row) * DM + kt * 32 + c * 8);
    }
#pragma unroll
    for (int j = 0; j < 2; ++j) {   // W: 1024 lines
        int line = tid + 512 * j;
        int row = line >> 2, c = line & 3;
        uint32_t doff = (uint32_t)row * 64u + (uint32_t)((c ^ ((row >> 1) & 3)) << 4);
        CP16(stage + 8192u + doff, Wh + (size_t)(n0 + row) * DM + kt * 32 + c * 8);
    }
    CP_COMMIT();
}

__global__ __launch_bounds__(512) void proj_mma_kernel(ProjArgs args) {
    extern __shared__ char ps[];
    const uint32_t sb = smem_u32(ps);
    const int z = blockIdx.z;
    const unsigned short* __restrict__ Xh = g_xh + (size_t)z * XSEG;
    const unsigned short* __restrict__ Wh = g_wh + (size_t)z * WSEG;
    const float* __restrict__ bias = args.bias[z];
    const float scale = args.scale[z];
    unsigned short* __restrict__ dst = (z == 0) ? g_qh : (z == 1) ? g_kh : g_vh;

    const int tid = threadIdx.x, lane = tid & 31, wid = tid >> 5;
    const int wm = wid & 3, wn = wid >> 2;
    const int m0 = blockIdx.y * 128, n0 = blockIdx.x * 256;
    const int flr = lane & 15, flc = lane >> 4;

    float C[2][8][4];
#pragma unroll
    for (int i = 0; i < 2; ++i)
#pragma unroll
        for (int j = 0; j < 8; ++j)
#pragma unroll
            for (int k = 0; k < 4; ++k) C[i][j][k] = 0.f;

    proj_issue(sb, 0, 0, tid, m0, n0, Xh, Wh);
    proj_issue(sb, 1, 1, tid, m0, n0, Xh, Wh);

    for (int kt = 0; kt < 32; ++kt) {
        if (kt < 31) CP_WAIT1(); else CP_WAIT0();
        __syncthreads();
        if (kt + 2 < 32)
            proj_issue(sb, (kt + 2) % 3, kt + 2, tid, m0, n0, Xh, Wh);

        const uint32_t base = sb + (uint32_t)(kt % 3) * PSTG;
#pragma unroll
        for (int ks = 0; ks < 2; ++ks) {
            const uint32_t csw = (uint32_t)(((2 * ks + flc) ^ ((flr >> 1) & 3)) << 4);
            uint32_t a4[2][4];
#pragma unroll
            for (int mt = 0; mt < 2; ++mt) {
                uint32_t off = (uint32_t)((32 * wm + 16 * mt + flr) * 64) + csw;
                ldsm4(base + off, a4[mt]);
            }
#pragma unroll
            for (int ntp = 0; ntp < 4; ++ntp) {
                uint32_t boff = (uint32_t)((64 * wn + 16 * ntp + flr) * 64) + csw;
                uint32_t b4[4];
                ldsm4(base + 8192u + boff, b4);
                mma16816f(C[0][2 * ntp],     a4[0], b4[0], b4[2]);
                mma16816f(C[1][2 * ntp],     a4[1], b4[0], b4[2]);
                mma16816f(C[0][2 * ntp + 1], a4[0], b4[1], b4[3]);
                mma16816f(C[1][2 * ntp + 1], a4[1], b4[1], b4[3]);
            }
        }
    }

    // epilogue: bias + scale -> single fp16, head-split
#pragma unroll
    for (int nt = 0; nt < 8; ++nt) {
        int n = n0 + 64 * wn + 8 * nt + 2 * (lane & 3);
        int h = n >> 6, d = n & 63;
        float2 bv = *(const float2*)(bias + n);
#pragma unroll
        for (int mt = 0; mt < 2; ++mt) {
            int mbase = m0 + 32 * wm + 16 * mt + (lane >> 2);
#pragma unroll
            for (int half = 0; half < 2; ++half) {
                int m = mbase + 8 * half;
                int b = m >> 11, s = m & (S_ - 1);
                float vx = (C[mt][nt][2 * half + 0] + bv.x) * scale;
                float vy = (C[mt][nt][2 * half + 1] + bv.y) * scale;
                size_t off = ((size_t)(b * H_ + h) * S_ + s) * DH + d;
                *(uint32_t*)(dst + off) = cvt2_f16(vx, vy);
            }
        }
    }
}

// ---------------------------------------------------------------------------
// Flash attention: all single fp16. QK = 1 MMA, PV = 1 MMA per tile-pair.
// 512 threads, 16 warps x 16 q-rows. Stage (16KB): K@0 | V@8K, 3 stages.
// Q single plane @49152 (32KB). Total 81920.
// ---------------------------------------------------------------------------
#define ASTG 16384u
#define AQOFF 49152u
#define ATTN_SMEM 81920u

__device__ __forceinline__ void attn_issue_kv(uint32_t sb, int st, int kt,
                                              int tid, size_t bhS) {
#pragma unroll
    for (int j = 0; j < 2; ++j) {
        int cid = tid + 512 * j;
        int sub = cid >> 9, w = cid & 511, row = w >> 3, c = w & 7;
        const unsigned short* plane = sub ? g_vh : g_kh;
        const void* src = plane + (bhS + (size_t)(kt * 64 + row)) * DH + c * 8;
        uint32_t dst = sb + (uint32_t)st * ASTG + (uint32_t)sub * 8192u
                     + (uint32_t)row * 128u + (uint32_t)((c ^ (row & 7)) << 4);
        CP16(dst, src);
    }
    CP_COMMIT();
}

__global__ __launch_bounds__(512) void attn_mma_kernel(float* __restrict__ out)
{
    extern __shared__ char as_[];
    const uint32_t sb = smem_u32(as_);

    const int tid = threadIdx.x, lane = tid & 31, wid = tid >> 5;
    const int bz = blockIdx.z, h = blockIdx.y;
    const int q0 = blockIdx.x * 256;
    const size_t bhS = (size_t)(bz * H_ + h) * S_;

    const int flr = lane & 15, flc = lane >> 4;
    const int r_in = lane >> 2;
    const int c_in = 2 * (lane & 3);

    // prologue: Q plane (256 rows) + first two K/V tiles
    {
#pragma unroll
        for (int j = 0; j < 4; ++j) {
            int cid = tid + 512 * j;
            int row = cid >> 3, c = cid & 7;
            const void* src = g_qh + (bhS + (size_t)(q0 + row)) * DH + c * 8;
            uint32_t dst = sb + AQOFF
                         + (uint32_t)row * 128u + (uint32_t)((c ^ (row & 7)) << 4);
            CP16(dst, src);
        }
    }
    attn_issue_kv(sb, 0, 0, tid, bhS);
    attn_issue_kv(sb, 1, 1, tid, bhS);

    float oC[8][4];
#pragma unroll
    for (int j = 0; j < 8; ++j)
#pragma unroll
        for (int k = 0; k < 4; ++k) oC[j][k] = 0.f;
    float mi0 = NEGINF, mi1 = NEGINF, li0 = 0.f, li1 = 0.f;

    const int rowA0 = q0 + 16 * wid + r_in;
    const unsigned short* mb = g_mb + (size_t)bz * S_ * S_;
    const uint32_t qbase = sb + AQOFF;
    const int qrow = 16 * wid + flr;

    for (int kt = 0; kt < 32; ++kt) {
        if (kt < 31) CP_WAIT1(); else CP_WAIT0();
        __syncthreads();
        if (kt + 2 < 32) attn_issue_kv(sb, (kt + 2) % 3, kt + 2, tid, bhS);

        const uint32_t base = sb + (uint32_t)(kt % 3) * ASTG;

        // S accumulators initialized with mask bias
        float sC[8][4];
#pragma unroll
        for (int nt = 0; nt < 8; ++nt) {
            size_t rA = (size_t)rowA0 * S_ + kt * 64 + 8 * nt + c_in;
            uint32_t bA = *(const uint32_t*)(mb + rA);
            uint32_t bB = *(const uint32_t*)(mb + rA + 8 * (size_t)S_);
            sC[nt][0] = bf16lo_f(bA); sC[nt][1] = bf16hi_f(bA);
            sC[nt][2] = bf16lo_f(bB); sC[nt][3] = bf16hi_f(bB);
        }

        // -- S += Q K^T (single term) --
#pragma unroll
        for (int ks = 0; ks < 4; ++ks) {
            uint32_t qoff = (uint32_t)(qrow * 128)
                          + (uint32_t)(((2 * ks + flc) ^ (qrow & 7)) << 4);
            uint32_t q4[4];
            ldsm4(qbase + qoff, q4);
            uint32_t k4[4][4];
#pragma unroll
            for (int ntp = 0; ntp < 4; ++ntp) {
                uint32_t koff = (uint32_t)((16 * ntp + flr) * 128)
                              + (uint32_t)(((2 * ks + flc) ^ (flr & 7)) << 4);
                ldsm4(base + koff, k4[ntp]);
            }
#pragma unroll
            for (int ntp = 0; ntp < 4; ++ntp) {
                mma16816f(sC[2 * ntp],     q4, k4[ntp][0], k4[ntp][2]);
                mma16816f(sC[2 * ntp + 1], q4, k4[ntp][1], k4[ntp][3]);
            }
        }

        // -- online softmax (log2 domain) --
        float mx0 = NEGINF, mx1 = NEGINF;
#pragma unroll
        for (int nt = 0; nt < 8; ++nt) {
            mx0 = fmaxf(mx0, fmaxf(sC[nt][0], sC[nt][1]));
            mx1 = fmaxf(mx1, fmaxf(sC[nt][2], sC[nt][3]));
        }
        mx0 = fmaxf(mx0, __shfl_xor_sync(0xffffffffu, mx0, 1));
        mx0 = fmaxf(mx0, __shfl_xor_sync(0xffffffffu, mx0, 2));
        mx1 = fmaxf(mx1, __shfl_xor_sync(0xffffffffu, mx1, 1));
        mx1 = fmaxf(mx1, __shfl_xor_sync(0xffffffffu, mx1, 2));

        float mn0 = fmaxf(mi0, mx0), mn1 = fmaxf(mi1, mx1);
        float f0 = ex2f(mi0 - mn0), f1 = ex2f(mi1 - mn1);
        float sum0 = 0.f, sum1 = 0.f;
#pragma unroll
        for (int nt = 0; nt < 8; ++nt) {
            sC[nt][0] = ex2f(sC[nt][0] - mn0);
            sC[nt][1] = ex2f(sC[nt][1] - mn0);
            sC[nt][2] = ex2f(sC[nt][2] - mn1);
            sC[nt][3] = ex2f(sC[nt][3] - mn1);
            sum0 += sC[nt][0] + sC[nt][1];
            sum1 += sC[nt][2] + sC[nt][3];
        }
        sum0 += __shfl_xor_sync(0xffffffffu, sum0, 1);
        sum0 += __shfl_xor_sync(0xffffffffu, sum0, 2);
        sum1 += __shfl_xor_sync(0xffffffffu, sum1, 1);
        sum1 += __shfl_xor_sync(0xffffffffu, sum1, 2);
        li0 = li0 * f0 + sum0;
        li1 = li1 * f1 + sum1;
        mi0 = mn0; mi1 = mn1;
#pragma unroll
        for (int nt = 0; nt < 8; ++nt) {
            oC[nt][0] *= f0; oC[nt][1] *= f0;
            oC[nt][2] *= f1; oC[nt][3] *= f1;
        }

        // -- O += P V --
#pragma unroll
        for (int kp = 0; kp < 4; ++kp) {
            uint32_t pa[4];
            pa[0] = cvt2_f16(sC[2 * kp][0],     sC[2 * kp][1]);
            pa[1] = cvt2_f16(sC[2 * kp][2],     sC[2 * kp][3]);
            pa[2] = cvt2_f16(sC[2 * kp + 1][0], sC[2 * kp + 1][1]);
            pa[3] = cvt2_f16(sC[2 * kp + 1][2], sC[2 * kp + 1][3]);

            const int trow = kp * 16 + ((lane >> 3) & 1) * 8 + (lane & 7);
            const int cb = lane >> 4;
            uint32_t v4[4][4];
#pragma unroll
            for (int ntp = 0; ntp < 4; ++ntp) {
                uint32_t voff = (uint32_t)(trow * 128)
                              + (uint32_t)(((2 * ntp + cb) ^ (trow & 7)) << 4);
                ldsm4t(base + 8192u + voff, v4[ntp]);
            }
#pragma unroll
            for (int ntp = 0; ntp < 4; ++ntp) {
                mma16816f(oC[2 * ntp],     pa, v4[ntp][0], v4[ntp][1]);
                mma16816f(oC[2 * ntp + 1], pa, v4[ntp][2], v4[ntp][3]);
            }
        }
    }

    // ---- epilogue ----
    float inv0 = (li0 > 0.f) ? 1.0f / li0 : 0.f;
    float inv1 = (li1 > 0.f) ? 1.0f / li1 : 0.f;
    const int qr = rowA0;
    const int d0 = h * DH + c_in;
#pragma unroll
    for (int nt = 0; nt < 8; ++nt) {
        float2 v0, v1;
        v0.x = oC[nt][0] * inv0; v0.y = oC[nt][1] * inv0;
        v1.x = oC[nt][2] * inv1; v1.y = oC[nt][3] * inv1;
        *(float2*)(out + (size_t)(bz * S_ + qr) * DM + d0 + 8 * nt) = v0;
        *(float2*)(out + (size_t)(bz * S_ + qr + 8) * DM + d0 + 8 * nt) = v1;
    }
}

// ---------------------------------------------------------------------------
extern "C" void kernel_launch(void* const* d_in, const int* in_sizes, int n_in,
                              void* d_out, int out_size) {
    const void* mask = d_in[3];
    float* out = (float*)d_out;

    static int attr_done = 0;
    if (!attr_done) {
        cudaFuncSetAttribute(proj_mma_kernel,
                             cudaFuncAttributeMaxDynamicSharedMemorySize, PROJ_SMEM);
        cudaFuncSetAttribute(attn_mma_kernel,
                             cudaFuncAttributeMaxDynamicSharedMemorySize, ATTN_SMEM);
        attr_done = 1;
    }

    ConvArgs ca;
    ca.src[0] = (const float*)d_in[0];
    ca.src[1] = (const float*)d_in[1];
    ca.src[2] = (const float*)d_in[2];
    ca.src[3] = (const float*)d_in[4];
    ca.src[4] = (const float*)d_in[6];
    ca.src[5] = (const float*)d_in[8];
    convert_kernel<<<dim3(1024, 1, 7), 256>>>(ca, (const unsigned int*)mask);

    mask_conv_kernel<<<1024, 256>>>(mask);

    ProjArgs pa;
    pa.bias[0] = (const float*)d_in[5];
    pa.bias[1] = (const float*)d_in[7];
    pa.bias[2] = (const float*)d_in[9];
    pa.scale[0] = QSCALE; pa.scale[1] = 1.0f; pa.scale[2] = 1.0f;
    proj_mma_kernel<<<dim3(4, 32, 3), 512, PROJ_SMEM>>>(pa);

    attn_mma_kernel<<<dim3(8, 16, 2), 512, ATTN_SMEM>>>(out);
}

// round 12
// speedup vs baseline: 6.0799x; 1.2441x over previous
#include <cuda_runtime.h>
#include <cuda_bf16.h>
#include <cuda_fp16.h>
#include <cstdint>
#include <cstddef>

#define B_  2
#define S_  2048
#define DM  1024
#define H_  16
#define DH  64
#define M_  (B_*S_)   // 4096
#define NEGINF -1e30f
#define QSCALE (0.125f * 1.44269504088896f)

#define XSEG (M_*DM)
#define WSEG (DM*DM)
#define QKV  (B_*H_*S_*DH)

__device__ unsigned short g_xh[3*XSEG];                 // X: single fp16
__device__ unsigned short g_wh[3*WSEG];                 // W: single fp16
__device__ unsigned short g_qh[QKV];                    // Q: single fp16 (scaled)
__device__ unsigned short g_kh[QKV];                    // K: single fp16
__device__ unsigned short g_vh[QKV];                    // V: single fp16
__device__ unsigned short g_mb[(size_t)B_*S_*S_];       // mask bias (0 / bf16(-1e30))
__device__ int g_mask_mode;

// ---------------------------------------------------------------------------
__device__ __forceinline__ uint32_t smem_u32(const void* p) {
    uint32_t a;
    asm("{ .reg .u64 t; cvta.to.shared.u64 t, %1; cvt.u32.u64 %0, t; }"
        : "=r"(a) : "l"(p));
    return a;
}
__device__ __forceinline__ void ldsm4(uint32_t addr, uint32_t* r) {
    asm volatile("ldmatrix.sync.aligned.m8n8.x4.shared.b16 {%0,%1,%2,%3}, [%4];"
        : "=r"(r[0]), "=r"(r[1]), "=r"(r[2]), "=r"(r[3]) : "r"(addr));
}
__device__ __forceinline__ void ldsm4t(uint32_t addr, uint32_t* r) {
    asm volatile("ldmatrix.sync.aligned.m8n8.x4.trans.shared.b16 {%0,%1,%2,%3}, [%4];"
        : "=r"(r[0]), "=r"(r[1]), "=r"(r[2]), "=r"(r[3]) : "r"(addr));
}
__device__ __forceinline__ void mma16816f(float* c, const uint32_t* a,
                                          uint32_t b0, uint32_t b1) {
    asm volatile(
        "mma.sync.aligned.m16n8k16.row.col.f32.f16.f16.f32 "
        "{%0,%1,%2,%3}, {%4,%5,%6,%7}, {%8,%9}, {%0,%1,%2,%3};"
        : "+f"(c[0]), "+f"(c[1]), "+f"(c[2]), "+f"(c[3])
        : "r"(a[0]), "r"(a[1]), "r"(a[2]), "r"(a[3]), "r"(b0), "r"(b1));
}
__device__ __forceinline__ uint32_t cvt2_f16(float lo_elem, float hi_elem) {
    uint32_t r;
    asm("cvt.rn.f16x2.f32 %0, %1, %2;" : "=r"(r) : "f"(hi_elem), "f"(lo_elem));
    return r;
}
__device__ __forceinline__ float bf16lo_f(uint32_t v) { return __uint_as_float(v << 16); }
__device__ __forceinline__ float bf16hi_f(uint32_t v) { return __uint_as_float(v & 0xFFFF0000u); }
__device__ __forceinline__ float ex2f(float x) {
    float y;
    asm("ex2.approx.f32 %0, %1;" : "=f"(y) : "f"(x));
    return y;
}
#define CP16(dst, src) \
    asm volatile("cp.async.cg.shared.global [%0], [%1], 16;" :: "r"(dst), "l"(src))
#define CP_COMMIT() asm volatile("cp.async.commit_group;")
#define CP_WAIT1()  asm volatile("cp.async.wait_group 1;")
#define CP_WAIT0()  asm volatile("cp.async.wait_group 0;")

// ---------------------------------------------------------------------------
// Convert fp32 -> single fp16 planes; z==6 detects mask dtype.
// ---------------------------------------------------------------------------
struct ConvArgs { const float* src[6]; };

__global__ __launch_bounds__(256) void convert_kernel(ConvArgs a,
                                                      const unsigned int* mask) {
    const int z = blockIdx.z;
    const int tid = threadIdx.x;
    if (z == 6) {
        if (blockIdx.x != 0) return;
        int ok_i32 = 1, ok_u8 = 1;
        for (int i = tid; i < 4096; i += 256) {
            unsigned w = mask[i];
            ok_i32 &= (w <= 1u);
            ok_u8  &= ((w & 0xFEFEFEFEu) == 0u);
        }
        ok_i32 = __syncthreads_and(ok_i32);
        ok_u8  = __syncthreads_and(ok_u8);
        if (tid == 0) g_mask_mode = ok_i32 ? 0 : (ok_u8 ? 1 : 2);
        return;
    }
    const float4* src = (const float4*)a.src[z];
    int nf8;
    unsigned short* dh;
    if (z < 3) { nf8 = XSEG / 8; dh = g_xh + (size_t)z * XSEG; }
    else       { nf8 = WSEG / 8; dh = g_wh + (size_t)(z - 3) * WSEG; }
    for (int i = blockIdx.x * 256 + tid; i < nf8; i += 1024 * 256) {
        float4 v0 = src[2 * i];
        float4 v1 = src[2 * i + 1];
        uint4 hv;
        hv.x = cvt2_f16(v0.x, v0.y);
        hv.y = cvt2_f16(v0.z, v0.w);
        hv.z = cvt2_f16(v1.x, v1.y);
        hv.w = cvt2_f16(v1.z, v1.w);
        ((uint4*)dh)[i] = hv;
    }
}

// ---------------------------------------------------------------------------
// Mask -> bf16 additive bias plane.
// ---------------------------------------------------------------------------
__global__ __launch_bounds__(256) void mask_conv_kernel(const void* mask) {
    const int mode = g_mask_mode;
    __nv_bfloat16 nb = __float2bfloat16(NEGINF);
    const uint32_t neg = (uint32_t)*(unsigned short*)&nb;
    const int n8 = (int)(((size_t)B_ * S_ * S_) / 8);
    for (int i = blockIdx.x * 256 + threadIdx.x; i < n8; i += gridDim.x * 256) {
        unsigned m[8];
        if (mode == 0) {
            int4 a = ((const int4*)mask)[2 * i];
            int4 b = ((const int4*)mask)[2 * i + 1];
            m[0] = a.x != 0; m[1] = a.y != 0; m[2] = a.z != 0; m[3] = a.w != 0;
            m[4] = b.x != 0; m[5] = b.y != 0; m[6] = b.z != 0; m[7] = b.w != 0;
        } else if (mode == 1) {
            uint2 a = ((const uint2*)mask)[i];
#pragma unroll
            for (int j = 0; j < 4; ++j) m[j] = (a.x >> (8 * j)) & 255u;
#pragma unroll
            for (int j = 0; j < 4; ++j) m[4 + j] = (a.y >> (8 * j)) & 255u;
        } else {
            float4 a = ((const float4*)mask)[2 * i];
            float4 b = ((const float4*)mask)[2 * i + 1];
            m[0] = a.x != 0.f; m[1] = a.y != 0.f; m[2] = a.z != 0.f; m[3] = a.w != 0.f;
            m[4] = b.x != 0.f; m[5] = b.y != 0.f; m[6] = b.z != 0.f; m[7] = b.w != 0.f;
        }
        uint4 o;
        o.x = (m[0] ? neg : 0u) | ((m[1] ? neg : 0u) << 16);
        o.y = (m[2] ? neg : 0u) | ((m[3] ? neg : 0u) << 16);
        o.z = (m[4] ? neg : 0u) | ((m[5] ? neg : 0u) << 16);
        o.w = (m[6] ? neg : 0u) | ((m[7] ? neg : 0u) << 16);
        ((uint4*)g_mb)[i] = o;
    }
}

// ---------------------------------------------------------------------------
// Projection GEMM: single fp16 x single fp16, fp32 accumulate. (as R11)
// ---------------------------------------------------------------------------
#define PSTG 24576u
#define PROJ_SMEM (3u * PSTG)   // 73728

struct ProjArgs { const float* bias[3]; float scale[3]; };

__device__ __forceinline__ void proj_issue(
    uint32_t sb, int st, int kt, int tid, int m0, int n0,
    const unsigned short* Xh, const unsigned short* Wh)
{
    const uint32_t stage = sb + (uint32_t)st * PSTG;
    {
        int row = tid >> 2, c = tid & 3;
        uint32_t doff = (uint32_t)row * 64u + (uint32_t)((c ^ ((row >> 1) & 3)) << 4);
        CP16(stage + doff, Xh + (size_t)(m0 + row) * DM + kt * 32 + c * 8);
    }
#pragma unroll
    for (int j = 0; j < 2; ++j) {
        int line = tid + 512 * j;
        int row = line >> 2, c = line & 3;
        uint32_t doff = (uint32_t)row * 64u + (uint32_t)((c ^ ((row >> 1) & 3)) << 4);
        CP16(stage + 8192u + doff, Wh + (size_t)(n0 + row) * DM + kt * 32 + c * 8);
    }
    CP_COMMIT();
}

__global__ __launch_bounds__(512) void proj_mma_kernel(ProjArgs args) {
    extern __shared__ char ps[];
    const uint32_t sb = smem_u32(ps);
    const int z = blockIdx.z;
    const unsigned short* __restrict__ Xh = g_xh + (size_t)z * XSEG;
    const unsigned short* __restrict__ Wh = g_wh + (size_t)z * WSEG;
    const float* __restrict__ bias = args.bias[z];
    const float scale = args.scale[z];
    unsigned short* __restrict__ dst = (z == 0) ? g_qh : (z == 1) ? g_kh : g_vh;

    const int tid = threadIdx.x, lane = tid & 31, wid = tid >> 5;
    const int wm = wid & 3, wn = wid >> 2;
    const int m0 = blockIdx.y * 128, n0 = blockIdx.x * 256;
    const int flr = lane & 15, flc = lane >> 4;

    float C[2][8][4];
#pragma unroll
    for (int i = 0; i < 2; ++i)
#pragma unroll
        for (int j = 0; j < 8; ++j)
#pragma unroll
            for (int k = 0; k < 4; ++k) C[i][j][k] = 0.f;

    proj_issue(sb, 0, 0, tid, m0, n0, Xh, Wh);
    proj_issue(sb, 1, 1, tid, m0, n0, Xh, Wh);

    for (int kt = 0; kt < 32; ++kt) {
        if (kt < 31) CP_WAIT1(); else CP_WAIT0();
        __syncthreads();
        if (kt + 2 < 32)
            proj_issue(sb, (kt + 2) % 3, kt + 2, tid, m0, n0, Xh, Wh);

        const uint32_t base = sb + (uint32_t)(kt % 3) * PSTG;
#pragma unroll
        for (int ks = 0; ks < 2; ++ks) {
            const uint32_t csw = (uint32_t)(((2 * ks + flc) ^ ((flr >> 1) & 3)) << 4);
            uint32_t a4[2][4];
#pragma unroll
            for (int mt = 0; mt < 2; ++mt) {
                uint32_t off = (uint32_t)((32 * wm + 16 * mt + flr) * 64) + csw;
                ldsm4(base + off, a4[mt]);
            }
#pragma unroll
            for (int ntp = 0; ntp < 4; ++ntp) {
                uint32_t boff = (uint32_t)((64 * wn + 16 * ntp + flr) * 64) + csw;
                uint32_t b4[4];
                ldsm4(base + 8192u + boff, b4);
                mma16816f(C[0][2 * ntp],     a4[0], b4[0], b4[2]);
                mma16816f(C[1][2 * ntp],     a4[1], b4[0], b4[2]);
                mma16816f(C[0][2 * ntp + 1], a4[0], b4[1], b4[3]);
                mma16816f(C[1][2 * ntp + 1], a4[1], b4[1], b4[3]);
            }
        }
    }

#pragma unroll
    for (int nt = 0; nt < 8; ++nt) {
        int n = n0 + 64 * wn + 8 * nt + 2 * (lane & 3);
        int h = n >> 6, d = n & 63;
        float2 bv = *(const float2*)(bias + n);
#pragma unroll
        for (int mt = 0; mt < 2; ++mt) {
            int mbase = m0 + 32 * wm + 16 * mt + (lane >> 2);
#pragma unroll
            for (int half = 0; half < 2; ++half) {
                int m = mbase + 8 * half;
                int b = m >> 11, s = m & (S_ - 1);
                float vx = (C[mt][nt][2 * half + 0] + bv.x) * scale;
                float vy = (C[mt][nt][2 * half + 1] + bv.y) * scale;
                size_t off = ((size_t)(b * H_ + h) * S_ + s) * DH + d;
                *(uint32_t*)(dst + off) = cvt2_f16(vx, vy);
            }
        }
    }
}

// ---------------------------------------------------------------------------
// Flash attention: fp16, mask bias staged via cp.async + ldsm C-frag init,
// Q fragments in registers. 512 threads, 16 warps x 16 q-rows.
// Stage (48KB): K@0 (8K) | V@8K (8K) | Mbias@16K (32K). 3 stages = 144K.
// Q plane @147456 (32K). Total 180224.
// ---------------------------------------------------------------------------
#define ASTG 49152u
#define AQOFF 147456u
#define ATTN_SMEM 180224u

__device__ __forceinline__ void attn_issue(uint32_t sb, int st, int kt,
                                           int tid, size_t bhS,
                                           const unsigned short* mbq) {
    const uint32_t stage = sb + (uint32_t)st * ASTG;
    // K and V: 512 lines each (64 rows x 8 chunks)
#pragma unroll
    for (int j = 0; j < 2; ++j) {
        int cid = tid + 512 * j;
        int sub = cid >> 9, w = cid & 511, row = w >> 3, c = w & 7;
        const unsigned short* plane = sub ? g_vh : g_kh;
        const void* src = plane + (bhS + (size_t)(kt * 64 + row)) * DH + c * 8;
        uint32_t dst = stage + (uint32_t)sub * 8192u
                     + (uint32_t)row * 128u + (uint32_t)((c ^ (row & 7)) << 4);
        CP16(dst, src);
    }
    // mask bias: 256 rows x 8 chunks = 2048 lines
#pragma unroll
    for (int j = 0; j < 4; ++j) {
        int cid = tid + 512 * j;
        int row = cid >> 3, c = cid & 7;
        const void* src = mbq + (size_t)row * S_ + kt * 64 + c * 8;
        uint32_t dst = stage + 16384u
                     + (uint32_t)row * 128u + (uint32_t)((c ^ (row & 7)) << 4);
        CP16(dst, src);
    }
    CP_COMMIT();
}

__global__ __launch_bounds__(512) void attn_mma_kernel(float* __restrict__ out)
{
    extern __shared__ char as_[];
    const uint32_t sb = smem_u32(as_);

    const int tid = threadIdx.x, lane = tid & 31, wid = tid >> 5;
    const int bz = blockIdx.z, h = blockIdx.y;
    const int q0 = blockIdx.x * 256;
    const size_t bhS = (size_t)(bz * H_ + h) * S_;

    const int flr = lane & 15, flc = lane >> 4;
    const int r_in = lane >> 2;
    const int c_in = 2 * (lane & 3);

    const unsigned short* mbq = g_mb + (size_t)bz * S_ * S_ + (size_t)q0 * S_;

    // prologue: Q plane + tiles 0,1 (Q goes in group 0)
    {
#pragma unroll
        for (int j = 0; j < 4; ++j) {
            int cid = tid + 512 * j;
            int row = cid >> 3, c = cid & 7;
            const void* src = g_qh + (bhS + (size_t)(q0 + row)) * DH + c * 8;
            uint32_t dst = sb + AQOFF
                         + (uint32_t)row * 128u + (uint32_t)((c ^ (row & 7)) << 4);
            CP16(dst, src);
        }
    }
    attn_issue(sb, 0, 0, tid, bhS, mbq);
    attn_issue(sb, 1, 1, tid, bhS, mbq);

    // wait for group 0 (Q + tile0), then hoist Q fragments to registers
    CP_WAIT1();
    __syncthreads();
    const int qrow = 16 * wid + flr;
    uint32_t qf[4][4];
#pragma unroll
    for (int ks = 0; ks < 4; ++ks) {
        uint32_t qoff = (uint32_t)(qrow * 128)
                      + (uint32_t)(((2 * ks + flc) ^ (qrow & 7)) << 4);
        ldsm4(sb + AQOFF + qoff, qf[ks]);
    }

    float oC[8][4];
#pragma unroll
    for (int j = 0; j < 8; ++j)
#pragma unroll
        for (int k = 0; k < 4; ++k) oC[j][k] = 0.f;
    float mi0 = NEGINF, mi1 = NEGINF, li0 = 0.f, li1 = 0.f;

    const int rowA0 = q0 + 16 * wid + r_in;
    const uint32_t msw = (uint32_t)(qrow & 7) << 4;

    for (int kt = 0; kt < 32; ++kt) {
        if (kt < 31) CP_WAIT1(); else CP_WAIT0();
        __syncthreads();
        if (kt + 2 < 32) attn_issue(sb, (kt + 2) % 3, kt + 2, tid, bhS, mbq);

        const uint32_t base = sb + (uint32_t)(kt % 3) * ASTG;

        // S accumulators initialized with mask bias via ldsm (C-frag layout)
        float sC[8][4];
#pragma unroll
        for (int ntp = 0; ntp < 4; ++ntp) {
            uint32_t moff = (uint32_t)(qrow * 128)
                          + (uint32_t)(((2 * ntp + flc) ^ (qrow & 7)) << 4);
            uint32_t mr[4];
            ldsm4(base + 16384u + moff, mr);
            sC[2 * ntp][0]     = bf16lo_f(mr[0]); sC[2 * ntp][1]     = bf16hi_f(mr[0]);
            sC[2 * ntp][2]     = bf16lo_f(mr[1]); sC[2 * ntp][3]     = bf16hi_f(mr[1]);
            sC[2 * ntp + 1][0] = bf16lo_f(mr[2]); sC[2 * ntp + 1][1] = bf16hi_f(mr[2]);
            sC[2 * ntp + 1][2] = bf16lo_f(mr[3]); sC[2 * ntp + 1][3] = bf16hi_f(mr[3]);
        }

        // -- S += Q K^T --
#pragma unroll
        for (int ks = 0; ks < 4; ++ks) {
            uint32_t k4[4][4];
#pragma unroll
            for (int ntp = 0; ntp < 4; ++ntp) {
                uint32_t koff = (uint32_t)((16 * ntp + flr) * 128)
                              + (uint32_t)(((2 * ks + flc) ^ (flr & 7)) << 4);
                ldsm4(base + koff, k4[ntp]);
            }
#pragma unroll
            for (int ntp = 0; ntp < 4; ++ntp) {
                mma16816f(sC[2 * ntp],     qf[ks], k4[ntp][0], k4[ntp][2]);
                mma16816f(sC[2 * ntp + 1], qf[ks], k4[ntp][1], k4[ntp][3]);
            }
        }

        // -- online softmax (log2 domain) --
        float mx0 = NEGINF, mx1 = NEGINF;
#pragma unroll
        for (int nt = 0; nt < 8; ++nt) {
            mx0 = fmaxf(mx0, fmaxf(sC[nt][0], sC[nt][1]));
            mx1 = fmaxf(mx1, fmaxf(sC[nt][2], sC[nt][3]));
        }
        mx0 = fmaxf(mx0, __shfl_xor_sync(0xffffffffu, mx0, 1));
        mx0 = fmaxf(mx0, __shfl_xor_sync(0xffffffffu, mx0, 2));
        mx1 = fmaxf(mx1, __shfl_xor_sync(0xffffffffu, mx1, 1));
        mx1 = fmaxf(mx1, __shfl_xor_sync(0xffffffffu, mx1, 2));

        float mn0 = fmaxf(mi0, mx0), mn1 = fmaxf(mi1, mx1);
        float f0 = ex2f(mi0 - mn0), f1 = ex2f(mi1 - mn1);
        float sum0 = 0.f, sum1 = 0.f;
#pragma unroll
        for (int nt = 0; nt < 8; ++nt) {
            sC[nt][0] = ex2f(sC[nt][0] - mn0);
            sC[nt][1] = ex2f(sC[nt][1] - mn0);
            sC[nt][2] = ex2f(sC[nt][2] - mn1);
            sC[nt][3] = ex2f(sC[nt][3] - mn1);
            sum0 += sC[nt][0] + sC[nt][1];
            sum1 += sC[nt][2] + sC[nt][3];
        }
        sum0 += __shfl_xor_sync(0xffffffffu, sum0, 1);
        sum0 += __shfl_xor_sync(0xffffffffu, sum0, 2);
        sum1 += __shfl_xor_sync(0xffffffffu, sum1, 1);
        sum1 += __shfl_xor_sync(0xffffffffu, sum1, 2);
        li0 = li0 * f0 + sum0;
        li1 = li1 * f1 + sum1;
        mi0 = mn0; mi1 = mn1;
#pragma unroll
        for (int nt = 0; nt < 8; ++nt) {
            oC[nt][0] *= f0; oC[nt][1] *= f0;
            oC[nt][2] *= f1; oC[nt][3] *= f1;
        }

        // -- O += P V --
#pragma unroll
        for (int kp = 0; kp < 4; ++kp) {
            uint32_t pa[4];
            pa[0] = cvt2_f16(sC[2 * kp][0],     sC[2 * kp][1]);
            pa[1] = cvt2_f16(sC[2 * kp][2],     sC[2 * kp][3]);
            pa[2] = cvt2_f16(sC[2 * kp + 1][0], sC[2 * kp + 1][1]);
            pa[3] = cvt2_f16(sC[2 * kp + 1][2], sC[2 * kp + 1][3]);

            const int trow = kp * 16 + ((lane >> 3) & 1) * 8 + (lane & 7);
            const int cb = lane >> 4;
            uint32_t v4[4][4];
#pragma unroll
            for (int ntp = 0; ntp < 4; ++ntp) {
                uint32_t voff = (uint32_t)(trow * 128)
                              + (uint32_t)(((2 * ntp + cb) ^ (trow & 7)) << 4);
                ldsm4t(base + 8192u + voff, v4[ntp]);
            }
#pragma unroll
            for (int ntp = 0; ntp < 4; ++ntp) {
                mma16816f(oC[2 * ntp],     pa, v4[ntp][0], v4[ntp][1]);
                mma16816f(oC[2 * ntp + 1], pa, v4[ntp][2], v4[ntp][3]);
            }
        }
    }

    // ---- epilogue ----
    float inv0 = (li0 > 0.f) ? 1.0f / li0 : 0.f;
    float inv1 = (li1 > 0.f) ? 1.0f / li1 : 0.f;
    const int qr = rowA0;
    const int d0 = h * DH + c_in;
#pragma unroll
    for (int nt = 0; nt < 8; ++nt) {
        float2 v0, v1;
        v0.x = oC[nt][0] * inv0; v0.y = oC[nt][1] * inv0;
        v1.x = oC[nt][2] * inv1; v1.y = oC[nt][3] * inv1;
        *(float2*)(out + (size_t)(bz * S_ + qr) * DM + d0 + 8 * nt) = v0;
        *(float2*)(out + (size_t)(bz * S_ + qr + 8) * DM + d0 + 8 * nt) = v1;
    }
    (void)msw;
}

// ---------------------------------------------------------------------------
extern "C" void kernel_launch(void* const* d_in, const int* in_sizes, int n_in,
                              void* d_out, int out_size) {
    const void* mask = d_in[3];
    float* out = (float*)d_out;

    static int attr_done = 0;
    if (!attr_done) {
        cudaFuncSetAttribute(proj_mma_kernel,
                             cudaFuncAttributeMaxDynamicSharedMemorySize, PROJ_SMEM);
        cudaFuncSetAttribute(attn_mma_kernel,
                             cudaFuncAttributeMaxDynamicSharedMemorySize, ATTN_SMEM);
        attr_done = 1;
    }

    ConvArgs ca;
    ca.src[0] = (const float*)d_in[0];
    ca.src[1] = (const float*)d_in[1];
    ca.src[2] = (const float*)d_in[2];
    ca.src[3] = (const float*)d_in[4];
    ca.src[4] = (const float*)d_in[6];
    ca.src[5] = (const float*)d_in[8];
    convert_kernel<<<dim3(1024, 1, 7), 256>>>(ca, (const unsigned int*)mask);

    mask_conv_kernel<<<2048, 256>>>(mask);

    ProjArgs pa;
    pa.bias[0] = (const float*)d_in[5];
    pa.bias[1] = (const float*)d_in[7];
    pa.bias[2] = (const float*)d_in[9];
    pa.scale[0] = QSCALE; pa.scale[1] = 1.0f; pa.scale[2] = 1.0f;
    proj_mma_kernel<<<dim3(4, 32, 3), 512, PROJ_SMEM>>>(pa);

    attn_mma_kernel<<<dim3(8, 16, 2), 512, ATTN_SMEM>>>(out);
}